// round 1
// baseline (speedup 1.0000x reference)
#include <cuda_runtime.h>
#include <math.h>
#include <stdint.h>

// Problem constants
#define BB   2
#define NN   2048
#define DD   1024
#define HH   16
#define HDD  64
#define BSZ  64
#define MM   32          // N / BS blocks
#define MAXK 32
#define SCALEF 0.125f    // 64^-0.5

// ---------------- scratch (static device globals; no allocation) ----------
__device__ float g_qkv [BB * NN * 3 * DD];   // [B, N, 3*D]  (q | k | v per token)
__device__ float g_attn[BB * NN * DD];       // [B, N, D] attention output
__device__ float g_qb  [BB * HH * MM * HDD]; // coarse queries
__device__ float g_kb  [BB * HH * MM * HDD]; // coarse keys
__device__ int   g_kept[BB * HH * MM * MAXK];
__device__ int   g_kcnt[BB * HH * MM];

// ---------------------------------------------------------------------------
// SGEMM (NT): C[m,n] = sum_k A[m,k] * B[n,k] (+ bias[n])
// A: [Mr,K] row-major, B: [Nc,K] row-major (i.e. we multiply by B^T).
// 128x128 tile, BK=8, 256 threads, 8x8 per thread. Dims assumed multiples
// of 128 / 8 (true here: 4096x3072x1024 and 4096x1024x1024).
// ---------------------------------------------------------------------------
template <bool USE_BIAS>
__global__ __launch_bounds__(256) void sgemm_nt(
    const float* __restrict__ A, const float* __restrict__ Bm,
    const float* __restrict__ bias, float* __restrict__ C,
    int Mr, int Nc, int K)
{
    __shared__ float As[8][132];
    __shared__ float Bs[8][132];

    const int tid  = threadIdx.x;
    const int bm   = blockIdx.y * 128;
    const int bn   = blockIdx.x * 128;
    const int lrow = tid >> 1;          // 0..127
    const int lcol = (tid & 1) * 4;     // 0 or 4
    const int tm   = (tid >> 4) * 8;    // 0..120
    const int tn   = (tid & 15) * 8;    // 0..120

    const float* Aptr = A  + (size_t)(bm + lrow) * K + lcol;
    const float* Bptr = Bm + (size_t)(bn + lrow) * K + lcol;

    float acc[8][8];
#pragma unroll
    for (int i = 0; i < 8; i++)
#pragma unroll
        for (int j = 0; j < 8; j++) acc[i][j] = 0.0f;

    for (int k0 = 0; k0 < K; k0 += 8) {
        float4 av = *(const float4*)(Aptr + k0);
        float4 bv = *(const float4*)(Bptr + k0);
        __syncthreads();
        As[lcol + 0][lrow] = av.x; As[lcol + 1][lrow] = av.y;
        As[lcol + 2][lrow] = av.z; As[lcol + 3][lrow] = av.w;
        Bs[lcol + 0][lrow] = bv.x; Bs[lcol + 1][lrow] = bv.y;
        Bs[lcol + 2][lrow] = bv.z; Bs[lcol + 3][lrow] = bv.w;
        __syncthreads();
#pragma unroll
        for (int kk = 0; kk < 8; kk++) {
            float a[8], b[8];
#pragma unroll
            for (int i = 0; i < 8; i++) a[i] = As[kk][tm + i];
#pragma unroll
            for (int j = 0; j < 8; j++) b[j] = Bs[kk][tn + j];
#pragma unroll
            for (int i = 0; i < 8; i++)
#pragma unroll
                for (int j = 0; j < 8; j++)
                    acc[i][j] = fmaf(a[i], b[j], acc[i][j]);
        }
    }

#pragma unroll
    for (int i = 0; i < 8; i++) {
        float* crow = C + (size_t)(bm + tm + i) * Nc + bn + tn;
#pragma unroll
        for (int j = 0; j < 8; j++) {
            float v = acc[i][j];
            if (USE_BIAS) v += bias[bn + tn + j];
            crow[j] = v;
        }
    }
}

// ---------------------------------------------------------------------------
// Block-mean pooling: qb/kb[b,h,m,d] = mean over 64 tokens of q/k.
// grid = B*H*M blocks, 64 threads (one per d).
// ---------------------------------------------------------------------------
__global__ __launch_bounds__(64) void pool_kernel()
{
    const int row = blockIdx.x;           // (b*H + h)*M + m
    const int d   = threadIdx.x;
    const int m   = row % MM;
    const int h   = (row / MM) % HH;
    const int b   = row / (MM * HH);

    const float* base = g_qkv + ((size_t)(b * NN + m * BSZ) * (3 * DD)) + h * HDD + d;
    float sq = 0.0f, sk = 0.0f;
    for (int i = 0; i < BSZ; i++) {
        sq += base[(size_t)i * 3 * DD];
        sk += base[(size_t)i * 3 * DD + DD];
    }
    g_qb[(size_t)row * HDD + d] = sq * (1.0f / BSZ);
    g_kb[(size_t)row * HDD + d] = sk * (1.0f / BSZ);
}

// ---------------------------------------------------------------------------
// Block scores + top-2 threshold + diagonal keep. One warp per (b,h,m) row,
// lane = key block index n (M = 32 = warp size).
// Matches jax.lax.top_k(c, 2)[0][...,-1:] semantics (2nd largest with
// multiplicity), mask = (c >= thresh) | eye.
// ---------------------------------------------------------------------------
__global__ __launch_bounds__(32) void mask_kernel()
{
    const int row  = blockIdx.x;          // (b*H + h)*M + m
    const int lane = threadIdx.x;         // key block n
    const int m    = row % MM;
    const int bh   = row / MM;

    const float* qb = g_qb + (size_t)row * HDD;
    const float* kb = g_kb + ((size_t)bh * MM + lane) * HDD;

    float s = 0.0f;
    for (int d = 0; d < HDD; d++) s = fmaf(qb[d], kb[d], s);
    s *= SCALEF;

    const unsigned FULL = 0xffffffffu;
    float m1 = s;
#pragma unroll
    for (int off = 16; off; off >>= 1) m1 = fmaxf(m1, __shfl_xor_sync(FULL, m1, off));
    unsigned b1 = __ballot_sync(FULL, s == m1);
    int lead = __ffs(b1) - 1;                       // remove exactly one max instance
    float v2 = (lane == lead) ? -INFINITY : s;
    float m2 = v2;
#pragma unroll
    for (int off = 16; off; off >>= 1) m2 = fmaxf(m2, __shfl_xor_sync(FULL, m2, off));

    bool keep = (s >= m2) || (lane == m);
    unsigned km = __ballot_sync(FULL, keep);
    if (lane == 0) g_kcnt[row] = __popc(km);
    if (keep) {
        int pos = __popc(km & ((1u << lane) - 1u));
        g_kept[(size_t)row * MAXK + pos] = lane;
    }
}

// ---------------------------------------------------------------------------
// Sparse block attention with online softmax.
// grid = B*H*M blocks, 64 threads; thread t owns query t of the block.
// Q row and output accumulator live in registers; K/V tiles staged in smem
// (reads of Ks[j][d]/Vs[j][d] are warp-broadcast, conflict-free).
// ---------------------------------------------------------------------------
__global__ __launch_bounds__(64) void attn_kernel()
{
    __shared__ float Ks[64][65];
    __shared__ float Vs[64][65];

    const int row = blockIdx.x;           // (b*H + h)*M + m
    const int t   = threadIdx.x;          // query within block
    const int m   = row % MM;
    const int h   = (row / MM) % HH;
    const int b   = row / (MM * HH);

    const float* qptr = g_qkv + ((size_t)(b * NN + m * BSZ + t) * (3 * DD)) + h * HDD;
    float q[64];
#pragma unroll
    for (int d4 = 0; d4 < 64; d4 += 4) {
        float4 v = *(const float4*)(qptr + d4);
        q[d4] = v.x; q[d4 + 1] = v.y; q[d4 + 2] = v.z; q[d4 + 3] = v.w;
    }

    float acc[64];
#pragma unroll
    for (int d = 0; d < 64; d++) acc[d] = 0.0f;
    float mrun = -INFINITY, lrun = 0.0f;

    const int cnt = g_kcnt[row];
    for (int kbi = 0; kbi < cnt; kbi++) {
        const int nblk = g_kept[(size_t)row * MAXK + kbi];
        const float* kbase = g_qkv + ((size_t)(b * NN + nblk * BSZ) * (3 * DD)) + DD + h * HDD;
        const float* vbase = kbase + DD;

        __syncthreads();     // protect previous-iteration smem reads
        for (int i = t; i < 64 * 16; i += 64) {
            int r = i >> 4;
            int c = (i & 15) << 2;
            float4 kv = *(const float4*)(kbase + (size_t)r * 3 * DD + c);
            Ks[r][c] = kv.x; Ks[r][c + 1] = kv.y; Ks[r][c + 2] = kv.z; Ks[r][c + 3] = kv.w;
            float4 vv = *(const float4*)(vbase + (size_t)r * 3 * DD + c);
            Vs[r][c] = vv.x; Vs[r][c + 1] = vv.y; Vs[r][c + 2] = vv.z; Vs[r][c + 3] = vv.w;
        }
        __syncthreads();

        for (int j = 0; j < 64; j++) {
            // 4 partial chains to break the serial FMA dependency
            float s0 = 0.0f, s1 = 0.0f, s2 = 0.0f, s3 = 0.0f;
#pragma unroll
            for (int d = 0; d < 64; d += 4) {
                s0 = fmaf(q[d],     Ks[j][d],     s0);
                s1 = fmaf(q[d + 1], Ks[j][d + 1], s1);
                s2 = fmaf(q[d + 2], Ks[j][d + 2], s2);
                s3 = fmaf(q[d + 3], Ks[j][d + 3], s3);
            }
            float s = ((s0 + s1) + (s2 + s3)) * SCALEF;

            float mnew   = fmaxf(mrun, s);
            float escale = __expf(mrun - mnew);   // 0 when mrun == -inf
            float p      = __expf(s - mnew);
            lrun = lrun * escale + p;
#pragma unroll
            for (int d = 0; d < 64; d++)
                acc[d] = fmaf(acc[d], escale, p * Vs[j][d]);
            mrun = mnew;
        }
    }

    const float inv = 1.0f / lrun;
    float* optr = g_attn + ((size_t)(b * NN + m * BSZ + t) * DD) + h * HDD;
#pragma unroll
    for (int d = 0; d < 64; d++) optr[d] = acc[d] * inv;
}

// ---------------------------------------------------------------------------
// Launch
// ---------------------------------------------------------------------------
extern "C" void kernel_launch(void* const* d_in, const int* in_sizes, int n_in,
                              void* d_out, int out_size)
{
    // Map inputs by element count (all four sizes are distinct):
    //   x: 4194304, qkv_w: 3145728, proj_w: 1048576, proj_b: 1024
    const float* x = nullptr; const float* qkv_w = nullptr;
    const float* proj_w = nullptr; const float* proj_b = nullptr;
    for (int i = 0; i < n_in; i++) {
        switch (in_sizes[i]) {
            case BB * NN * DD:       x      = (const float*)d_in[i]; break;
            case 3 * DD * DD:        qkv_w  = (const float*)d_in[i]; break;
            case DD * DD:            proj_w = (const float*)d_in[i]; break;
            case DD:                 proj_b = (const float*)d_in[i]; break;
            default: break;
        }
    }
    float* out = (float*)d_out;

    void* p;
    cudaGetSymbolAddress(&p, g_qkv);  float* qkv  = (float*)p;
    cudaGetSymbolAddress(&p, g_attn); float* attn = (float*)p;

    // 1) QKV projection: [4096,1024] x [3072,1024]^T -> [4096,3072]
    {
        dim3 grid(3 * DD / 128, BB * NN / 128);   // (24, 32)
        sgemm_nt<false><<<grid, 256>>>(x, qkv_w, nullptr, qkv, BB * NN, 3 * DD, DD);
    }
    // 2) coarse pooling
    pool_kernel<<<BB * HH * MM, 64>>>();
    // 3) block scores -> top-2 threshold -> kept-block lists
    mask_kernel<<<BB * HH * MM, 32>>>();
    // 4) sparse block attention
    attn_kernel<<<BB * HH * MM, 64>>>();
    // 5) output projection + bias: [4096,1024] x [1024,1024]^T -> [4096,1024]
    {
        dim3 grid(DD / 128, BB * NN / 128);       // (8, 32)
        sgemm_nt<true><<<grid, 256>>>(attn, proj_w, proj_b, out, BB * NN, DD, DD);
    }
}

// round 3
// speedup vs baseline: 2.0143x; 2.0143x over previous
#include <cuda_runtime.h>
#include <cuda_bf16.h>
#include <math.h>
#include <stdint.h>

// Problem constants
#define BB   2
#define NN   2048
#define DD   1024
#define HH   16
#define HDD  64
#define BSZ  64
#define MM   32
#define MAXK 32
#define SCALEF 0.125f
#define TOK  (BB * NN)          // 4096 tokens

// ---------------- scratch ----------------
__device__ float g_qkv [TOK * 3 * DD];          // QKV projection output (fp32)
__device__ float g_qb  [BB * HH * MM * HDD];
__device__ float g_kb  [BB * HH * MM * HDD];
__device__ int   g_kept[BB * HH * MM * MAXK];
__device__ int   g_kcnt[BB * HH * MM];
// bf16 hi/lo splits
__device__ __nv_bfloat16 g_xh [TOK * DD],     g_xl [TOK * DD];
__device__ __nv_bfloat16 g_wqh[3 * DD * DD],  g_wql[3 * DD * DD];
__device__ __nv_bfloat16 g_wph[DD * DD],      g_wpl[DD * DD];
__device__ __nv_bfloat16 g_ah [TOK * DD],     g_al [TOK * DD];   // attn out split

// =====================================================================
// fp32 -> bf16 hi/lo split (pre-pass), float4 granularity
// =====================================================================
static __device__ __forceinline__ uint32_t pack2h(float a, float b) {
    return (uint32_t)__bfloat16_as_ushort(__float2bfloat16(a)) |
           ((uint32_t)__bfloat16_as_ushort(__float2bfloat16(b)) << 16);
}
__global__ __launch_bounds__(256) void split_kernel(
    const float* __restrict__ src,
    __nv_bfloat16* __restrict__ hi, __nv_bfloat16* __restrict__ lo, int n4)
{
    int i = blockIdx.x * blockDim.x + threadIdx.x;
    if (i >= n4) return;
    float4 v = ((const float4*)src)[i];
    float f[4] = {v.x, v.y, v.z, v.w};
    float r[4];
#pragma unroll
    for (int j = 0; j < 4; j++) {
        __nv_bfloat16 h = __float2bfloat16(f[j]);
        r[j] = f[j] - __bfloat162float(h);
    }
    uint2 ph, pl;
    ph.x = pack2h(f[0], f[1]); ph.y = pack2h(f[2], f[3]);
    pl.x = pack2h(r[0], r[1]); pl.y = pack2h(r[2], r[3]);
    ((uint2*)hi)[i] = ph;
    ((uint2*)lo)[i] = pl;
}

// =====================================================================
// bf16x3 warp-MMA GEMM (NT): C[m,n] = sum_k A[m,k]*B[n,k] (+bias[n])
// C = Ah*Bh + Ah*Bl + Al*Bh  (fp32 accum; lo*lo term ~2^-18, dropped)
// CTA 128x128, K-chunks of 32, 256 threads, warp tile 64x32.
// smem rows padded to 40 bf16 (20 words) -> conflict-free fragment LDS.
// =====================================================================
#define PADK 40

#define MMA_BF16(c, a, b)                                                  \
    asm volatile("mma.sync.aligned.m16n8k16.row.col.f32.bf16.bf16.f32 "    \
        "{%0,%1,%2,%3}, {%4,%5,%6,%7}, {%8,%9}, {%0,%1,%2,%3};"            \
        : "+f"((c)[0]), "+f"((c)[1]), "+f"((c)[2]), "+f"((c)[3])           \
        : "r"((a)[0]), "r"((a)[1]), "r"((a)[2]), "r"((a)[3]),              \
          "r"((b)[0]), "r"((b)[1]))

__global__ __launch_bounds__(256) void gemm_mma(
    const __nv_bfloat16* __restrict__ Ah_, const __nv_bfloat16* __restrict__ Al_,
    const __nv_bfloat16* __restrict__ Bh_, const __nv_bfloat16* __restrict__ Bl_,
    const float* __restrict__ bias, float* __restrict__ C,
    int Nc, int K, int useBias)
{
    __shared__ __align__(16) uint16_t smA[2][128 * PADK];  // Ah, Al
    __shared__ __align__(16) uint16_t smB[2][128 * PADK];  // Bh, Bl

    const int tid  = threadIdx.x;
    const int wid  = tid >> 5;
    const int lane = tid & 31;
    const int g    = lane >> 2;
    const int t    = lane & 3;
    const int wm   = wid & 1;        // 0..1 -> 64 rows each
    const int wn   = wid >> 1;       // 0..3 -> 32 cols each
    const int bm   = blockIdx.y * 128;
    const int bn   = blockIdx.x * 128;

    float acc[4][4][4];
#pragma unroll
    for (int mt = 0; mt < 4; mt++)
#pragma unroll
        for (int nt = 0; nt < 4; nt++)
#pragma unroll
            for (int r = 0; r < 4; r++) acc[mt][nt][r] = 0.0f;

    const int NCH = K >> 5;    // 32 fp32-k per chunk

    for (int ch = 0; ch < NCH; ch++) {
        const int k0 = ch << 5;

        // global loads for this chunk (uint2 = 4 bf16)
        uint2 ra[4], rb[4], rc[4], rd[4];
#pragma unroll
        for (int j = 0; j < 4; j++) {
            int lin = (j << 8) + tid;
            int row = lin >> 3;
            int c4  = (lin & 7) << 2;
            size_t offA = (size_t)(bm + row) * K + k0 + c4;
            size_t offB = (size_t)(bn + row) * K + k0 + c4;
            ra[j] = *(const uint2*)(Ah_ + offA);
            rb[j] = *(const uint2*)(Al_ + offA);
            rc[j] = *(const uint2*)(Bh_ + offB);
            rd[j] = *(const uint2*)(Bl_ + offB);
        }
        __syncthreads();   // previous chunk fully consumed
#pragma unroll
        for (int j = 0; j < 4; j++) {
            int lin = (j << 8) + tid;
            int row = lin >> 3;
            int c4  = (lin & 7) << 2;
            int so  = row * PADK + c4;
            *(uint2*)(&smA[0][so]) = ra[j];
            *(uint2*)(&smA[1][so]) = rb[j];
            *(uint2*)(&smB[0][so]) = rc[j];
            *(uint2*)(&smB[1][so]) = rd[j];
        }
        __syncthreads();

#pragma unroll
        for (int ks = 0; ks < 2; ks++) {
            const int kb = ks << 4;
            uint32_t fah[4][4], fal[4][4];
#pragma unroll
            for (int mt = 0; mt < 4; mt++) {
                int r0 = wm * 64 + mt * 16 + g;
                int a0 = r0 * PADK + kb + t * 2;
                int a1 = (r0 + 8) * PADK + kb + t * 2;
                fah[mt][0] = *(const uint32_t*)(&smA[0][a0]);
                fah[mt][1] = *(const uint32_t*)(&smA[0][a1]);
                fah[mt][2] = *(const uint32_t*)(&smA[0][a0 + 8]);
                fah[mt][3] = *(const uint32_t*)(&smA[0][a1 + 8]);
                fal[mt][0] = *(const uint32_t*)(&smA[1][a0]);
                fal[mt][1] = *(const uint32_t*)(&smA[1][a1]);
                fal[mt][2] = *(const uint32_t*)(&smA[1][a0 + 8]);
                fal[mt][3] = *(const uint32_t*)(&smA[1][a1 + 8]);
            }
            uint32_t fbh[4][2], fbl[4][2];
#pragma unroll
            for (int nt = 0; nt < 4; nt++) {
                int n0 = wn * 32 + nt * 8 + g;
                int b0 = n0 * PADK + kb + t * 2;
                fbh[nt][0] = *(const uint32_t*)(&smB[0][b0]);
                fbh[nt][1] = *(const uint32_t*)(&smB[0][b0 + 8]);
                fbl[nt][0] = *(const uint32_t*)(&smB[1][b0]);
                fbl[nt][1] = *(const uint32_t*)(&smB[1][b0 + 8]);
            }
#pragma unroll
            for (int mt = 0; mt < 4; mt++)
#pragma unroll
                for (int nt = 0; nt < 4; nt++) {
                    MMA_BF16(acc[mt][nt], fah[mt], fbh[nt]);
                    MMA_BF16(acc[mt][nt], fah[mt], fbl[nt]);
                    MMA_BF16(acc[mt][nt], fal[mt], fbh[nt]);
                }
        }
    }

    // epilogue
#pragma unroll
    for (int nt = 0; nt < 4; nt++) {
        int col = bn + wn * 32 + nt * 8 + t * 2;
        float b0v = useBias ? bias[col]     : 0.0f;
        float b1v = useBias ? bias[col + 1] : 0.0f;
#pragma unroll
        for (int mt = 0; mt < 4; mt++) {
            int row = bm + wm * 64 + mt * 16 + g;
            float2 lo2, hi2;
            lo2.x = acc[mt][nt][0] + b0v; lo2.y = acc[mt][nt][1] + b1v;
            hi2.x = acc[mt][nt][2] + b0v; hi2.y = acc[mt][nt][3] + b1v;
            *(float2*)(C + (size_t)row * Nc + col)       = lo2;
            *(float2*)(C + (size_t)(row + 8) * Nc + col) = hi2;
        }
    }
}

// =====================================================================
// Block-mean pooling
// =====================================================================
__global__ __launch_bounds__(64) void pool_kernel()
{
    const int row = blockIdx.x;
    const int d   = threadIdx.x;
    const int m   = row % MM;
    const int b   = row / (MM * HH);
    const int h   = (row / MM) % HH;

    const float* base = g_qkv + ((size_t)(b * NN + m * BSZ) * (3 * DD)) + h * HDD + d;
    float sq = 0.0f, sk = 0.0f;
    for (int i = 0; i < BSZ; i++) {
        sq += base[(size_t)i * 3 * DD];
        sk += base[(size_t)i * 3 * DD + DD];
    }
    g_qb[(size_t)row * HDD + d] = sq * (1.0f / BSZ);
    g_kb[(size_t)row * HDD + d] = sk * (1.0f / BSZ);
}

// =====================================================================
// Block scores + top-2 threshold + diagonal keep (one warp per row)
// =====================================================================
__global__ __launch_bounds__(32) void mask_kernel()
{
    const int row  = blockIdx.x;
    const int lane = threadIdx.x;
    const int m    = row % MM;
    const int bh   = row / MM;

    const float* qb = g_qb + (size_t)row * HDD;
    const float* kb = g_kb + ((size_t)bh * MM + lane) * HDD;

    float s = 0.0f;
    for (int d = 0; d < HDD; d++) s = fmaf(qb[d], kb[d], s);
    s *= SCALEF;

    const unsigned FULL = 0xffffffffu;
    float m1 = s;
#pragma unroll
    for (int off = 16; off; off >>= 1) m1 = fmaxf(m1, __shfl_xor_sync(FULL, m1, off));
    unsigned b1 = __ballot_sync(FULL, s == m1);
    int lead = __ffs(b1) - 1;
    float v2 = (lane == lead) ? -INFINITY : s;
    float m2 = v2;
#pragma unroll
    for (int off = 16; off; off >>= 1) m2 = fmaxf(m2, __shfl_xor_sync(FULL, m2, off));

    bool keep = (s >= m2) || (lane == m);
    unsigned km = __ballot_sync(FULL, keep);
    if (lane == 0) g_kcnt[row] = __popc(km);
    if (keep) {
        int pos = __popc(km & ((1u << lane) - 1u));
        g_kept[(size_t)row * MAXK + pos] = lane;
    }
}

// =====================================================================
// Sparse block attention, online softmax chunked 8 keys at a time.
// Epilogue writes bf16 hi/lo split (input to proj GEMM).
// =====================================================================
__global__ __launch_bounds__(64) void attn_kernel()
{
    __shared__ float Ks[64 * 64];
    __shared__ float Vs[64 * 64];

    const int row = blockIdx.x;
    const int t   = threadIdx.x;
    const int m   = row % MM;
    const int h   = (row / MM) % HH;
    const int b   = row / (MM * HH);

    const float* qptr = g_qkv + ((size_t)(b * NN + m * BSZ + t) * (3 * DD)) + h * HDD;
    float q[64];
#pragma unroll
    for (int d4 = 0; d4 < 16; d4++) {
        float4 v = *(const float4*)(qptr + (d4 << 2));
        q[(d4 << 2) + 0] = v.x; q[(d4 << 2) + 1] = v.y;
        q[(d4 << 2) + 2] = v.z; q[(d4 << 2) + 3] = v.w;
    }

    float acc[64];
#pragma unroll
    for (int d = 0; d < 64; d++) acc[d] = 0.0f;
    float mrun = -INFINITY, lrun = 0.0f;

    const int cnt = g_kcnt[row];
    for (int kbi = 0; kbi < cnt; kbi++) {
        const int nblk = g_kept[(size_t)row * MAXK + kbi];
        const float* kbase = g_qkv + ((size_t)(b * NN + nblk * BSZ) * (3 * DD)) + DD + h * HDD;
        const float* vbase = kbase + DD;

        __syncthreads();
        for (int i = t; i < 64 * 16; i += 64) {
            int r = i >> 4, c4 = i & 15;
            *(float4*)(Ks + (r << 6) + (c4 << 2)) =
                *(const float4*)(kbase + (size_t)r * 3 * DD + (c4 << 2));
            *(float4*)(Vs + (r << 6) + (c4 << 2)) =
                *(const float4*)(vbase + (size_t)r * 3 * DD + (c4 << 2));
        }
        __syncthreads();

        const float4* K4 = (const float4*)Ks;
        const float4* V4 = (const float4*)Vs;

        for (int j0 = 0; j0 < 64; j0 += 8) {
            float s[8];
#pragma unroll
            for (int jj = 0; jj < 8; jj++) {
                const float4* kr = K4 + ((j0 + jj) << 4);
                float c0 = 0.f, c1 = 0.f, c2 = 0.f, c3 = 0.f;
#pragma unroll
                for (int d4 = 0; d4 < 16; d4++) {
                    float4 kv = kr[d4];
                    c0 = fmaf(q[(d4 << 2) + 0], kv.x, c0);
                    c1 = fmaf(q[(d4 << 2) + 1], kv.y, c1);
                    c2 = fmaf(q[(d4 << 2) + 2], kv.z, c2);
                    c3 = fmaf(q[(d4 << 2) + 3], kv.w, c3);
                }
                s[jj] = ((c0 + c1) + (c2 + c3)) * SCALEF;
            }
            float cmax = fmaxf(fmaxf(fmaxf(s[0], s[1]), fmaxf(s[2], s[3])),
                               fmaxf(fmaxf(s[4], s[5]), fmaxf(s[6], s[7])));
            float mnew = fmaxf(mrun, cmax);
            float esc  = __expf(mrun - mnew);
            float p[8]; float ps = 0.f;
#pragma unroll
            for (int jj = 0; jj < 8; jj++) { p[jj] = __expf(s[jj] - mnew); ps += p[jj]; }
            lrun = lrun * esc + ps;
            mrun = mnew;
#pragma unroll
            for (int d4 = 0; d4 < 16; d4++) {
                float a0 = acc[(d4 << 2) + 0] * esc;
                float a1 = acc[(d4 << 2) + 1] * esc;
                float a2 = acc[(d4 << 2) + 2] * esc;
                float a3 = acc[(d4 << 2) + 3] * esc;
#pragma unroll
                for (int jj = 0; jj < 8; jj++) {
                    float4 vv = V4[((j0 + jj) << 4) + d4];
                    a0 = fmaf(p[jj], vv.x, a0);
                    a1 = fmaf(p[jj], vv.y, a1);
                    a2 = fmaf(p[jj], vv.z, a2);
                    a3 = fmaf(p[jj], vv.w, a3);
                }
                acc[(d4 << 2) + 0] = a0; acc[(d4 << 2) + 1] = a1;
                acc[(d4 << 2) + 2] = a2; acc[(d4 << 2) + 3] = a3;
            }
        }
    }

    const float inv = 1.0f / lrun;
    const size_t obase = ((size_t)(b * NN + m * BSZ + t) * DD) + h * HDD;
#pragma unroll
    for (int d = 0; d < 64; d += 4) {
        float f[4], r[4];
#pragma unroll
        for (int j = 0; j < 4; j++) {
            f[j] = acc[d + j] * inv;
            __nv_bfloat16 hb = __float2bfloat16(f[j]);
            r[j] = f[j] - __bfloat162float(hb);
        }
        uint2 ph, pl;
        ph.x = pack2h(f[0], f[1]); ph.y = pack2h(f[2], f[3]);
        pl.x = pack2h(r[0], r[1]); pl.y = pack2h(r[2], r[3]);
        *(uint2*)(g_ah + obase + d) = ph;
        *(uint2*)(g_al + obase + d) = pl;
    }
}

// =====================================================================
// Launch
// =====================================================================
extern "C" void kernel_launch(void* const* d_in, const int* in_sizes, int n_in,
                              void* d_out, int out_size)
{
    const float* x = nullptr; const float* qkv_w = nullptr;
    const float* proj_w = nullptr; const float* proj_b = nullptr;
    for (int i = 0; i < n_in; i++) {
        switch (in_sizes[i]) {
            case TOK * DD / 2 * 2: break; // unreachable placeholder
        }
    }
    for (int i = 0; i < n_in; i++) {
        if      (in_sizes[i] == BB * NN * DD) x      = (const float*)d_in[i];
        else if (in_sizes[i] == 3 * DD * DD)  qkv_w  = (const float*)d_in[i];
        else if (in_sizes[i] == DD * DD)      proj_w = (const float*)d_in[i];
        else if (in_sizes[i] == DD)           proj_b = (const float*)d_in[i];
    }
    float* out = (float*)d_out;

    void* p;
    cudaGetSymbolAddress(&p, g_qkv); float* qkv = (float*)p;
    __nv_bfloat16 *xh, *xl, *wqh, *wql, *wph, *wpl, *ah, *al;
    cudaGetSymbolAddress(&p, g_xh);  xh  = (__nv_bfloat16*)p;
    cudaGetSymbolAddress(&p, g_xl);  xl  = (__nv_bfloat16*)p;
    cudaGetSymbolAddress(&p, g_wqh); wqh = (__nv_bfloat16*)p;
    cudaGetSymbolAddress(&p, g_wql); wql = (__nv_bfloat16*)p;
    cudaGetSymbolAddress(&p, g_wph); wph = (__nv_bfloat16*)p;
    cudaGetSymbolAddress(&p, g_wpl); wpl = (__nv_bfloat16*)p;
    cudaGetSymbolAddress(&p, g_ah);  ah  = (__nv_bfloat16*)p;
    cudaGetSymbolAddress(&p, g_al);  al  = (__nv_bfloat16*)p;

    // 0) fp32 -> bf16 hi/lo splits
    {
        int n4 = TOK * DD / 4;
        split_kernel<<<(n4 + 255) / 256, 256>>>(x, xh, xl, n4);
        n4 = 3 * DD * DD / 4;
        split_kernel<<<(n4 + 255) / 256, 256>>>(qkv_w, wqh, wql, n4);
        n4 = DD * DD / 4;
        split_kernel<<<(n4 + 255) / 256, 256>>>(proj_w, wph, wpl, n4);
    }
    // 1) QKV projection: [4096,1024] x [3072,1024]^T -> g_qkv
    gemm_mma<<<dim3(3 * DD / 128, TOK / 128), 256>>>(
        xh, xl, wqh, wql, nullptr, qkv, 3 * DD, DD, 0);
    // 2) coarse pooling
    pool_kernel<<<BB * HH * MM, 64>>>();
    // 3) block top-2 mask
    mask_kernel<<<BB * HH * MM, 32>>>();
    // 4) sparse block attention (writes bf16 hi/lo attn output)
    attn_kernel<<<BB * HH * MM, 64>>>();
    // 5) output projection + bias -> out
    gemm_mma<<<dim3(DD / 128, TOK / 128), 256>>>(
        ah, al, wph, wpl, proj_b, out, DD, DD, 1);
}

// round 4
// speedup vs baseline: 2.0993x; 1.0422x over previous
#include <cuda_runtime.h>
#include <cuda_bf16.h>
#include <math.h>
#include <stdint.h>

// Problem constants
#define BB   2
#define NN   2048
#define DD   1024
#define HH   16
#define HDD  64
#define BSZ  64
#define MM   32
#define MAXK 32
#define SCALEF 0.125f
#define TOK  (BB * NN)

// ---------------- scratch ----------------
__device__ float g_qkv [TOK * 3 * DD];
__device__ float g_qb  [BB * HH * MM * HDD];
__device__ float g_kb  [BB * HH * MM * HDD];
__device__ int   g_kept[BB * HH * MM * MAXK];
__device__ int   g_kcnt[BB * HH * MM];
__device__ __nv_bfloat16 g_xh [TOK * DD],     g_xl [TOK * DD];
__device__ __nv_bfloat16 g_wqh[3 * DD * DD],  g_wql[3 * DD * DD];
__device__ __nv_bfloat16 g_wph[DD * DD],      g_wpl[DD * DD];
__device__ __nv_bfloat16 g_ah [TOK * DD],     g_al [TOK * DD];

// =====================================================================
// fp32 -> bf16 hi/lo split
// =====================================================================
static __device__ __forceinline__ uint32_t pack2h(float a, float b) {
    return (uint32_t)__bfloat16_as_ushort(__float2bfloat16(a)) |
           ((uint32_t)__bfloat16_as_ushort(__float2bfloat16(b)) << 16);
}
__global__ __launch_bounds__(256) void split_kernel(
    const float* __restrict__ src,
    __nv_bfloat16* __restrict__ hi, __nv_bfloat16* __restrict__ lo, int n4)
{
    int i = blockIdx.x * blockDim.x + threadIdx.x;
    if (i >= n4) return;
    float4 v = ((const float4*)src)[i];
    float f[4] = {v.x, v.y, v.z, v.w};
    float r[4];
#pragma unroll
    for (int j = 0; j < 4; j++) {
        __nv_bfloat16 h = __float2bfloat16(f[j]);
        r[j] = f[j] - __bfloat162float(h);
    }
    uint2 ph, pl;
    ph.x = pack2h(f[0], f[1]); ph.y = pack2h(f[2], f[3]);
    pl.x = pack2h(r[0], r[1]); pl.y = pack2h(r[2], r[3]);
    ((uint2*)hi)[i] = ph;
    ((uint2*)lo)[i] = pl;
}

// =====================================================================
// bf16x3 warp-MMA GEMM (NT), software-pipelined double-buffered stages.
// =====================================================================
#define PADK 40
#define TILE_E (128 * PADK)          // uint16 elems per tile
#define STAGE_E (4 * TILE_E)         // Ah, Al, Bh, Bl
#define GEMM_SMEM (2u * STAGE_E * 2u) // bytes

#define MMA_BF16(c, a, b)                                                  \
    asm volatile("mma.sync.aligned.m16n8k16.row.col.f32.bf16.bf16.f32 "    \
        "{%0,%1,%2,%3}, {%4,%5,%6,%7}, {%8,%9}, {%0,%1,%2,%3};"            \
        : "+f"((c)[0]), "+f"((c)[1]), "+f"((c)[2]), "+f"((c)[3])           \
        : "r"((a)[0]), "r"((a)[1]), "r"((a)[2]), "r"((a)[3]),              \
          "r"((b)[0]), "r"((b)[1]))

__global__ __launch_bounds__(256, 1) void gemm_mma(
    const __nv_bfloat16* __restrict__ Ah_, const __nv_bfloat16* __restrict__ Al_,
    const __nv_bfloat16* __restrict__ Bh_, const __nv_bfloat16* __restrict__ Bl_,
    const float* __restrict__ bias, float* __restrict__ C,
    int Nc, int K, int useBias)
{
    extern __shared__ __align__(16) uint16_t smg[];

    const int tid  = threadIdx.x;
    const int wid  = tid >> 5;
    const int lane = tid & 31;
    const int g    = lane >> 2;
    const int t    = lane & 3;
    const int wm   = wid & 1;
    const int wn   = wid >> 1;
    const int bm   = blockIdx.y * 128;
    const int bn   = blockIdx.x * 128;

    // per-thread load coordinates (same every chunk)
    int lrow[4], lc4[4], lso[4];
#pragma unroll
    for (int j = 0; j < 4; j++) {
        int lin = (j << 8) + tid;
        lrow[j] = lin >> 3;
        lc4[j]  = (lin & 7) << 2;
        lso[j]  = lrow[j] * PADK + lc4[j];
    }

    float acc[4][4][4];
#pragma unroll
    for (int mt = 0; mt < 4; mt++)
#pragma unroll
        for (int nt = 0; nt < 4; nt++)
#pragma unroll
            for (int r = 0; r < 4; r++) acc[mt][nt][r] = 0.0f;

    const int NCH = K >> 5;

    uint2 ra[4], rb[4], rc[4], rd[4];
    // prologue: load chunk 0
#pragma unroll
    for (int j = 0; j < 4; j++) {
        size_t offA = (size_t)(bm + lrow[j]) * K + lc4[j];
        size_t offB = (size_t)(bn + lrow[j]) * K + lc4[j];
        ra[j] = *(const uint2*)(Ah_ + offA);
        rb[j] = *(const uint2*)(Al_ + offA);
        rc[j] = *(const uint2*)(Bh_ + offB);
        rd[j] = *(const uint2*)(Bl_ + offB);
    }
    {
        uint16_t* st = smg;  // stage 0
#pragma unroll
        for (int j = 0; j < 4; j++) {
            *(uint2*)(st + lso[j])              = ra[j];
            *(uint2*)(st + TILE_E + lso[j])     = rb[j];
            *(uint2*)(st + 2 * TILE_E + lso[j]) = rc[j];
            *(uint2*)(st + 3 * TILE_E + lso[j]) = rd[j];
        }
    }

    for (int ch = 0; ch < NCH; ch++) {
        const int s = ch & 1;
        uint16_t* cur = smg + s * STAGE_E;
        __syncthreads();                       // stage s visible

        // issue next chunk's LDGs (in flight during MMAs)
        if (ch + 1 < NCH) {
            const int k0 = (ch + 1) << 5;
#pragma unroll
            for (int j = 0; j < 4; j++) {
                size_t offA = (size_t)(bm + lrow[j]) * K + k0 + lc4[j];
                size_t offB = (size_t)(bn + lrow[j]) * K + k0 + lc4[j];
                ra[j] = *(const uint2*)(Ah_ + offA);
                rb[j] = *(const uint2*)(Al_ + offA);
                rc[j] = *(const uint2*)(Bh_ + offB);
                rd[j] = *(const uint2*)(Bl_ + offB);
            }
        }

        const uint16_t* sAh = cur;
        const uint16_t* sAl = cur + TILE_E;
        const uint16_t* sBh = cur + 2 * TILE_E;
        const uint16_t* sBl = cur + 3 * TILE_E;

#pragma unroll
        for (int ks = 0; ks < 2; ks++) {
            const int kb = ks << 4;
            uint32_t fah[4][4], fal[4][4];
#pragma unroll
            for (int mt = 0; mt < 4; mt++) {
                int r0 = wm * 64 + mt * 16 + g;
                int a0 = r0 * PADK + kb + t * 2;
                int a1 = (r0 + 8) * PADK + kb + t * 2;
                fah[mt][0] = *(const uint32_t*)(sAh + a0);
                fah[mt][1] = *(const uint32_t*)(sAh + a1);
                fah[mt][2] = *(const uint32_t*)(sAh + a0 + 8);
                fah[mt][3] = *(const uint32_t*)(sAh + a1 + 8);
                fal[mt][0] = *(const uint32_t*)(sAl + a0);
                fal[mt][1] = *(const uint32_t*)(sAl + a1);
                fal[mt][2] = *(const uint32_t*)(sAl + a0 + 8);
                fal[mt][3] = *(const uint32_t*)(sAl + a1 + 8);
            }
            uint32_t fbh[4][2], fbl[4][2];
#pragma unroll
            for (int nt = 0; nt < 4; nt++) {
                int n0 = wn * 32 + nt * 8 + g;
                int b0 = n0 * PADK + kb + t * 2;
                fbh[nt][0] = *(const uint32_t*)(sBh + b0);
                fbh[nt][1] = *(const uint32_t*)(sBh + b0 + 8);
                fbl[nt][0] = *(const uint32_t*)(sBl + b0);
                fbl[nt][1] = *(const uint32_t*)(sBl + b0 + 8);
            }
#pragma unroll
            for (int mt = 0; mt < 4; mt++)
#pragma unroll
                for (int nt = 0; nt < 4; nt++) {
                    MMA_BF16(acc[mt][nt], fah[mt], fbh[nt]);
                    MMA_BF16(acc[mt][nt], fah[mt], fbl[nt]);
                    MMA_BF16(acc[mt][nt], fal[mt], fbh[nt]);
                }
        }

        // store next chunk into the other stage (no sync needed: that stage
        // was last READ before this iteration's top syncthreads)
        if (ch + 1 < NCH) {
            uint16_t* nxt = smg + (s ^ 1) * STAGE_E;
#pragma unroll
            for (int j = 0; j < 4; j++) {
                *(uint2*)(nxt + lso[j])              = ra[j];
                *(uint2*)(nxt + TILE_E + lso[j])     = rb[j];
                *(uint2*)(nxt + 2 * TILE_E + lso[j]) = rc[j];
                *(uint2*)(nxt + 3 * TILE_E + lso[j]) = rd[j];
            }
        }
    }

    // epilogue
#pragma unroll
    for (int nt = 0; nt < 4; nt++) {
        int col = bn + wn * 32 + nt * 8 + t * 2;
        float b0v = useBias ? bias[col]     : 0.0f;
        float b1v = useBias ? bias[col + 1] : 0.0f;
#pragma unroll
        for (int mt = 0; mt < 4; mt++) {
            int row = bm + wm * 64 + mt * 16 + g;
            float2 lo2, hi2;
            lo2.x = acc[mt][nt][0] + b0v; lo2.y = acc[mt][nt][1] + b1v;
            hi2.x = acc[mt][nt][2] + b0v; hi2.y = acc[mt][nt][3] + b1v;
            *(float2*)(C + (size_t)row * Nc + col)       = lo2;
            *(float2*)(C + (size_t)(row + 8) * Nc + col) = hi2;
        }
    }
}

// =====================================================================
// Block-mean pooling
// =====================================================================
__global__ __launch_bounds__(64) void pool_kernel()
{
    const int row = blockIdx.x;
    const int d   = threadIdx.x;
    const int m   = row % MM;
    const int b   = row / (MM * HH);
    const int h   = (row / MM) % HH;

    const float* base = g_qkv + ((size_t)(b * NN + m * BSZ) * (3 * DD)) + h * HDD + d;
    float sq = 0.0f, sk = 0.0f;
    for (int i = 0; i < BSZ; i++) {
        sq += base[(size_t)i * 3 * DD];
        sk += base[(size_t)i * 3 * DD + DD];
    }
    g_qb[(size_t)row * HDD + d] = sq * (1.0f / BSZ);
    g_kb[(size_t)row * HDD + d] = sk * (1.0f / BSZ);
}

// =====================================================================
// Block scores + top-2 threshold + diagonal keep
// =====================================================================
__global__ __launch_bounds__(32) void mask_kernel()
{
    const int row  = blockIdx.x;
    const int lane = threadIdx.x;
    const int m    = row % MM;
    const int bh   = row / MM;

    const float* qb = g_qb + (size_t)row * HDD;
    const float* kb = g_kb + ((size_t)bh * MM + lane) * HDD;

    float s = 0.0f;
    for (int d = 0; d < HDD; d++) s = fmaf(qb[d], kb[d], s);
    s *= SCALEF;

    const unsigned FULL = 0xffffffffu;
    float m1 = s;
#pragma unroll
    for (int off = 16; off; off >>= 1) m1 = fmaxf(m1, __shfl_xor_sync(FULL, m1, off));
    unsigned b1 = __ballot_sync(FULL, s == m1);
    int lead = __ffs(b1) - 1;
    float v2 = (lane == lead) ? -INFINITY : s;
    float m2 = v2;
#pragma unroll
    for (int off = 16; off; off >>= 1) m2 = fmaxf(m2, __shfl_xor_sync(FULL, m2, off));

    bool keep = (s >= m2) || (lane == m);
    unsigned km = __ballot_sync(FULL, keep);
    if (lane == 0) g_kcnt[row] = __popc(km);
    if (keep) {
        int pos = __popc(km & ((1u << lane) - 1u));
        g_kept[(size_t)row * MAXK + pos] = lane;
    }
}

// =====================================================================
// Sparse block attention: cp.async double-buffered K/V tiles,
// online softmax chunked 8 keys at a time, bf16 hi/lo epilogue.
// =====================================================================
#define ATT_STAGE_F 8192              // floats per stage (K 4096 + V 4096)
#define ATT_SMEM (2u * ATT_STAGE_F * 4u)

static __device__ __forceinline__ uint32_t smem_u32(const void* p) {
    uint32_t a;
    asm("{ .reg .u64 t; cvta.to.shared.u64 t, %1; cvt.u32.u64 %0, t; }"
        : "=r"(a) : "l"(p));
    return a;
}
static __device__ __forceinline__ void cp16(uint32_t s, const void* g) {
    asm volatile("cp.async.cg.shared.global [%0], [%1], 16;"
                 :: "r"(s), "l"(g) : "memory");
}

__global__ __launch_bounds__(64) void attn_kernel()
{
    extern __shared__ __align__(16) float asm_f[];

    const int row = blockIdx.x;
    const int t   = threadIdx.x;
    const int m   = row % MM;
    const int h   = (row / MM) % HH;
    const int b   = row / (MM * HH);

    const uint32_t sbase = smem_u32(asm_f);

    const float* qptr = g_qkv + ((size_t)(b * NN + m * BSZ + t) * (3 * DD)) + h * HDD;
    float q[64];
#pragma unroll
    for (int d4 = 0; d4 < 16; d4++) {
        float4 v = *(const float4*)(qptr + (d4 << 2));
        q[(d4 << 2) + 0] = v.x; q[(d4 << 2) + 1] = v.y;
        q[(d4 << 2) + 2] = v.z; q[(d4 << 2) + 3] = v.w;
    }

    float acc[64];
#pragma unroll
    for (int d = 0; d < 64; d++) acc[d] = 0.0f;
    float mrun = -INFINITY, lrun = 0.0f;

    const int cnt = g_kcnt[row];
    const int*  kept = g_kept + (size_t)row * MAXK;
    const float* hk  = g_qkv + DD + h * HDD;     // K base for head h
    const int r16 = t >> 2;                       // rows this thread copies: r16, r16+16, r16+32, r16+48
    const int c16 = (t & 3) << 4;                 // 16-float column offset? no: 4 chunks of 16B
    // each thread copies 16 (row,16B) pieces for K and 16 for V:
    // linear i = t + 64*j, row = i>>4, c4 = i&15 (16B units)

    // prologue: prefetch tile 0
    {
        const int nblk = kept[0];
        const float* kb = hk + (size_t)(b * NN + nblk * BSZ) * (3 * DD);
#pragma unroll
        for (int j = 0; j < 16; j++) {
            int i = t + (j << 6);
            int r = i >> 4, c4 = i & 15;
            uint32_t so = sbase + (uint32_t)((r << 6) + (c4 << 2)) * 4u;
            const float* gk = kb + (size_t)r * 3 * DD + (c4 << 2);
            cp16(so, gk);
            cp16(so + 16384u, gk + DD);
        }
        asm volatile("cp.async.commit_group;" ::: "memory");
    }

    for (int kbi = 0; kbi < cnt; kbi++) {
        const int s = kbi & 1;
        if (kbi + 1 < cnt) {
            const int nblk = kept[kbi + 1];
            const float* kb = hk + (size_t)(b * NN + nblk * BSZ) * (3 * DD);
            const uint32_t stg = sbase + (uint32_t)((s ^ 1) * ATT_STAGE_F) * 4u;
#pragma unroll
            for (int j = 0; j < 16; j++) {
                int i = t + (j << 6);
                int r = i >> 4, c4 = i & 15;
                uint32_t so = stg + (uint32_t)((r << 6) + (c4 << 2)) * 4u;
                const float* gk = kb + (size_t)r * 3 * DD + (c4 << 2);
                cp16(so, gk);
                cp16(so + 16384u, gk + DD);
            }
            asm volatile("cp.async.commit_group;" ::: "memory");
            asm volatile("cp.async.wait_group 1;" ::: "memory");
        } else {
            asm volatile("cp.async.wait_group 0;" ::: "memory");
        }
        __syncthreads();          // whole tile s present

        const float4* K4 = (const float4*)(asm_f + s * ATT_STAGE_F);
        const float4* V4 = K4 + 1024;

        for (int j0 = 0; j0 < 64; j0 += 8) {
            float sc[8];
#pragma unroll
            for (int jj = 0; jj < 8; jj++) {
                const float4* kr = K4 + ((j0 + jj) << 4);
                float c0 = 0.f, c1 = 0.f, c2 = 0.f, c3 = 0.f;
#pragma unroll
                for (int d4 = 0; d4 < 16; d4++) {
                    float4 kv = kr[d4];
                    c0 = fmaf(q[(d4 << 2) + 0], kv.x, c0);
                    c1 = fmaf(q[(d4 << 2) + 1], kv.y, c1);
                    c2 = fmaf(q[(d4 << 2) + 2], kv.z, c2);
                    c3 = fmaf(q[(d4 << 2) + 3], kv.w, c3);
                }
                sc[jj] = ((c0 + c1) + (c2 + c3)) * SCALEF;
            }
            float cmax = fmaxf(fmaxf(fmaxf(sc[0], sc[1]), fmaxf(sc[2], sc[3])),
                               fmaxf(fmaxf(sc[4], sc[5]), fmaxf(sc[6], sc[7])));
            float mnew = fmaxf(mrun, cmax);
            float esc  = __expf(mrun - mnew);
            float p[8]; float ps = 0.f;
#pragma unroll
            for (int jj = 0; jj < 8; jj++) { p[jj] = __expf(sc[jj] - mnew); ps += p[jj]; }
            lrun = lrun * esc + ps;
            mrun = mnew;
#pragma unroll
            for (int d4 = 0; d4 < 16; d4++) {
                float a0 = acc[(d4 << 2) + 0] * esc;
                float a1 = acc[(d4 << 2) + 1] * esc;
                float a2 = acc[(d4 << 2) + 2] * esc;
                float a3 = acc[(d4 << 2) + 3] * esc;
#pragma unroll
                for (int jj = 0; jj < 8; jj++) {
                    float4 vv = V4[((j0 + jj) << 4) + d4];
                    a0 = fmaf(p[jj], vv.x, a0);
                    a1 = fmaf(p[jj], vv.y, a1);
                    a2 = fmaf(p[jj], vv.z, a2);
                    a3 = fmaf(p[jj], vv.w, a3);
                }
                acc[(d4 << 2) + 0] = a0; acc[(d4 << 2) + 1] = a1;
                acc[(d4 << 2) + 2] = a2; acc[(d4 << 2) + 3] = a3;
            }
        }
        __syncthreads();          // done with stage s before it is overwritten
    }

    const float inv = 1.0f / lrun;
    const size_t obase = ((size_t)(b * NN + m * BSZ + t) * DD) + h * HDD;
#pragma unroll
    for (int d = 0; d < 64; d += 4) {
        float f[4], r[4];
#pragma unroll
        for (int j = 0; j < 4; j++) {
            f[j] = acc[d + j] * inv;
            __nv_bfloat16 hb = __float2bfloat16(f[j]);
            r[j] = f[j] - __bfloat162float(hb);
        }
        uint2 ph, pl;
        ph.x = pack2h(f[0], f[1]); ph.y = pack2h(f[2], f[3]);
        pl.x = pack2h(r[0], r[1]); pl.y = pack2h(r[2], r[3]);
        *(uint2*)(g_ah + obase + d) = ph;
        *(uint2*)(g_al + obase + d) = pl;
    }
}

// =====================================================================
// Launch
// =====================================================================
extern "C" void kernel_launch(void* const* d_in, const int* in_sizes, int n_in,
                              void* d_out, int out_size)
{
    const float* x = nullptr; const float* qkv_w = nullptr;
    const float* proj_w = nullptr; const float* proj_b = nullptr;
    for (int i = 0; i < n_in; i++) {
        if      (in_sizes[i] == BB * NN * DD) x      = (const float*)d_in[i];
        else if (in_sizes[i] == 3 * DD * DD)  qkv_w  = (const float*)d_in[i];
        else if (in_sizes[i] == DD * DD)      proj_w = (const float*)d_in[i];
        else if (in_sizes[i] == DD)           proj_b = (const float*)d_in[i];
    }
    float* out = (float*)d_out;

    void* p;
    cudaGetSymbolAddress(&p, g_qkv); float* qkv = (float*)p;
    __nv_bfloat16 *xh, *xl, *wqh, *wql, *wph, *wpl, *ah, *al;
    cudaGetSymbolAddress(&p, g_xh);  xh  = (__nv_bfloat16*)p;
    cudaGetSymbolAddress(&p, g_xl);  xl  = (__nv_bfloat16*)p;
    cudaGetSymbolAddress(&p, g_wqh); wqh = (__nv_bfloat16*)p;
    cudaGetSymbolAddress(&p, g_wql); wql = (__nv_bfloat16*)p;
    cudaGetSymbolAddress(&p, g_wph); wph = (__nv_bfloat16*)p;
    cudaGetSymbolAddress(&p, g_wpl); wpl = (__nv_bfloat16*)p;
    cudaGetSymbolAddress(&p, g_ah);  ah  = (__nv_bfloat16*)p;
    cudaGetSymbolAddress(&p, g_al);  al  = (__nv_bfloat16*)p;

    static int attr_done = 0;
    if (!attr_done) {
        cudaFuncSetAttribute(gemm_mma, cudaFuncAttributeMaxDynamicSharedMemorySize, GEMM_SMEM);
        cudaFuncSetAttribute(attn_kernel, cudaFuncAttributeMaxDynamicSharedMemorySize, ATT_SMEM);
        attr_done = 1;
    }

    // 0) fp32 -> bf16 hi/lo splits
    {
        int n4 = TOK * DD / 4;
        split_kernel<<<(n4 + 255) / 256, 256>>>(x, xh, xl, n4);
        n4 = 3 * DD * DD / 4;
        split_kernel<<<(n4 + 255) / 256, 256>>>(qkv_w, wqh, wql, n4);
        n4 = DD * DD / 4;
        split_kernel<<<(n4 + 255) / 256, 256>>>(proj_w, wph, wpl, n4);
    }
    // 1) QKV projection
    gemm_mma<<<dim3(3 * DD / 128, TOK / 128), 256, GEMM_SMEM>>>(
        xh, xl, wqh, wql, nullptr, qkv, 3 * DD, DD, 0);
    // 2) coarse pooling
    pool_kernel<<<BB * HH * MM, 64>>>();
    // 3) block top-2 mask
    mask_kernel<<<BB * HH * MM, 32>>>();
    // 4) sparse block attention
    attn_kernel<<<BB * HH * MM, 64, ATT_SMEM>>>();
    // 5) output projection + bias
    gemm_mma<<<dim3(DD / 128, TOK / 128), 256, GEMM_SMEM>>>(
        ah, al, wph, wpl, proj_b, out, DD, DD, 1);
}

// round 5
// speedup vs baseline: 2.3254x; 1.1077x over previous
#include <cuda_runtime.h>
#include <cuda_bf16.h>
#include <math.h>
#include <stdint.h>

// Problem constants
#define BB   2
#define NN   2048
#define DD   1024
#define HH   16
#define HDD  64
#define BSZ  64
#define MM   32
#define MAXK 32
#define SCALEF 0.125f
#define TOK  (BB * NN)

// ---------------- scratch ----------------
__device__ float g_qkv [TOK * 3 * DD];
__device__ float g_qb  [BB * HH * MM * HDD];
__device__ float g_kb  [BB * HH * MM * HDD];
__device__ int   g_kept[BB * HH * MM * MAXK];
__device__ int   g_kcnt[BB * HH * MM];
__device__ __nv_bfloat16 g_xh [TOK * DD],     g_xl [TOK * DD];
__device__ __nv_bfloat16 g_wqh[3 * DD * DD],  g_wql[3 * DD * DD];
__device__ __nv_bfloat16 g_wph[DD * DD],      g_wpl[DD * DD];
__device__ __nv_bfloat16 g_ah [TOK * DD],     g_al [TOK * DD];

// =====================================================================
// helpers
// =====================================================================
static __device__ __forceinline__ uint32_t pack2h(float a, float b) {
    return (uint32_t)__bfloat16_as_ushort(__float2bfloat16(a)) |
           ((uint32_t)__bfloat16_as_ushort(__float2bfloat16(b)) << 16);
}
static __device__ __forceinline__ uint32_t smem_u32(const void* p) {
    uint32_t a;
    asm("{ .reg .u64 t; cvta.to.shared.u64 t, %1; cvt.u32.u64 %0, t; }"
        : "=r"(a) : "l"(p));
    return a;
}
static __device__ __forceinline__ void cp16(uint32_t s, const void* g) {
    asm volatile("cp.async.cg.shared.global [%0], [%1], 16;"
                 :: "r"(s), "l"(g) : "memory");
}
static __device__ __forceinline__ void ldm4(uint32_t* r, uint32_t a) {
    asm volatile("ldmatrix.sync.aligned.m8n8.x4.shared.b16 {%0,%1,%2,%3}, [%4];"
        : "=r"(r[0]), "=r"(r[1]), "=r"(r[2]), "=r"(r[3]) : "r"(a));
}

__global__ __launch_bounds__(256) void split_kernel(
    const float* __restrict__ src,
    __nv_bfloat16* __restrict__ hi, __nv_bfloat16* __restrict__ lo, int n4)
{
    int i = blockIdx.x * blockDim.x + threadIdx.x;
    if (i >= n4) return;
    float4 v = ((const float4*)src)[i];
    float f[4] = {v.x, v.y, v.z, v.w};
    float r[4];
#pragma unroll
    for (int j = 0; j < 4; j++) {
        __nv_bfloat16 h = __float2bfloat16(f[j]);
        r[j] = f[j] - __bfloat162float(h);
    }
    uint2 ph, pl;
    ph.x = pack2h(f[0], f[1]); ph.y = pack2h(f[2], f[3]);
    pl.x = pack2h(r[0], r[1]); pl.y = pack2h(r[2], r[3]);
    ((uint2*)hi)[i] = ph;
    ((uint2*)lo)[i] = pl;
}

// =====================================================================
// bf16x3 warp-MMA GEMM (NT): cp.async 4-stage pipeline + ldmatrix.
// CTA 128x128, 256 thr, warp tile 64x32, K-chunks of 32.
// =====================================================================
#define PADK 40
#define TILE_E (128 * PADK)                  // uint16 per tile
#define STAGE_B (4u * TILE_E * 2u)           // bytes: Ah Al Bh Bl
#define NSTG 4
#define GEMM_SMEM (NSTG * STAGE_B)           // 163840 B

#define MMA_BF16(c, a, b)                                                  \
    asm volatile("mma.sync.aligned.m16n8k16.row.col.f32.bf16.bf16.f32 "    \
        "{%0,%1,%2,%3}, {%4,%5,%6,%7}, {%8,%9}, {%0,%1,%2,%3};"            \
        : "+f"((c)[0]), "+f"((c)[1]), "+f"((c)[2]), "+f"((c)[3])           \
        : "r"((a)[0]), "r"((a)[1]), "r"((a)[2]), "r"((a)[3]),              \
          "r"((b)[0]), "r"((b)[1]))

__global__ __launch_bounds__(256, 1) void gemm_mma(
    const __nv_bfloat16* __restrict__ Ah_, const __nv_bfloat16* __restrict__ Al_,
    const __nv_bfloat16* __restrict__ Bh_, const __nv_bfloat16* __restrict__ Bl_,
    const float* __restrict__ bias, float* __restrict__ C,
    int Nc, int K, int useBias)
{
    extern __shared__ __align__(16) uint16_t smg[];
    const uint32_t sbase = smem_u32(smg);

    const int tid  = threadIdx.x;
    const int wid  = tid >> 5;
    const int lane = tid & 31;
    const int g    = lane >> 2;
    const int t    = lane & 3;
    const int wm   = wid & 1;
    const int wn   = wid >> 1;
    const int bm   = blockIdx.y * 128;
    const int bn   = blockIdx.x * 128;

    // cp.async coordinates: lin = tid + 256*j, row = lin>>2, c = lin&3 (16B units)
    int crow[2], cc[2];  uint32_t cdst[2];
#pragma unroll
    for (int j = 0; j < 2; j++) {
        int lin = tid + (j << 8);
        crow[j] = lin >> 2;
        cc[j]   = lin & 3;
        cdst[j] = (uint32_t)(crow[j] * PADK * 2 + cc[j] * 16);
    }

    // ldmatrix per-lane byte offsets (within a stage)
    // A (x4): lanes0-15 rows m0-15 @k0, lanes16-31 same rows @k+8
    uint32_t aoff[4];
#pragma unroll
    for (int mt = 0; mt < 4; mt++) {
        int mrow = wm * 64 + mt * 16 + (lane & 15);
        int ke   = (lane >> 4) << 3;
        aoff[mt] = (uint32_t)((mrow * PADK + ke) * 2);
    }
    // B (x4): covers two n8 tiles; np=0 -> nt0,1; np=1 -> nt2,3
    uint32_t boff[2];
#pragma unroll
    for (int np = 0; np < 2; np++) {
        int nrow = wn * 32 + np * 16 + ((lane >> 4) << 3) + (lane & 7);
        int ke   = ((lane >> 3) & 1) << 3;
        boff[np] = (uint32_t)((nrow * PADK + ke) * 2);
    }

    float acc[4][4][4];
#pragma unroll
    for (int mt = 0; mt < 4; mt++)
#pragma unroll
        for (int nt = 0; nt < 4; nt++)
#pragma unroll
            for (int r = 0; r < 4; r++) acc[mt][nt][r] = 0.0f;

    const int NCH = K >> 5;

    // issue one chunk's cp.asyncs into stage st
    auto issue = [&](int ch, int st) {
        const int k0 = ch << 5;
        const uint32_t stg = sbase + (uint32_t)st * STAGE_B;
#pragma unroll
        for (int j = 0; j < 2; j++) {
            size_t offA = (size_t)(bm + crow[j]) * K + k0 + (cc[j] << 3);
            size_t offB = (size_t)(bn + crow[j]) * K + k0 + (cc[j] << 3);
            cp16(stg + cdst[j],                        Ah_ + offA);
            cp16(stg + TILE_E * 2 + cdst[j],           Al_ + offA);
            cp16(stg + TILE_E * 4 + cdst[j],           Bh_ + offB);
            cp16(stg + TILE_E * 6 + cdst[j],           Bl_ + offB);
        }
    };

    // prologue: stages 0..2
#pragma unroll
    for (int p = 0; p < 3; p++) {
        issue(p, p);
        asm volatile("cp.async.commit_group;" ::: "memory");
    }

    for (int ch = 0; ch < NCH; ch++) {
        asm volatile("cp.async.wait_group 2;" ::: "memory");
        __syncthreads();                       // stage ch ready; stage ch-1 fully read

        if (ch + 3 < NCH) issue(ch + 3, (ch + 3) & 3);
        asm volatile("cp.async.commit_group;" ::: "memory");  // uniform group count

        const uint32_t stg = sbase + (uint32_t)(ch & 3) * STAGE_B;

#pragma unroll
        for (int ks = 0; ks < 2; ks++) {
            const uint32_t kadd = (uint32_t)(ks << 5);  // +16 elems = 32 bytes
            uint32_t fah[4][4], fal[4][4], fbh[2][4], fbl[2][4];
#pragma unroll
            for (int mt = 0; mt < 4; mt++) {
                ldm4(fah[mt], stg + aoff[mt] + kadd);
                ldm4(fal[mt], stg + TILE_E * 2 + aoff[mt] + kadd);
            }
#pragma unroll
            for (int np = 0; np < 2; np++) {
                ldm4(fbh[np], stg + TILE_E * 4 + boff[np] + kadd);
                ldm4(fbl[np], stg + TILE_E * 6 + boff[np] + kadd);
            }
            // pass 1: Ah*Bh (16 independent MMAs)
#pragma unroll
            for (int mt = 0; mt < 4; mt++)
#pragma unroll
                for (int nt = 0; nt < 4; nt++)
                    MMA_BF16(acc[mt][nt], fah[mt], &fbh[nt >> 1][(nt & 1) << 1]);
            // pass 2: Ah*Bl
#pragma unroll
            for (int mt = 0; mt < 4; mt++)
#pragma unroll
                for (int nt = 0; nt < 4; nt++)
                    MMA_BF16(acc[mt][nt], fah[mt], &fbl[nt >> 1][(nt & 1) << 1]);
            // pass 3: Al*Bh
#pragma unroll
            for (int mt = 0; mt < 4; mt++)
#pragma unroll
                for (int nt = 0; nt < 4; nt++)
                    MMA_BF16(acc[mt][nt], fal[mt], &fbh[nt >> 1][(nt & 1) << 1]);
        }
    }

    // epilogue
#pragma unroll
    for (int nt = 0; nt < 4; nt++) {
        int col = bn + wn * 32 + nt * 8 + t * 2;
        float b0v = useBias ? bias[col]     : 0.0f;
        float b1v = useBias ? bias[col + 1] : 0.0f;
#pragma unroll
        for (int mt = 0; mt < 4; mt++) {
            int row = bm + wm * 64 + mt * 16 + g;
            float2 lo2, hi2;
            lo2.x = acc[mt][nt][0] + b0v; lo2.y = acc[mt][nt][1] + b1v;
            hi2.x = acc[mt][nt][2] + b0v; hi2.y = acc[mt][nt][3] + b1v;
            *(float2*)(C + (size_t)row * Nc + col)       = lo2;
            *(float2*)(C + (size_t)(row + 8) * Nc + col) = hi2;
        }
    }
}

// =====================================================================
// Block-mean pooling
// =====================================================================
__global__ __launch_bounds__(64) void pool_kernel()
{
    const int row = blockIdx.x;
    const int d   = threadIdx.x;
    const int m   = row % MM;
    const int b   = row / (MM * HH);
    const int h   = (row / MM) % HH;

    const float* base = g_qkv + ((size_t)(b * NN + m * BSZ) * (3 * DD)) + h * HDD + d;
    float sq = 0.0f, sk = 0.0f;
    for (int i = 0; i < BSZ; i++) {
        sq += base[(size_t)i * 3 * DD];
        sk += base[(size_t)i * 3 * DD + DD];
    }
    g_qb[(size_t)row * HDD + d] = sq * (1.0f / BSZ);
    g_kb[(size_t)row * HDD + d] = sk * (1.0f / BSZ);
}

// =====================================================================
// Block scores + top-2 threshold + diagonal keep
// =====================================================================
__global__ __launch_bounds__(32) void mask_kernel()
{
    const int row  = blockIdx.x;
    const int lane = threadIdx.x;
    const int m    = row % MM;
    const int bh   = row / MM;

    const float* qb = g_qb + (size_t)row * HDD;
    const float* kb = g_kb + ((size_t)bh * MM + lane) * HDD;

    float s = 0.0f;
    for (int d = 0; d < HDD; d++) s = fmaf(qb[d], kb[d], s);
    s *= SCALEF;

    const unsigned FULL = 0xffffffffu;
    float m1 = s;
#pragma unroll
    for (int off = 16; off; off >>= 1) m1 = fmaxf(m1, __shfl_xor_sync(FULL, m1, off));
    unsigned b1 = __ballot_sync(FULL, s == m1);
    int lead = __ffs(b1) - 1;
    float v2 = (lane == lead) ? -INFINITY : s;
    float m2 = v2;
#pragma unroll
    for (int off = 16; off; off >>= 1) m2 = fmaxf(m2, __shfl_xor_sync(FULL, m2, off));

    bool keep = (s >= m2) || (lane == m);
    unsigned km = __ballot_sync(FULL, keep);
    if (lane == 0) g_kcnt[row] = __popc(km);
    if (keep) {
        int pos = __popc(km & ((1u << lane) - 1u));
        g_kept[(size_t)row * MAXK + pos] = lane;
    }
}

// =====================================================================
// Sparse block attention (cp.async double-buffered), bf16 hi/lo epilogue
// =====================================================================
#define ATT_STAGE_F 8192
#define ATT_SMEM (2u * ATT_STAGE_F * 4u)

__global__ __launch_bounds__(64) void attn_kernel()
{
    extern __shared__ __align__(16) float asm_f[];

    const int row = blockIdx.x;
    const int t   = threadIdx.x;
    const int m   = row % MM;
    const int h   = (row / MM) % HH;
    const int b   = row / (MM * HH);

    const uint32_t sbase = smem_u32(asm_f);

    const float* qptr = g_qkv + ((size_t)(b * NN + m * BSZ + t) * (3 * DD)) + h * HDD;
    float q[64];
#pragma unroll
    for (int d4 = 0; d4 < 16; d4++) {
        float4 v = *(const float4*)(qptr + (d4 << 2));
        q[(d4 << 2) + 0] = v.x; q[(d4 << 2) + 1] = v.y;
        q[(d4 << 2) + 2] = v.z; q[(d4 << 2) + 3] = v.w;
    }

    float acc[64];
#pragma unroll
    for (int d = 0; d < 64; d++) acc[d] = 0.0f;
    float mrun = -INFINITY, lrun = 0.0f;

    const int cnt = g_kcnt[row];
    const int*  kept = g_kept + (size_t)row * MAXK;
    const float* hk  = g_qkv + DD + h * HDD;

    {
        const int nblk = kept[0];
        const float* kb = hk + (size_t)(b * NN + nblk * BSZ) * (3 * DD);
#pragma unroll
        for (int j = 0; j < 16; j++) {
            int i = t + (j << 6);
            int r = i >> 4, c4 = i & 15;
            uint32_t so = sbase + (uint32_t)((r << 6) + (c4 << 2)) * 4u;
            const float* gk = kb + (size_t)r * 3 * DD + (c4 << 2);
            cp16(so, gk);
            cp16(so + 16384u, gk + DD);
        }
        asm volatile("cp.async.commit_group;" ::: "memory");
    }

    for (int kbi = 0; kbi < cnt; kbi++) {
        const int s = kbi & 1;
        if (kbi + 1 < cnt) {
            const int nblk = kept[kbi + 1];
            const float* kb = hk + (size_t)(b * NN + nblk * BSZ) * (3 * DD);
            const uint32_t stg = sbase + (uint32_t)((s ^ 1) * ATT_STAGE_F) * 4u;
#pragma unroll
            for (int j = 0; j < 16; j++) {
                int i = t + (j << 6);
                int r = i >> 4, c4 = i & 15;
                uint32_t so = stg + (uint32_t)((r << 6) + (c4 << 2)) * 4u;
                const float* gk = kb + (size_t)r * 3 * DD + (c4 << 2);
                cp16(so, gk);
                cp16(so + 16384u, gk + DD);
            }
            asm volatile("cp.async.commit_group;" ::: "memory");
            asm volatile("cp.async.wait_group 1;" ::: "memory");
        } else {
            asm volatile("cp.async.wait_group 0;" ::: "memory");
        }
        __syncthreads();

        const float4* K4 = (const float4*)(asm_f + s * ATT_STAGE_F);
        const float4* V4 = K4 + 1024;

        for (int j0 = 0; j0 < 64; j0 += 8) {
            float sc[8];
#pragma unroll
            for (int jj = 0; jj < 8; jj++) {
                const float4* kr = K4 + ((j0 + jj) << 4);
                float c0 = 0.f, c1 = 0.f, c2 = 0.f, c3 = 0.f;
#pragma unroll
                for (int d4 = 0; d4 < 16; d4++) {
                    float4 kv = kr[d4];
                    c0 = fmaf(q[(d4 << 2) + 0], kv.x, c0);
                    c1 = fmaf(q[(d4 << 2) + 1], kv.y, c1);
                    c2 = fmaf(q[(d4 << 2) + 2], kv.z, c2);
                    c3 = fmaf(q[(d4 << 2) + 3], kv.w, c3);
                }
                sc[jj] = ((c0 + c1) + (c2 + c3)) * SCALEF;
            }
            float cmax = fmaxf(fmaxf(fmaxf(sc[0], sc[1]), fmaxf(sc[2], sc[3])),
                               fmaxf(fmaxf(sc[4], sc[5]), fmaxf(sc[6], sc[7])));
            float mnew = fmaxf(mrun, cmax);
            float esc  = __expf(mrun - mnew);
            float p[8]; float ps = 0.f;
#pragma unroll
            for (int jj = 0; jj < 8; jj++) { p[jj] = __expf(sc[jj] - mnew); ps += p[jj]; }
            lrun = lrun * esc + ps;
            mrun = mnew;
#pragma unroll
            for (int d4 = 0; d4 < 16; d4++) {
                float a0 = acc[(d4 << 2) + 0] * esc;
                float a1 = acc[(d4 << 2) + 1] * esc;
                float a2 = acc[(d4 << 2) + 2] * esc;
                float a3 = acc[(d4 << 2) + 3] * esc;
#pragma unroll
                for (int jj = 0; jj < 8; jj++) {
                    float4 vv = V4[((j0 + jj) << 4) + d4];
                    a0 = fmaf(p[jj], vv.x, a0);
                    a1 = fmaf(p[jj], vv.y, a1);
                    a2 = fmaf(p[jj], vv.z, a2);
                    a3 = fmaf(p[jj], vv.w, a3);
                }
                acc[(d4 << 2) + 0] = a0; acc[(d4 << 2) + 1] = a1;
                acc[(d4 << 2) + 2] = a2; acc[(d4 << 2) + 3] = a3;
            }
        }
        __syncthreads();
    }

    const float inv = 1.0f / lrun;
    const size_t obase = ((size_t)(b * NN + m * BSZ + t) * DD) + h * HDD;
#pragma unroll
    for (int d = 0; d < 64; d += 4) {
        float f[4], r[4];
#pragma unroll
        for (int j = 0; j < 4; j++) {
            f[j] = acc[d + j] * inv;
            __nv_bfloat16 hb = __float2bfloat16(f[j]);
            r[j] = f[j] - __bfloat162float(hb);
        }
        uint2 ph, pl;
        ph.x = pack2h(f[0], f[1]); ph.y = pack2h(f[2], f[3]);
        pl.x = pack2h(r[0], r[1]); pl.y = pack2h(r[2], r[3]);
        *(uint2*)(g_ah + obase + d) = ph;
        *(uint2*)(g_al + obase + d) = pl;
    }
}

// =====================================================================
// Launch
// =====================================================================
extern "C" void kernel_launch(void* const* d_in, const int* in_sizes, int n_in,
                              void* d_out, int out_size)
{
    const float* x = nullptr; const float* qkv_w = nullptr;
    const float* proj_w = nullptr; const float* proj_b = nullptr;
    for (int i = 0; i < n_in; i++) {
        if      (in_sizes[i] == BB * NN * DD) x      = (const float*)d_in[i];
        else if (in_sizes[i] == 3 * DD * DD)  qkv_w  = (const float*)d_in[i];
        else if (in_sizes[i] == DD * DD)      proj_w = (const float*)d_in[i];
        else if (in_sizes[i] == DD)           proj_b = (const float*)d_in[i];
    }
    float* out = (float*)d_out;

    void* p;
    cudaGetSymbolAddress(&p, g_qkv); float* qkv = (float*)p;
    __nv_bfloat16 *xh, *xl, *wqh, *wql, *wph, *wpl, *ah, *al;
    cudaGetSymbolAddress(&p, g_xh);  xh  = (__nv_bfloat16*)p;
    cudaGetSymbolAddress(&p, g_xl);  xl  = (__nv_bfloat16*)p;
    cudaGetSymbolAddress(&p, g_wqh); wqh = (__nv_bfloat16*)p;
    cudaGetSymbolAddress(&p, g_wql); wql = (__nv_bfloat16*)p;
    cudaGetSymbolAddress(&p, g_wph); wph = (__nv_bfloat16*)p;
    cudaGetSymbolAddress(&p, g_wpl); wpl = (__nv_bfloat16*)p;
    cudaGetSymbolAddress(&p, g_ah);  ah  = (__nv_bfloat16*)p;
    cudaGetSymbolAddress(&p, g_al);  al  = (__nv_bfloat16*)p;

    static int attr_done = 0;
    if (!attr_done) {
        cudaFuncSetAttribute(gemm_mma, cudaFuncAttributeMaxDynamicSharedMemorySize, GEMM_SMEM);
        cudaFuncSetAttribute(attn_kernel, cudaFuncAttributeMaxDynamicSharedMemorySize, ATT_SMEM);
        attr_done = 1;
    }

    {
        int n4 = TOK * DD / 4;
        split_kernel<<<(n4 + 255) / 256, 256>>>(x, xh, xl, n4);
        n4 = 3 * DD * DD / 4;
        split_kernel<<<(n4 + 255) / 256, 256>>>(qkv_w, wqh, wql, n4);
        n4 = DD * DD / 4;
        split_kernel<<<(n4 + 255) / 256, 256>>>(proj_w, wph, wpl, n4);
    }
    gemm_mma<<<dim3(3 * DD / 128, TOK / 128), 256, GEMM_SMEM>>>(
        xh, xl, wqh, wql, nullptr, qkv, 3 * DD, DD, 0);
    pool_kernel<<<BB * HH * MM, 64>>>();
    mask_kernel<<<BB * HH * MM, 32>>>();
    attn_kernel<<<BB * HH * MM, 64, ATT_SMEM>>>();
    gemm_mma<<<dim3(DD / 128, TOK / 128), 256, GEMM_SMEM>>>(
        ah, al, wph, wpl, proj_b, out, DD, DD, 1);
}

// round 6
// speedup vs baseline: 2.4969x; 1.0738x over previous
#include <cuda_runtime.h>
#include <cuda_bf16.h>
#include <math.h>
#include <stdint.h>

// Problem constants
#define BB   2
#define NN   2048
#define DD   1024
#define HH   16
#define HDD  64
#define BSZ  64
#define MM   32
#define MAXK 32
#define SCALEF 0.125f
#define TOK  (BB * NN)

// ---------------- scratch ----------------
__device__ float g_qkv [TOK * 3 * DD];
__device__ float g_qb  [BB * HH * MM * HDD];
__device__ float g_kb  [BB * HH * MM * HDD];
__device__ int   g_kept[BB * HH * MM * MAXK];
__device__ int   g_kcnt[BB * HH * MM];
__device__ __nv_bfloat16 g_xh [TOK * DD],     g_xl [TOK * DD];
__device__ __nv_bfloat16 g_wqh[3 * DD * DD],  g_wql[3 * DD * DD];
__device__ __nv_bfloat16 g_wph[DD * DD],      g_wpl[DD * DD];
__device__ __nv_bfloat16 g_ah [TOK * DD],     g_al [TOK * DD];

// =====================================================================
// helpers
// =====================================================================
static __device__ __forceinline__ uint32_t pack2h(float a, float b) {
    return (uint32_t)__bfloat16_as_ushort(__float2bfloat16(a)) |
           ((uint32_t)__bfloat16_as_ushort(__float2bfloat16(b)) << 16);
}
static __device__ __forceinline__ uint32_t smem_u32(const void* p) {
    uint32_t a;
    asm("{ .reg .u64 t; cvta.to.shared.u64 t, %1; cvt.u32.u64 %0, t; }"
        : "=r"(a) : "l"(p));
    return a;
}
static __device__ __forceinline__ void cp16(uint32_t s, const void* g) {
    asm volatile("cp.async.cg.shared.global [%0], [%1], 16;"
                 :: "r"(s), "l"(g) : "memory");
}
static __device__ __forceinline__ void ldm4(uint32_t* r, uint32_t a) {
    asm volatile("ldmatrix.sync.aligned.m8n8.x4.shared.b16 {%0,%1,%2,%3}, [%4];"
        : "=r"(r[0]), "=r"(r[1]), "=r"(r[2]), "=r"(r[3]) : "r"(a));
}

__global__ __launch_bounds__(256) void split_kernel(
    const float* __restrict__ src,
    __nv_bfloat16* __restrict__ hi, __nv_bfloat16* __restrict__ lo, int n4)
{
    int i = blockIdx.x * blockDim.x + threadIdx.x;
    if (i >= n4) return;
    float4 v = ((const float4*)src)[i];
    float f[4] = {v.x, v.y, v.z, v.w};
    float r[4];
#pragma unroll
    for (int j = 0; j < 4; j++) {
        __nv_bfloat16 h = __float2bfloat16(f[j]);
        r[j] = f[j] - __bfloat162float(h);
    }
    uint2 ph, pl;
    ph.x = pack2h(f[0], f[1]); ph.y = pack2h(f[2], f[3]);
    pl.x = pack2h(r[0], r[1]); pl.y = pack2h(r[2], r[3]);
    ((uint2*)hi)[i] = ph;
    ((uint2*)lo)[i] = pl;
}

// =====================================================================
// bf16x3 warp-MMA GEMM (NT): 3-stage cp.async pipeline, K-chunk 64.
// CTA 128x128, 256 thr, warp tile 64x32.
// =====================================================================
#define CHK 64                                 // fp32 k per chunk
#define PADK 72                                // padded row length (elems)
#define TILE_E (128 * PADK)                    // uint16 per tile
#define STAGE_B (4u * TILE_E * 2u)             // bytes: Ah Al Bh Bl = 73728
#define NSTG 3
#define GEMM_SMEM (NSTG * STAGE_B)             // 221184 B

#define MMA_BF16(c, a, b)                                                  \
    asm volatile("mma.sync.aligned.m16n8k16.row.col.f32.bf16.bf16.f32 "    \
        "{%0,%1,%2,%3}, {%4,%5,%6,%7}, {%8,%9}, {%0,%1,%2,%3};"            \
        : "+f"((c)[0]), "+f"((c)[1]), "+f"((c)[2]), "+f"((c)[3])           \
        : "r"((a)[0]), "r"((a)[1]), "r"((a)[2]), "r"((a)[3]),              \
          "r"((b)[0]), "r"((b)[1]))

__global__ __launch_bounds__(256, 1) void gemm_mma(
    const __nv_bfloat16* __restrict__ Ah_, const __nv_bfloat16* __restrict__ Al_,
    const __nv_bfloat16* __restrict__ Bh_, const __nv_bfloat16* __restrict__ Bl_,
    const float* __restrict__ bias, float* __restrict__ C,
    int Nc, int K, int useBias)
{
    extern __shared__ __align__(16) uint16_t smg[];
    const uint32_t sbase = smem_u32(smg);

    const int tid  = threadIdx.x;
    const int wid  = tid >> 5;
    const int lane = tid & 31;
    const int g    = lane >> 2;
    const int t    = lane & 3;
    const int wm   = wid & 1;
    const int wn   = wid >> 1;
    const int bm   = blockIdx.y * 128;
    const int bn   = blockIdx.x * 128;

    // cp.async coords: chunk row = 64 fp32 = 128B = 8 x 16B pieces
    // lin = tid + 256*j (j<4 per tile), row = lin>>3, c = lin&7
    int crow[4]; uint32_t cdst[4]; int ccol[4];
#pragma unroll
    for (int j = 0; j < 4; j++) {
        int lin = tid + (j << 8);
        crow[j] = lin >> 3;
        ccol[j] = (lin & 7) << 3;             // elem offset within chunk
        cdst[j] = (uint32_t)(crow[j] * PADK * 2 + (lin & 7) * 16);
    }

    // ldmatrix per-lane byte offsets (within a stage tile)
    uint32_t aoff[4];
#pragma unroll
    for (int mt = 0; mt < 4; mt++) {
        int mrow = wm * 64 + mt * 16 + (lane & 15);
        int ke   = (lane >> 4) << 3;
        aoff[mt] = (uint32_t)((mrow * PADK + ke) * 2);
    }
    uint32_t boff[2];
#pragma unroll
    for (int np = 0; np < 2; np++) {
        int nrow = wn * 32 + np * 16 + ((lane >> 4) << 3) + (lane & 7);
        int ke   = ((lane >> 3) & 1) << 3;
        boff[np] = (uint32_t)((nrow * PADK + ke) * 2);
    }

    float acc[4][4][4];
#pragma unroll
    for (int mt = 0; mt < 4; mt++)
#pragma unroll
        for (int nt = 0; nt < 4; nt++)
#pragma unroll
            for (int r = 0; r < 4; r++) acc[mt][nt][r] = 0.0f;

    const int NCH = K >> 6;                    // K=1024 -> 16 chunks

    auto issue = [&](int ch, int st) {
        const int k0 = ch << 6;
        const uint32_t stg = sbase + (uint32_t)st * STAGE_B;
#pragma unroll
        for (int j = 0; j < 4; j++) {
            size_t offA = (size_t)(bm + crow[j]) * K + k0 + ccol[j];
            size_t offB = (size_t)(bn + crow[j]) * K + k0 + ccol[j];
            cp16(stg + cdst[j],              Ah_ + offA);
            cp16(stg + TILE_E * 2 + cdst[j], Al_ + offA);
            cp16(stg + TILE_E * 4 + cdst[j], Bh_ + offB);
            cp16(stg + TILE_E * 6 + cdst[j], Bl_ + offB);
        }
    };

    issue(0, 0);
    asm volatile("cp.async.commit_group;" ::: "memory");
    issue(1, 1);
    asm volatile("cp.async.commit_group;" ::: "memory");

    for (int ch = 0; ch < NCH; ch++) {
        asm volatile("cp.async.wait_group 1;" ::: "memory");
        __syncthreads();                       // stage ch ready; stage ch-1 reads done

        if (ch + 2 < NCH) issue(ch + 2, (ch + 2) % 3);
        asm volatile("cp.async.commit_group;" ::: "memory");

        const uint32_t stg = sbase + (uint32_t)(ch % 3) * STAGE_B;

#pragma unroll
        for (int ks = 0; ks < 4; ks++) {
            const uint32_t kadd = (uint32_t)(ks << 5);  // +16 elems = 32B
            uint32_t fah[4][4], fal[4][4], fbh[2][4], fbl[2][4];
#pragma unroll
            for (int mt = 0; mt < 4; mt++) {
                ldm4(fah[mt], stg + aoff[mt] + kadd);
                ldm4(fal[mt], stg + TILE_E * 2 + aoff[mt] + kadd);
            }
#pragma unroll
            for (int np = 0; np < 2; np++) {
                ldm4(fbh[np], stg + TILE_E * 4 + boff[np] + kadd);
                ldm4(fbl[np], stg + TILE_E * 6 + boff[np] + kadd);
            }
#pragma unroll
            for (int mt = 0; mt < 4; mt++)
#pragma unroll
                for (int nt = 0; nt < 4; nt++)
                    MMA_BF16(acc[mt][nt], fah[mt], &fbh[nt >> 1][(nt & 1) << 1]);
#pragma unroll
            for (int mt = 0; mt < 4; mt++)
#pragma unroll
                for (int nt = 0; nt < 4; nt++)
                    MMA_BF16(acc[mt][nt], fah[mt], &fbl[nt >> 1][(nt & 1) << 1]);
#pragma unroll
            for (int mt = 0; mt < 4; mt++)
#pragma unroll
                for (int nt = 0; nt < 4; nt++)
                    MMA_BF16(acc[mt][nt], fal[mt], &fbh[nt >> 1][(nt & 1) << 1]);
        }
    }

    // epilogue
#pragma unroll
    for (int nt = 0; nt < 4; nt++) {
        int col = bn + wn * 32 + nt * 8 + t * 2;
        float b0v = useBias ? bias[col]     : 0.0f;
        float b1v = useBias ? bias[col + 1] : 0.0f;
#pragma unroll
        for (int mt = 0; mt < 4; mt++) {
            int row = bm + wm * 64 + mt * 16 + g;
            float2 lo2, hi2;
            lo2.x = acc[mt][nt][0] + b0v; lo2.y = acc[mt][nt][1] + b1v;
            hi2.x = acc[mt][nt][2] + b0v; hi2.y = acc[mt][nt][3] + b1v;
            *(float2*)(C + (size_t)row * Nc + col)       = lo2;
            *(float2*)(C + (size_t)(row + 8) * Nc + col) = hi2;
        }
    }
}

// =====================================================================
// Block-mean pooling
// =====================================================================
__global__ __launch_bounds__(64) void pool_kernel()
{
    const int row = blockIdx.x;
    const int d   = threadIdx.x;
    const int m   = row % MM;
    const int b   = row / (MM * HH);
    const int h   = (row / MM) % HH;

    const float* base = g_qkv + ((size_t)(b * NN + m * BSZ) * (3 * DD)) + h * HDD + d;
    float sq = 0.0f, sk = 0.0f;
    for (int i = 0; i < BSZ; i++) {
        sq += base[(size_t)i * 3 * DD];
        sk += base[(size_t)i * 3 * DD + DD];
    }
    g_qb[(size_t)row * HDD + d] = sq * (1.0f / BSZ);
    g_kb[(size_t)row * HDD + d] = sk * (1.0f / BSZ);
}

// =====================================================================
// Block scores + top-2 threshold + diagonal keep
// =====================================================================
__global__ __launch_bounds__(32) void mask_kernel()
{
    const int row  = blockIdx.x;
    const int lane = threadIdx.x;
    const int m    = row % MM;
    const int bh   = row / MM;

    const float* qb = g_qb + (size_t)row * HDD;
    const float* kb = g_kb + ((size_t)bh * MM + lane) * HDD;

    float s = 0.0f;
    for (int d = 0; d < HDD; d++) s = fmaf(qb[d], kb[d], s);
    s *= SCALEF;

    const unsigned FULL = 0xffffffffu;
    float m1 = s;
#pragma unroll
    for (int off = 16; off; off >>= 1) m1 = fmaxf(m1, __shfl_xor_sync(FULL, m1, off));
    unsigned b1 = __ballot_sync(FULL, s == m1);
    int lead = __ffs(b1) - 1;
    float v2 = (lane == lead) ? -INFINITY : s;
    float m2 = v2;
#pragma unroll
    for (int off = 16; off; off >>= 1) m2 = fmaxf(m2, __shfl_xor_sync(FULL, m2, off));

    bool keep = (s >= m2) || (lane == m);
    unsigned km = __ballot_sync(FULL, keep);
    if (lane == 0) g_kcnt[row] = __popc(km);
    if (keep) {
        int pos = __popc(km & ((1u << lane) - 1u));
        g_kept[(size_t)row * MAXK + pos] = lane;
    }
}

// =====================================================================
// Sparse block attention (cp.async double-buffered), bf16 hi/lo epilogue
// =====================================================================
#define ATT_STAGE_F 8192
#define ATT_SMEM (2u * ATT_STAGE_F * 4u)

__global__ __launch_bounds__(64) void attn_kernel()
{
    extern __shared__ __align__(16) float asm_f[];

    const int row = blockIdx.x;
    const int t   = threadIdx.x;
    const int m   = row % MM;
    const int h   = (row / MM) % HH;
    const int b   = row / (MM * HH);

    const uint32_t sbase = smem_u32(asm_f);

    const float* qptr = g_qkv + ((size_t)(b * NN + m * BSZ + t) * (3 * DD)) + h * HDD;
    float q[64];
#pragma unroll
    for (int d4 = 0; d4 < 16; d4++) {
        float4 v = *(const float4*)(qptr + (d4 << 2));
        q[(d4 << 2) + 0] = v.x; q[(d4 << 2) + 1] = v.y;
        q[(d4 << 2) + 2] = v.z; q[(d4 << 2) + 3] = v.w;
    }

    float acc[64];
#pragma unroll
    for (int d = 0; d < 64; d++) acc[d] = 0.0f;
    float mrun = -INFINITY, lrun = 0.0f;

    const int cnt = g_kcnt[row];
    const int*  kept = g_kept + (size_t)row * MAXK;
    const float* hk  = g_qkv + DD + h * HDD;

    {
        const int nblk = kept[0];
        const float* kb = hk + (size_t)(b * NN + nblk * BSZ) * (3 * DD);
#pragma unroll
        for (int j = 0; j < 16; j++) {
            int i = t + (j << 6);
            int r = i >> 4, c4 = i & 15;
            uint32_t so = sbase + (uint32_t)((r << 6) + (c4 << 2)) * 4u;
            const float* gk = kb + (size_t)r * 3 * DD + (c4 << 2);
            cp16(so, gk);
            cp16(so + 16384u, gk + DD);
        }
        asm volatile("cp.async.commit_group;" ::: "memory");
    }

    for (int kbi = 0; kbi < cnt; kbi++) {
        const int s = kbi & 1;
        if (kbi + 1 < cnt) {
            const int nblk = kept[kbi + 1];
            const float* kb = hk + (size_t)(b * NN + nblk * BSZ) * (3 * DD);
            const uint32_t stg = sbase + (uint32_t)((s ^ 1) * ATT_STAGE_F) * 4u;
#pragma unroll
            for (int j = 0; j < 16; j++) {
                int i = t + (j << 6);
                int r = i >> 4, c4 = i & 15;
                uint32_t so = stg + (uint32_t)((r << 6) + (c4 << 2)) * 4u;
                const float* gk = kb + (size_t)r * 3 * DD + (c4 << 2);
                cp16(so, gk);
                cp16(so + 16384u, gk + DD);
            }
            asm volatile("cp.async.commit_group;" ::: "memory");
            asm volatile("cp.async.wait_group 1;" ::: "memory");
        } else {
            asm volatile("cp.async.wait_group 0;" ::: "memory");
        }
        __syncthreads();

        const float4* K4 = (const float4*)(asm_f + s * ATT_STAGE_F);
        const float4* V4 = K4 + 1024;

        for (int j0 = 0; j0 < 64; j0 += 8) {
            float sc[8];
#pragma unroll
            for (int jj = 0; jj < 8; jj++) {
                const float4* kr = K4 + ((j0 + jj) << 4);
                float c0 = 0.f, c1 = 0.f, c2 = 0.f, c3 = 0.f;
#pragma unroll
                for (int d4 = 0; d4 < 16; d4++) {
                    float4 kv = kr[d4];
                    c0 = fmaf(q[(d4 << 2) + 0], kv.x, c0);
                    c1 = fmaf(q[(d4 << 2) + 1], kv.y, c1);
                    c2 = fmaf(q[(d4 << 2) + 2], kv.z, c2);
                    c3 = fmaf(q[(d4 << 2) + 3], kv.w, c3);
                }
                sc[jj] = ((c0 + c1) + (c2 + c3)) * SCALEF;
            }
            float cmax = fmaxf(fmaxf(fmaxf(sc[0], sc[1]), fmaxf(sc[2], sc[3])),
                               fmaxf(fmaxf(sc[4], sc[5]), fmaxf(sc[6], sc[7])));
            float mnew = fmaxf(mrun, cmax);
            float esc  = __expf(mrun - mnew);
            float p[8]; float ps = 0.f;
#pragma unroll
            for (int jj = 0; jj < 8; jj++) { p[jj] = __expf(sc[jj] - mnew); ps += p[jj]; }
            lrun = lrun * esc + ps;
            mrun = mnew;
#pragma unroll
            for (int d4 = 0; d4 < 16; d4++) {
                float a0 = acc[(d4 << 2) + 0] * esc;
                float a1 = acc[(d4 << 2) + 1] * esc;
                float a2 = acc[(d4 << 2) + 2] * esc;
                float a3 = acc[(d4 << 2) + 3] * esc;
#pragma unroll
                for (int jj = 0; jj < 8; jj++) {
                    float4 vv = V4[((j0 + jj) << 4) + d4];
                    a0 = fmaf(p[jj], vv.x, a0);
                    a1 = fmaf(p[jj], vv.y, a1);
                    a2 = fmaf(p[jj], vv.z, a2);
                    a3 = fmaf(p[jj], vv.w, a3);
                }
                acc[(d4 << 2) + 0] = a0; acc[(d4 << 2) + 1] = a1;
                acc[(d4 << 2) + 2] = a2; acc[(d4 << 2) + 3] = a3;
            }
        }
        __syncthreads();
    }

    const float inv = 1.0f / lrun;
    const size_t obase = ((size_t)(b * NN + m * BSZ + t) * DD) + h * HDD;
#pragma unroll
    for (int d = 0; d < 64; d += 4) {
        float f[4], r[4];
#pragma unroll
        for (int j = 0; j < 4; j++) {
            f[j] = acc[d + j] * inv;
            __nv_bfloat16 hb = __float2bfloat16(f[j]);
            r[j] = f[j] - __bfloat162float(hb);
        }
        uint2 ph, pl;
        ph.x = pack2h(f[0], f[1]); ph.y = pack2h(f[2], f[3]);
        pl.x = pack2h(r[0], r[1]); pl.y = pack2h(r[2], r[3]);
        *(uint2*)(g_ah + obase + d) = ph;
        *(uint2*)(g_al + obase + d) = pl;
    }
}

// =====================================================================
// Launch
// =====================================================================
extern "C" void kernel_launch(void* const* d_in, const int* in_sizes, int n_in,
                              void* d_out, int out_size)
{
    const float* x = nullptr; const float* qkv_w = nullptr;
    const float* proj_w = nullptr; const float* proj_b = nullptr;
    for (int i = 0; i < n_in; i++) {
        if      (in_sizes[i] == BB * NN * DD) x      = (const float*)d_in[i];
        else if (in_sizes[i] == 3 * DD * DD)  qkv_w  = (const float*)d_in[i];
        else if (in_sizes[i] == DD * DD)      proj_w = (const float*)d_in[i];
        else if (in_sizes[i] == DD)           proj_b = (const float*)d_in[i];
    }
    float* out = (float*)d_out;

    void* p;
    cudaGetSymbolAddress(&p, g_qkv); float* qkv = (float*)p;
    __nv_bfloat16 *xh, *xl, *wqh, *wql, *wph, *wpl, *ah, *al;
    cudaGetSymbolAddress(&p, g_xh);  xh  = (__nv_bfloat16*)p;
    cudaGetSymbolAddress(&p, g_xl);  xl  = (__nv_bfloat16*)p;
    cudaGetSymbolAddress(&p, g_wqh); wqh = (__nv_bfloat16*)p;
    cudaGetSymbolAddress(&p, g_wql); wql = (__nv_bfloat16*)p;
    cudaGetSymbolAddress(&p, g_wph); wph = (__nv_bfloat16*)p;
    cudaGetSymbolAddress(&p, g_wpl); wpl = (__nv_bfloat16*)p;
    cudaGetSymbolAddress(&p, g_ah);  ah  = (__nv_bfloat16*)p;
    cudaGetSymbolAddress(&p, g_al);  al  = (__nv_bfloat16*)p;

    static int attr_done = 0;
    if (!attr_done) {
        cudaFuncSetAttribute(gemm_mma, cudaFuncAttributeMaxDynamicSharedMemorySize, GEMM_SMEM);
        cudaFuncSetAttribute(attn_kernel, cudaFuncAttributeMaxDynamicSharedMemorySize, ATT_SMEM);
        attr_done = 1;
    }

    {
        int n4 = TOK * DD / 4;
        split_kernel<<<(n4 + 255) / 256, 256>>>(x, xh, xl, n4);
        n4 = 3 * DD * DD / 4;
        split_kernel<<<(n4 + 255) / 256, 256>>>(qkv_w, wqh, wql, n4);
        n4 = DD * DD / 4;
        split_kernel<<<(n4 + 255) / 256, 256>>>(proj_w, wph, wpl, n4);
    }
    gemm_mma<<<dim3(3 * DD / 128, TOK / 128), 256, GEMM_SMEM>>>(
        xh, xl, wqh, wql, nullptr, qkv, 3 * DD, DD, 0);
    pool_kernel<<<BB * HH * MM, 64>>>();
    mask_kernel<<<BB * HH * MM, 32>>>();
    attn_kernel<<<BB * HH * MM, 64, ATT_SMEM>>>();
    gemm_mma<<<dim3(DD / 128, TOK / 128), 256, GEMM_SMEM>>>(
        ah, al, wph, wpl, proj_b, out, DD, DD, 1);
}

// round 7
// speedup vs baseline: 2.5066x; 1.0039x over previous
#include <cuda_runtime.h>
#include <cuda_bf16.h>
#include <math.h>
#include <stdint.h>

// Problem constants
#define BB   2
#define NN   2048
#define DD   1024
#define HH   16
#define HDD  64
#define BSZ  64
#define MM   32
#define MAXK 32
#define SCALEF 0.125f
#define TOK  (BB * NN)

// ---------------- scratch ----------------
__device__ float g_qkv [TOK * 3 * DD];
__device__ float g_qb  [BB * HH * MM * HDD];
__device__ float g_kb  [BB * HH * MM * HDD];
__device__ int   g_kept[BB * HH * MM * MAXK];
__device__ int   g_kcnt[BB * HH * MM];
__device__ __nv_bfloat16 g_xh [TOK * DD],     g_xl [TOK * DD];
__device__ __nv_bfloat16 g_wqh[3 * DD * DD],  g_wql[3 * DD * DD];
__device__ __nv_bfloat16 g_wph[DD * DD],      g_wpl[DD * DD];
__device__ __nv_bfloat16 g_ah [TOK * DD],     g_al [TOK * DD];

// =====================================================================
// helpers
// =====================================================================
static __device__ __forceinline__ uint32_t pack2h(float a, float b) {
    return (uint32_t)__bfloat16_as_ushort(__float2bfloat16(a)) |
           ((uint32_t)__bfloat16_as_ushort(__float2bfloat16(b)) << 16);
}
static __device__ __forceinline__ uint32_t smem_u32(const void* p) {
    uint32_t a;
    asm("{ .reg .u64 t; cvta.to.shared.u64 t, %1; cvt.u32.u64 %0, t; }"
        : "=r"(a) : "l"(p));
    return a;
}
static __device__ __forceinline__ void cp16(uint32_t s, const void* g) {
    asm volatile("cp.async.cg.shared.global [%0], [%1], 16;"
                 :: "r"(s), "l"(g) : "memory");
}
static __device__ __forceinline__ void ldm4(uint32_t* r, uint32_t a) {
    asm volatile("ldmatrix.sync.aligned.m8n8.x4.shared.b16 {%0,%1,%2,%3}, [%4];"
        : "=r"(r[0]), "=r"(r[1]), "=r"(r[2]), "=r"(r[3]) : "r"(a));
}

__global__ __launch_bounds__(256) void split_kernel(
    const float* __restrict__ src,
    __nv_bfloat16* __restrict__ hi, __nv_bfloat16* __restrict__ lo, int n4)
{
    int i = blockIdx.x * blockDim.x + threadIdx.x;
    if (i >= n4) return;
    float4 v = ((const float4*)src)[i];
    float f[4] = {v.x, v.y, v.z, v.w};
    float r[4];
#pragma unroll
    for (int j = 0; j < 4; j++) {
        __nv_bfloat16 h = __float2bfloat16(f[j]);
        r[j] = f[j] - __bfloat162float(h);
    }
    uint2 ph, pl;
    ph.x = pack2h(f[0], f[1]); ph.y = pack2h(f[2], f[3]);
    pl.x = pack2h(r[0], r[1]); pl.y = pack2h(r[2], r[3]);
    ((uint2*)hi)[i] = ph;
    ((uint2*)lo)[i] = pl;
}

// =====================================================================
// bf16x3 warp-MMA GEMM (NT): 2-stage cp.async pipeline, K-chunk 32,
// 2 CTAs/SM. CTA 128x128, 256 thr, warp tile 64x32.
// =====================================================================
#define PADK 40
#define TILE_E (128 * PADK)                    // uint16 per tile
#define STAGE_B (4u * TILE_E * 2u)             // bytes: Ah Al Bh Bl = 40960
#define GEMM_SMEM (2u * STAGE_B)               // 81920 B

#define MMA_BF16(c, a, b)                                                  \
    asm volatile("mma.sync.aligned.m16n8k16.row.col.f32.bf16.bf16.f32 "    \
        "{%0,%1,%2,%3}, {%4,%5,%6,%7}, {%8,%9}, {%0,%1,%2,%3};"            \
        : "+f"((c)[0]), "+f"((c)[1]), "+f"((c)[2]), "+f"((c)[3])           \
        : "r"((a)[0]), "r"((a)[1]), "r"((a)[2]), "r"((a)[3]),              \
          "r"((b)[0]), "r"((b)[1]))

__global__ __launch_bounds__(256, 2) void gemm_mma(
    const __nv_bfloat16* __restrict__ Ah_, const __nv_bfloat16* __restrict__ Al_,
    const __nv_bfloat16* __restrict__ Bh_, const __nv_bfloat16* __restrict__ Bl_,
    const float* __restrict__ bias, float* __restrict__ C,
    int Nc, int K, int useBias)
{
    extern __shared__ __align__(16) uint16_t smg[];
    const uint32_t sbase = smem_u32(smg);

    const int tid  = threadIdx.x;
    const int wid  = tid >> 5;
    const int lane = tid & 31;
    const int wm   = wid & 1;
    const int wn   = wid >> 1;
    const int bm   = blockIdx.y * 128;
    const int bn   = blockIdx.x * 128;

    // cp.async coords: chunk = 32 elems = 64B = 4 x 16B pieces per row
    // lin = tid + 256*j (j<2), row = lin>>2, c = lin&3
    const int crow0 = tid >> 2;
    const int ccb   = (tid & 3) << 4;          // byte offset within chunk row
    // ldmatrix per-lane byte offsets
    uint32_t aoff[4];
#pragma unroll
    for (int mt = 0; mt < 4; mt++) {
        int mrow = wm * 64 + mt * 16 + (lane & 15);
        int ke   = (lane >> 4) << 3;
        aoff[mt] = (uint32_t)((mrow * PADK + ke) * 2);
    }
    uint32_t boff[2];
#pragma unroll
    for (int np = 0; np < 2; np++) {
        int nrow = wn * 32 + np * 16 + ((lane >> 4) << 3) + (lane & 7);
        int ke   = ((lane >> 3) & 1) << 3;
        boff[np] = (uint32_t)((nrow * PADK + ke) * 2);
    }

    float acc[4][4][4];
#pragma unroll
    for (int mt = 0; mt < 4; mt++)
#pragma unroll
        for (int nt = 0; nt < 4; nt++)
#pragma unroll
            for (int r = 0; r < 4; r++) acc[mt][nt][r] = 0.0f;

    const int NCH = K >> 5;                    // 32 chunks

    auto issue = [&](int ch, int st) {
        const int k0 = ch << 5;
        const uint32_t stg = sbase + (uint32_t)st * STAGE_B;
#pragma unroll
        for (int j = 0; j < 2; j++) {
            int row = crow0 + (j << 6);
            uint32_t dst = (uint32_t)(row * PADK * 2) + ccb;
            size_t offA = (size_t)(bm + row) * K + k0 + (ccb >> 1);
            size_t offB = (size_t)(bn + row) * K + k0 + (ccb >> 1);
            cp16(stg + dst,              Ah_ + offA);
            cp16(stg + TILE_E * 2 + dst, Al_ + offA);
            cp16(stg + TILE_E * 4 + dst, Bh_ + offB);
            cp16(stg + TILE_E * 6 + dst, Bl_ + offB);
        }
    };

    issue(0, 0);
    asm volatile("cp.async.commit_group;" ::: "memory");

    for (int ch = 0; ch < NCH; ch++) {
        // stage (ch+1)&1 was last read in iteration ch-1; the barrier below
        // (previous iteration's post-wait sync) already retired those reads.
        if (ch + 1 < NCH) issue(ch + 1, (ch + 1) & 1);
        asm volatile("cp.async.commit_group;" ::: "memory");
        asm volatile("cp.async.wait_group 1;" ::: "memory");   // chunk ch done
        __syncthreads();                                        // all threads' copies visible

        const uint32_t stg = sbase + (uint32_t)(ch & 1) * STAGE_B;

#pragma unroll
        for (int ks = 0; ks < 2; ks++) {
            const uint32_t kadd = (uint32_t)(ks << 5);
            uint32_t fah[4][4], fal[4][4], fbh[2][4], fbl[2][4];
#pragma unroll
            for (int mt = 0; mt < 4; mt++) {
                ldm4(fah[mt], stg + aoff[mt] + kadd);
                ldm4(fal[mt], stg + TILE_E * 2 + aoff[mt] + kadd);
            }
#pragma unroll
            for (int np = 0; np < 2; np++) {
                ldm4(fbh[np], stg + TILE_E * 4 + boff[np] + kadd);
                ldm4(fbl[np], stg + TILE_E * 6 + boff[np] + kadd);
            }
#pragma unroll
            for (int mt = 0; mt < 4; mt++)
#pragma unroll
                for (int nt = 0; nt < 4; nt++)
                    MMA_BF16(acc[mt][nt], fah[mt], &fbh[nt >> 1][(nt & 1) << 1]);
#pragma unroll
            for (int mt = 0; mt < 4; mt++)
#pragma unroll
                for (int nt = 0; nt < 4; nt++)
                    MMA_BF16(acc[mt][nt], fah[mt], &fbl[nt >> 1][(nt & 1) << 1]);
#pragma unroll
            for (int mt = 0; mt < 4; mt++)
#pragma unroll
                for (int nt = 0; nt < 4; nt++)
                    MMA_BF16(acc[mt][nt], fal[mt], &fbh[nt >> 1][(nt & 1) << 1]);
        }
        __syncthreads();   // reads of stage ch&1 done -> safe to overwrite next iter
    }

    // epilogue
    const int g = lane >> 2;
    const int t = lane & 3;
#pragma unroll
    for (int nt = 0; nt < 4; nt++) {
        int col = bn + wn * 32 + nt * 8 + t * 2;
        float b0v = useBias ? bias[col]     : 0.0f;
        float b1v = useBias ? bias[col + 1] : 0.0f;
#pragma unroll
        for (int mt = 0; mt < 4; mt++) {
            int row = bm + wm * 64 + mt * 16 + g;
            float2 lo2, hi2;
            lo2.x = acc[mt][nt][0] + b0v; lo2.y = acc[mt][nt][1] + b1v;
            hi2.x = acc[mt][nt][2] + b0v; hi2.y = acc[mt][nt][3] + b1v;
            *(float2*)(C + (size_t)row * Nc + col)       = lo2;
            *(float2*)(C + (size_t)(row + 8) * Nc + col) = hi2;
        }
    }
}

// =====================================================================
// Block-mean pooling
// =====================================================================
__global__ __launch_bounds__(64) void pool_kernel()
{
    const int row = blockIdx.x;
    const int d   = threadIdx.x;
    const int m   = row % MM;
    const int b   = row / (MM * HH);
    const int h   = (row / MM) % HH;

    const float* base = g_qkv + ((size_t)(b * NN + m * BSZ) * (3 * DD)) + h * HDD + d;
    float sq = 0.0f, sk = 0.0f;
    for (int i = 0; i < BSZ; i++) {
        sq += base[(size_t)i * 3 * DD];
        sk += base[(size_t)i * 3 * DD + DD];
    }
    g_qb[(size_t)row * HDD + d] = sq * (1.0f / BSZ);
    g_kb[(size_t)row * HDD + d] = sk * (1.0f / BSZ);
}

// =====================================================================
// Block scores + top-2 threshold + diagonal keep
// =====================================================================
__global__ __launch_bounds__(32) void mask_kernel()
{
    const int row  = blockIdx.x;
    const int lane = threadIdx.x;
    const int m    = row % MM;
    const int bh   = row / MM;

    const float* qb = g_qb + (size_t)row * HDD;
    const float* kb = g_kb + ((size_t)bh * MM + lane) * HDD;

    float s = 0.0f;
    for (int d = 0; d < HDD; d++) s = fmaf(qb[d], kb[d], s);
    s *= SCALEF;

    const unsigned FULL = 0xffffffffu;
    float m1 = s;
#pragma unroll
    for (int off = 16; off; off >>= 1) m1 = fmaxf(m1, __shfl_xor_sync(FULL, m1, off));
    unsigned b1 = __ballot_sync(FULL, s == m1);
    int lead = __ffs(b1) - 1;
    float v2 = (lane == lead) ? -INFINITY : s;
    float m2 = v2;
#pragma unroll
    for (int off = 16; off; off >>= 1) m2 = fmaxf(m2, __shfl_xor_sync(FULL, m2, off));

    bool keep = (s >= m2) || (lane == m);
    unsigned km = __ballot_sync(FULL, keep);
    if (lane == 0) g_kcnt[row] = __popc(km);
    if (keep) {
        int pos = __popc(km & ((1u << lane) - 1u));
        g_kept[(size_t)row * MAXK + pos] = lane;
    }
}

// =====================================================================
// Sparse block attention: single-stage K/V smem (32KB -> high occupancy),
// online softmax chunked 8 keys, bf16 hi/lo epilogue.
// =====================================================================
#define ATT_SMEM (8192u * 4u)     // K 64x64 + V 64x64 fp32

__global__ __launch_bounds__(64) void attn_kernel()
{
    extern __shared__ __align__(16) float asm_f[];

    const int row = blockIdx.x;
    const int t   = threadIdx.x;
    const int m   = row % MM;
    const int h   = (row / MM) % HH;
    const int b   = row / (MM * HH);

    const uint32_t sbase = smem_u32(asm_f);

    const float* qptr = g_qkv + ((size_t)(b * NN + m * BSZ + t) * (3 * DD)) + h * HDD;
    float q[64];
#pragma unroll
    for (int d4 = 0; d4 < 16; d4++) {
        float4 v = *(const float4*)(qptr + (d4 << 2));
        q[(d4 << 2) + 0] = v.x; q[(d4 << 2) + 1] = v.y;
        q[(d4 << 2) + 2] = v.z; q[(d4 << 2) + 3] = v.w;
    }

    float acc[64];
#pragma unroll
    for (int d = 0; d < 64; d++) acc[d] = 0.0f;
    float mrun = -INFINITY, lrun = 0.0f;

    const int cnt = g_kcnt[row];
    const int*  kept = g_kept + (size_t)row * MAXK;
    const float* hk  = g_qkv + DD + h * HDD;

    for (int kbi = 0; kbi < cnt; kbi++) {
        if (kbi > 0) __syncthreads();   // previous tile reads done
        const int nblk = kept[kbi];
        const float* kb = hk + (size_t)(b * NN + nblk * BSZ) * (3 * DD);
#pragma unroll
        for (int j = 0; j < 16; j++) {
            int i = t + (j << 6);
            int r = i >> 4, c4 = i & 15;
            uint32_t so = sbase + (uint32_t)((r << 6) + (c4 << 2)) * 4u;
            const float* gk = kb + (size_t)r * 3 * DD + (c4 << 2);
            cp16(so, gk);
            cp16(so + 16384u, gk + DD);
        }
        asm volatile("cp.async.commit_group;" ::: "memory");
        asm volatile("cp.async.wait_group 0;" ::: "memory");
        __syncthreads();

        const float4* K4 = (const float4*)asm_f;
        const float4* V4 = K4 + 1024;

        for (int j0 = 0; j0 < 64; j0 += 8) {
            float sc[8];
#pragma unroll
            for (int jj = 0; jj < 8; jj++) {
                const float4* kr = K4 + ((j0 + jj) << 4);
                float c0 = 0.f, c1 = 0.f, c2 = 0.f, c3 = 0.f;
#pragma unroll
                for (int d4 = 0; d4 < 16; d4++) {
                    float4 kv = kr[d4];
                    c0 = fmaf(q[(d4 << 2) + 0], kv.x, c0);
                    c1 = fmaf(q[(d4 << 2) + 1], kv.y, c1);
                    c2 = fmaf(q[(d4 << 2) + 2], kv.z, c2);
                    c3 = fmaf(q[(d4 << 2) + 3], kv.w, c3);
                }
                sc[jj] = ((c0 + c1) + (c2 + c3)) * SCALEF;
            }
            float cmax = fmaxf(fmaxf(fmaxf(sc[0], sc[1]), fmaxf(sc[2], sc[3])),
                               fmaxf(fmaxf(sc[4], sc[5]), fmaxf(sc[6], sc[7])));
            float mnew = fmaxf(mrun, cmax);
            float esc  = __expf(mrun - mnew);
            float p[8]; float ps = 0.f;
#pragma unroll
            for (int jj = 0; jj < 8; jj++) { p[jj] = __expf(sc[jj] - mnew); ps += p[jj]; }
            lrun = lrun * esc + ps;
            mrun = mnew;
#pragma unroll
            for (int d4 = 0; d4 < 16; d4++) {
                float a0 = acc[(d4 << 2) + 0] * esc;
                float a1 = acc[(d4 << 2) + 1] * esc;
                float a2 = acc[(d4 << 2) + 2] * esc;
                float a3 = acc[(d4 << 2) + 3] * esc;
#pragma unroll
                for (int jj = 0; jj < 8; jj++) {
                    float4 vv = V4[((j0 + jj) << 4) + d4];
                    a0 = fmaf(p[jj], vv.x, a0);
                    a1 = fmaf(p[jj], vv.y, a1);
                    a2 = fmaf(p[jj], vv.z, a2);
                    a3 = fmaf(p[jj], vv.w, a3);
                }
                acc[(d4 << 2) + 0] = a0; acc[(d4 << 2) + 1] = a1;
                acc[(d4 << 2) + 2] = a2; acc[(d4 << 2) + 3] = a3;
            }
        }
    }

    const float inv = 1.0f / lrun;
    const size_t obase = ((size_t)(b * NN + m * BSZ + t) * DD) + h * HDD;
#pragma unroll
    for (int d = 0; d < 64; d += 4) {
        float f[4], r[4];
#pragma unroll
        for (int j = 0; j < 4; j++) {
            f[j] = acc[d + j] * inv;
            __nv_bfloat16 hb = __float2bfloat16(f[j]);
            r[j] = f[j] - __bfloat162float(hb);
        }
        uint2 ph, pl;
        ph.x = pack2h(f[0], f[1]); ph.y = pack2h(f[2], f[3]);
        pl.x = pack2h(r[0], r[1]); pl.y = pack2h(r[2], r[3]);
        *(uint2*)(g_ah + obase + d) = ph;
        *(uint2*)(g_al + obase + d) = pl;
    }
}

// =====================================================================
// Launch
// =====================================================================
extern "C" void kernel_launch(void* const* d_in, const int* in_sizes, int n_in,
                              void* d_out, int out_size)
{
    const float* x = nullptr; const float* qkv_w = nullptr;
    const float* proj_w = nullptr; const float* proj_b = nullptr;
    for (int i = 0; i < n_in; i++) {
        if      (in_sizes[i] == BB * NN * DD) x      = (const float*)d_in[i];
        else if (in_sizes[i] == 3 * DD * DD)  qkv_w  = (const float*)d_in[i];
        else if (in_sizes[i] == DD * DD)      proj_w = (const float*)d_in[i];
        else if (in_sizes[i] == DD)           proj_b = (const float*)d_in[i];
    }
    float* out = (float*)d_out;

    void* p;
    cudaGetSymbolAddress(&p, g_qkv); float* qkv = (float*)p;
    __nv_bfloat16 *xh, *xl, *wqh, *wql, *wph, *wpl, *ah, *al;
    cudaGetSymbolAddress(&p, g_xh);  xh  = (__nv_bfloat16*)p;
    cudaGetSymbolAddress(&p, g_xl);  xl  = (__nv_bfloat16*)p;
    cudaGetSymbolAddress(&p, g_wqh); wqh = (__nv_bfloat16*)p;
    cudaGetSymbolAddress(&p, g_wql); wql = (__nv_bfloat16*)p;
    cudaGetSymbolAddress(&p, g_wph); wph = (__nv_bfloat16*)p;
    cudaGetSymbolAddress(&p, g_wpl); wpl = (__nv_bfloat16*)p;
    cudaGetSymbolAddress(&p, g_ah);  ah  = (__nv_bfloat16*)p;
    cudaGetSymbolAddress(&p, g_al);  al  = (__nv_bfloat16*)p;

    static int attr_done = 0;
    if (!attr_done) {
        cudaFuncSetAttribute(gemm_mma, cudaFuncAttributeMaxDynamicSharedMemorySize, GEMM_SMEM);
        cudaFuncSetAttribute(attn_kernel, cudaFuncAttributeMaxDynamicSharedMemorySize, ATT_SMEM);
        attr_done = 1;
    }

    {
        int n4 = TOK * DD / 4;
        split_kernel<<<(n4 + 255) / 256, 256>>>(x, xh, xl, n4);
        n4 = 3 * DD * DD / 4;
        split_kernel<<<(n4 + 255) / 256, 256>>>(qkv_w, wqh, wql, n4);
        n4 = DD * DD / 4;
        split_kernel<<<(n4 + 255) / 256, 256>>>(proj_w, wph, wpl, n4);
    }
    gemm_mma<<<dim3(3 * DD / 128, TOK / 128), 256, GEMM_SMEM>>>(
        xh, xl, wqh, wql, nullptr, qkv, 3 * DD, DD, 0);
    pool_kernel<<<BB * HH * MM, 64>>>();
    mask_kernel<<<BB * HH * MM, 32>>>();
    attn_kernel<<<BB * HH * MM, 64, ATT_SMEM>>>();
    gemm_mma<<<dim3(DD / 128, TOK / 128), 256, GEMM_SMEM>>>(
        ah, al, wph, wpl, proj_b, out, DD, DD, 1);
}

// round 8
// speedup vs baseline: 2.5723x; 1.0262x over previous
#include <cuda_runtime.h>
#include <cuda_bf16.h>
#include <math.h>
#include <stdint.h>

// Problem constants
#define BB   2
#define NN   2048
#define DD   1024
#define HH   16
#define HDD  64
#define BSZ  64
#define MM   32
#define MAXK 32
#define SCALEF 0.125f
#define TOK  (BB * NN)

typedef unsigned long long ull;

// ---------------- scratch ----------------
__device__ float g_qkv [TOK * 3 * DD];
__device__ float g_qb  [BB * HH * MM * HDD];
__device__ float g_kb  [BB * HH * MM * HDD];
__device__ int   g_kept[BB * HH * MM * MAXK];
__device__ int   g_kcnt[BB * HH * MM];
__device__ __nv_bfloat16 g_xh [TOK * DD],     g_xl [TOK * DD];
__device__ __nv_bfloat16 g_wqh[3 * DD * DD],  g_wql[3 * DD * DD];
__device__ __nv_bfloat16 g_wph[DD * DD],      g_wpl[DD * DD];
__device__ __nv_bfloat16 g_ah [TOK * DD],     g_al [TOK * DD];

// =====================================================================
// helpers
// =====================================================================
static __device__ __forceinline__ uint32_t pack2h(float a, float b) {
    return (uint32_t)__bfloat16_as_ushort(__float2bfloat16(a)) |
           ((uint32_t)__bfloat16_as_ushort(__float2bfloat16(b)) << 16);
}
static __device__ __forceinline__ uint32_t smem_u32(const void* p) {
    uint32_t a;
    asm("{ .reg .u64 t; cvta.to.shared.u64 t, %1; cvt.u32.u64 %0, t; }"
        : "=r"(a) : "l"(p));
    return a;
}
static __device__ __forceinline__ void cp16(uint32_t s, const void* g) {
    asm volatile("cp.async.cg.shared.global [%0], [%1], 16;"
                 :: "r"(s), "l"(g) : "memory");
}
static __device__ __forceinline__ void ldm4(uint32_t* r, uint32_t a) {
    asm volatile("ldmatrix.sync.aligned.m8n8.x4.shared.b16 {%0,%1,%2,%3}, [%4];"
        : "=r"(r[0]), "=r"(r[1]), "=r"(r[2]), "=r"(r[3]) : "r"(a));
}
// ---- packed f32x2 (Blackwell) ----
static __device__ __forceinline__ ull pk2(float a, float b) {
    ull r; asm("mov.b64 %0, {%1,%2};" : "=l"(r) : "f"(a), "f"(b)); return r;
}
static __device__ __forceinline__ void upk2(ull v, float* a, float* b) {
    asm("mov.b64 {%0,%1}, %2;" : "=f"(*a), "=f"(*b) : "l"(v));
}
static __device__ __forceinline__ ull fma2(ull a, ull b, ull c) {
    ull d; asm("fma.rn.f32x2 %0, %1, %2, %3;" : "=l"(d) : "l"(a), "l"(b), "l"(c));
    return d;
}
static __device__ __forceinline__ ull mul2(ull a, ull b) {
    ull d; asm("mul.rn.f32x2 %0, %1, %2;" : "=l"(d) : "l"(a), "l"(b));
    return d;
}

// =====================================================================
// fused fp32 -> bf16 hi/lo split for all three tensors
// =====================================================================
#define N4_X (TOK * DD / 4)
#define N4_WQ (3 * DD * DD / 4)
#define N4_WP (DD * DD / 4)

__global__ __launch_bounds__(256) void split3_kernel(
    const float* __restrict__ sx, __nv_bfloat16* __restrict__ xh, __nv_bfloat16* __restrict__ xl,
    const float* __restrict__ sq, __nv_bfloat16* __restrict__ qh, __nv_bfloat16* __restrict__ ql,
    const float* __restrict__ sp, __nv_bfloat16* __restrict__ ph, __nv_bfloat16* __restrict__ pl)
{
    int i = blockIdx.x * blockDim.x + threadIdx.x;
    const float* src; __nv_bfloat16 *hi, *lo;
    if (i < N4_X)               { src = sx; hi = xh; lo = xl; }
    else if (i < N4_X + N4_WQ)  { i -= N4_X; src = sq; hi = qh; lo = ql; }
    else                        { i -= N4_X + N4_WQ; if (i >= N4_WP) return;
                                  src = sp; hi = ph; lo = pl; }
    float4 v = ((const float4*)src)[i];
    float f[4] = {v.x, v.y, v.z, v.w};
    float r[4];
#pragma unroll
    for (int j = 0; j < 4; j++) {
        __nv_bfloat16 h = __float2bfloat16(f[j]);
        r[j] = f[j] - __bfloat162float(h);
    }
    uint2 phh, pll;
    phh.x = pack2h(f[0], f[1]); phh.y = pack2h(f[2], f[3]);
    pll.x = pack2h(r[0], r[1]); pll.y = pack2h(r[2], r[3]);
    ((uint2*)hi)[i] = phh;
    ((uint2*)lo)[i] = pll;
}

// =====================================================================
// bf16x3 warp-MMA GEMM (NT): 2-stage cp.async pipeline, K-chunk 32,
// 2 CTAs/SM. CTA 128x128, 256 thr, warp tile 64x32.  (unchanged from R7)
// =====================================================================
#define PADK 40
#define TILE_E (128 * PADK)
#define STAGE_B (4u * TILE_E * 2u)
#define GEMM_SMEM (2u * STAGE_B)

#define MMA_BF16(c, a, b)                                                  \
    asm volatile("mma.sync.aligned.m16n8k16.row.col.f32.bf16.bf16.f32 "    \
        "{%0,%1,%2,%3}, {%4,%5,%6,%7}, {%8,%9}, {%0,%1,%2,%3};"            \
        : "+f"((c)[0]), "+f"((c)[1]), "+f"((c)[2]), "+f"((c)[3])           \
        : "r"((a)[0]), "r"((a)[1]), "r"((a)[2]), "r"((a)[3]),              \
          "r"((b)[0]), "r"((b)[1]))

__global__ __launch_bounds__(256, 2) void gemm_mma(
    const __nv_bfloat16* __restrict__ Ah_, const __nv_bfloat16* __restrict__ Al_,
    const __nv_bfloat16* __restrict__ Bh_, const __nv_bfloat16* __restrict__ Bl_,
    const float* __restrict__ bias, float* __restrict__ C,
    int Nc, int K, int useBias)
{
    extern __shared__ __align__(16) uint16_t smg[];
    const uint32_t sbase = smem_u32(smg);

    const int tid  = threadIdx.x;
    const int wid  = tid >> 5;
    const int lane = tid & 31;
    const int wm   = wid & 1;
    const int wn   = wid >> 1;
    const int bm   = blockIdx.y * 128;
    const int bn   = blockIdx.x * 128;

    const int crow0 = tid >> 2;
    const int ccb   = (tid & 3) << 4;
    uint32_t aoff[4];
#pragma unroll
    for (int mt = 0; mt < 4; mt++) {
        int mrow = wm * 64 + mt * 16 + (lane & 15);
        int ke   = (lane >> 4) << 3;
        aoff[mt] = (uint32_t)((mrow * PADK + ke) * 2);
    }
    uint32_t boff[2];
#pragma unroll
    for (int np = 0; np < 2; np++) {
        int nrow = wn * 32 + np * 16 + ((lane >> 4) << 3) + (lane & 7);
        int ke   = ((lane >> 3) & 1) << 3;
        boff[np] = (uint32_t)((nrow * PADK + ke) * 2);
    }

    float acc[4][4][4];
#pragma unroll
    for (int mt = 0; mt < 4; mt++)
#pragma unroll
        for (int nt = 0; nt < 4; nt++)
#pragma unroll
            for (int r = 0; r < 4; r++) acc[mt][nt][r] = 0.0f;

    const int NCH = K >> 5;

    auto issue = [&](int ch, int st) {
        const int k0 = ch << 5;
        const uint32_t stg = sbase + (uint32_t)st * STAGE_B;
#pragma unroll
        for (int j = 0; j < 2; j++) {
            int row = crow0 + (j << 6);
            uint32_t dst = (uint32_t)(row * PADK * 2) + ccb;
            size_t offA = (size_t)(bm + row) * K + k0 + (ccb >> 1);
            size_t offB = (size_t)(bn + row) * K + k0 + (ccb >> 1);
            cp16(stg + dst,              Ah_ + offA);
            cp16(stg + TILE_E * 2 + dst, Al_ + offA);
            cp16(stg + TILE_E * 4 + dst, Bh_ + offB);
            cp16(stg + TILE_E * 6 + dst, Bl_ + offB);
        }
    };

    issue(0, 0);
    asm volatile("cp.async.commit_group;" ::: "memory");

    for (int ch = 0; ch < NCH; ch++) {
        if (ch + 1 < NCH) issue(ch + 1, (ch + 1) & 1);
        asm volatile("cp.async.commit_group;" ::: "memory");
        asm volatile("cp.async.wait_group 1;" ::: "memory");
        __syncthreads();

        const uint32_t stg = sbase + (uint32_t)(ch & 1) * STAGE_B;

#pragma unroll
        for (int ks = 0; ks < 2; ks++) {
            const uint32_t kadd = (uint32_t)(ks << 5);
            uint32_t fah[4][4], fal[4][4], fbh[2][4], fbl[2][4];
#pragma unroll
            for (int mt = 0; mt < 4; mt++) {
                ldm4(fah[mt], stg + aoff[mt] + kadd);
                ldm4(fal[mt], stg + TILE_E * 2 + aoff[mt] + kadd);
            }
#pragma unroll
            for (int np = 0; np < 2; np++) {
                ldm4(fbh[np], stg + TILE_E * 4 + boff[np] + kadd);
                ldm4(fbl[np], stg + TILE_E * 6 + boff[np] + kadd);
            }
#pragma unroll
            for (int mt = 0; mt < 4; mt++)
#pragma unroll
                for (int nt = 0; nt < 4; nt++)
                    MMA_BF16(acc[mt][nt], fah[mt], &fbh[nt >> 1][(nt & 1) << 1]);
#pragma unroll
            for (int mt = 0; mt < 4; mt++)
#pragma unroll
                for (int nt = 0; nt < 4; nt++)
                    MMA_BF16(acc[mt][nt], fah[mt], &fbl[nt >> 1][(nt & 1) << 1]);
#pragma unroll
            for (int mt = 0; mt < 4; mt++)
#pragma unroll
                for (int nt = 0; nt < 4; nt++)
                    MMA_BF16(acc[mt][nt], fal[mt], &fbh[nt >> 1][(nt & 1) << 1]);
        }
        __syncthreads();
    }

    const int g = lane >> 2;
    const int t = lane & 3;
#pragma unroll
    for (int nt = 0; nt < 4; nt++) {
        int col = bn + wn * 32 + nt * 8 + t * 2;
        float b0v = useBias ? bias[col]     : 0.0f;
        float b1v = useBias ? bias[col + 1] : 0.0f;
#pragma unroll
        for (int mt = 0; mt < 4; mt++) {
            int row = bm + wm * 64 + mt * 16 + g;
            float2 lo2, hi2;
            lo2.x = acc[mt][nt][0] + b0v; lo2.y = acc[mt][nt][1] + b1v;
            hi2.x = acc[mt][nt][2] + b0v; hi2.y = acc[mt][nt][3] + b1v;
            *(float2*)(C + (size_t)row * Nc + col)       = lo2;
            *(float2*)(C + (size_t)(row + 8) * Nc + col) = hi2;
        }
    }
}

// =====================================================================
// Block-mean pooling
// =====================================================================
__global__ __launch_bounds__(64) void pool_kernel()
{
    const int row = blockIdx.x;
    const int d   = threadIdx.x;
    const int m   = row % MM;
    const int b   = row / (MM * HH);
    const int h   = (row / MM) % HH;

    const float* base = g_qkv + ((size_t)(b * NN + m * BSZ) * (3 * DD)) + h * HDD + d;
    float sq = 0.0f, sk = 0.0f;
    for (int i = 0; i < BSZ; i++) {
        sq += base[(size_t)i * 3 * DD];
        sk += base[(size_t)i * 3 * DD + DD];
    }
    g_qb[(size_t)row * HDD + d] = sq * (1.0f / BSZ);
    g_kb[(size_t)row * HDD + d] = sk * (1.0f / BSZ);
}

// =====================================================================
// Block scores + top-2 threshold + diagonal keep
// =====================================================================
__global__ __launch_bounds__(32) void mask_kernel()
{
    const int row  = blockIdx.x;
    const int lane = threadIdx.x;
    const int m    = row % MM;
    const int bh   = row / MM;

    const float* qb = g_qb + (size_t)row * HDD;
    const float* kb = g_kb + ((size_t)bh * MM + lane) * HDD;

    float s = 0.0f;
    for (int d = 0; d < HDD; d++) s = fmaf(qb[d], kb[d], s);
    s *= SCALEF;

    const unsigned FULL = 0xffffffffu;
    float m1 = s;
#pragma unroll
    for (int off = 16; off; off >>= 1) m1 = fmaxf(m1, __shfl_xor_sync(FULL, m1, off));
    unsigned b1 = __ballot_sync(FULL, s == m1);
    int lead = __ffs(b1) - 1;
    float v2 = (lane == lead) ? -INFINITY : s;
    float m2 = v2;
#pragma unroll
    for (int off = 16; off; off >>= 1) m2 = fmaxf(m2, __shfl_xor_sync(FULL, m2, off));

    bool keep = (s >= m2) || (lane == m);
    unsigned km = __ballot_sync(FULL, keep);
    if (lane == 0) g_kcnt[row] = __popc(km);
    if (keep) {
        int pos = __popc(km & ((1u << lane) - 1u));
        g_kept[(size_t)row * MAXK + pos] = lane;
    }
}

// =====================================================================
// Sparse block attention with packed f32x2 math.
// Single-stage K/V smem (32KB), online softmax chunked 8 keys.
// =====================================================================
#define ATT_SMEM (8192u * 4u)

__global__ __launch_bounds__(64) void attn_kernel()
{
    extern __shared__ __align__(16) float asm_f[];

    const int row = blockIdx.x;
    const int t   = threadIdx.x;
    const int m   = row % MM;
    const int h   = (row / MM) % HH;
    const int b   = row / (MM * HH);

    const uint32_t sbase = smem_u32(asm_f);

    // q as 32 packed pairs: q2[i] = (q[2i], q[2i+1])
    const float* qptr = g_qkv + ((size_t)(b * NN + m * BSZ + t) * (3 * DD)) + h * HDD;
    ull q2[32];
#pragma unroll
    for (int i = 0; i < 32; i++) q2[i] = *(const ull*)(qptr + (i << 1));

    ull acc2[32];
#pragma unroll
    for (int i = 0; i < 32; i++) acc2[i] = 0ull;
    float mrun = -INFINITY, lrun = 0.0f;

    const int cnt = g_kcnt[row];
    const int*  kept = g_kept + (size_t)row * MAXK;
    const float* hk  = g_qkv + DD + h * HDD;

    for (int kbi = 0; kbi < cnt; kbi++) {
        if (kbi > 0) __syncthreads();
        const int nblk = kept[kbi];
        const float* kb = hk + (size_t)(b * NN + nblk * BSZ) * (3 * DD);
#pragma unroll
        for (int j = 0; j < 16; j++) {
            int i = t + (j << 6);
            int r = i >> 4, c4 = i & 15;
            uint32_t so = sbase + (uint32_t)((r << 6) + (c4 << 2)) * 4u;
            const float* gk = kb + (size_t)r * 3 * DD + (c4 << 2);
            cp16(so, gk);
            cp16(so + 16384u, gk + DD);
        }
        asm volatile("cp.async.commit_group;" ::: "memory");
        asm volatile("cp.async.wait_group 0;" ::: "memory");
        __syncthreads();

        const ull* K8 = (const ull*)asm_f;          // 64 rows x 32 pairs
        const ull* V8 = K8 + 2048;

        for (int j0 = 0; j0 < 64; j0 += 8) {
            float sc[8];
#pragma unroll
            for (int jj = 0; jj < 8; jj++) {
                const ull* kr = K8 + ((j0 + jj) << 5);
                ull s01 = 0ull, s23 = 0ull;
#pragma unroll
                for (int p = 0; p < 16; p++) {
                    s01 = fma2(q2[(p << 1)],     kr[(p << 1)],     s01);
                    s23 = fma2(q2[(p << 1) + 1], kr[(p << 1) + 1], s23);
                }
                float c0, c1, c2, c3;
                upk2(s01, &c0, &c1);
                upk2(s23, &c2, &c3);
                sc[jj] = ((c0 + c1) + (c2 + c3)) * SCALEF;
            }
            float cmax = fmaxf(fmaxf(fmaxf(sc[0], sc[1]), fmaxf(sc[2], sc[3])),
                               fmaxf(fmaxf(sc[4], sc[5]), fmaxf(sc[6], sc[7])));
            float mnew = fmaxf(mrun, cmax);
            float esc  = __expf(mrun - mnew);
            float p[8]; float ps = 0.f;
#pragma unroll
            for (int jj = 0; jj < 8; jj++) { p[jj] = __expf(sc[jj] - mnew); ps += p[jj]; }
            lrun = lrun * esc + ps;
            mrun = mnew;

            ull esc2 = pk2(esc, esc);
            ull p2[8];
#pragma unroll
            for (int jj = 0; jj < 8; jj++) p2[jj] = pk2(p[jj], p[jj]);
#pragma unroll
            for (int i = 0; i < 32; i++) {
                ull a = mul2(acc2[i], esc2);
#pragma unroll
                for (int jj = 0; jj < 8; jj++)
                    a = fma2(p2[jj], V8[((j0 + jj) << 5) + i], a);
                acc2[i] = a;
            }
        }
    }

    const float inv = 1.0f / lrun;
    const size_t obase = ((size_t)(b * NN + m * BSZ + t) * DD) + h * HDD;
#pragma unroll
    for (int i = 0; i < 32; i += 2) {
        float f[4], r[4];
        upk2(acc2[i],     &f[0], &f[1]);
        upk2(acc2[i + 1], &f[2], &f[3]);
#pragma unroll
        for (int j = 0; j < 4; j++) {
            f[j] *= inv;
            __nv_bfloat16 hb = __float2bfloat16(f[j]);
            r[j] = f[j] - __bfloat162float(hb);
        }
        uint2 ph, pl;
        ph.x = pack2h(f[0], f[1]); ph.y = pack2h(f[2], f[3]);
        pl.x = pack2h(r[0], r[1]); pl.y = pack2h(r[2], r[3]);
        *(uint2*)(g_ah + obase + (i << 1)) = ph;
        *(uint2*)(g_al + obase + (i << 1)) = pl;
    }
}

// =====================================================================
// Launch
// =====================================================================
extern "C" void kernel_launch(void* const* d_in, const int* in_sizes, int n_in,
                              void* d_out, int out_size)
{
    const float* x = nullptr; const float* qkv_w = nullptr;
    const float* proj_w = nullptr; const float* proj_b = nullptr;
    for (int i = 0; i < n_in; i++) {
        if      (in_sizes[i] == BB * NN * DD) x      = (const float*)d_in[i];
        else if (in_sizes[i] == 3 * DD * DD)  qkv_w  = (const float*)d_in[i];
        else if (in_sizes[i] == DD * DD)      proj_w = (const float*)d_in[i];
        else if (in_sizes[i] == DD)           proj_b = (const float*)d_in[i];
    }
    float* out = (float*)d_out;

    void* p;
    cudaGetSymbolAddress(&p, g_qkv); float* qkv = (float*)p;
    __nv_bfloat16 *xh, *xl, *wqh, *wql, *wph, *wpl, *ah, *al;
    cudaGetSymbolAddress(&p, g_xh);  xh  = (__nv_bfloat16*)p;
    cudaGetSymbolAddress(&p, g_xl);  xl  = (__nv_bfloat16*)p;
    cudaGetSymbolAddress(&p, g_wqh); wqh = (__nv_bfloat16*)p;
    cudaGetSymbolAddress(&p, g_wql); wql = (__nv_bfloat16*)p;
    cudaGetSymbolAddress(&p, g_wph); wph = (__nv_bfloat16*)p;
    cudaGetSymbolAddress(&p, g_wpl); wpl = (__nv_bfloat16*)p;
    cudaGetSymbolAddress(&p, g_ah);  ah  = (__nv_bfloat16*)p;
    cudaGetSymbolAddress(&p, g_al);  al  = (__nv_bfloat16*)p;

    static int attr_done = 0;
    if (!attr_done) {
        cudaFuncSetAttribute(gemm_mma, cudaFuncAttributeMaxDynamicSharedMemorySize, GEMM_SMEM);
        cudaFuncSetAttribute(attn_kernel, cudaFuncAttributeMaxDynamicSharedMemorySize, ATT_SMEM);
        attr_done = 1;
    }

    {
        int n4 = N4_X + N4_WQ + N4_WP;
        split3_kernel<<<(n4 + 255) / 256, 256>>>(x, xh, xl, qkv_w, wqh, wql,
                                                 proj_w, wph, wpl);
    }
    gemm_mma<<<dim3(3 * DD / 128, TOK / 128), 256, GEMM_SMEM>>>(
        xh, xl, wqh, wql, nullptr, qkv, 3 * DD, DD, 0);
    pool_kernel<<<BB * HH * MM, 64>>>();
    mask_kernel<<<BB * HH * MM, 32>>>();
    attn_kernel<<<BB * HH * MM, 64, ATT_SMEM>>>();
    gemm_mma<<<dim3(DD / 128, TOK / 128), 256, GEMM_SMEM>>>(
        ah, al, wph, wpl, proj_b, out, DD, DD, 1);
}

// round 9
// speedup vs baseline: 3.1867x; 1.2388x over previous
#include <cuda_runtime.h>
#include <cuda_fp16.h>
#include <math.h>
#include <stdint.h>

// Problem constants
#define BB   2
#define NN   2048
#define DD   1024
#define HH   16
#define HDD  64
#define BSZ  64
#define MM   32
#define MAXK 32
#define SCALEF 0.125f
#define TOK  (BB * NN)

typedef unsigned long long ull;

// ---------------- scratch ----------------
__device__ float g_qkv [TOK * 3 * DD];
__device__ float g_qb  [BB * HH * MM * HDD];
__device__ float g_kb  [BB * HH * MM * HDD];
__device__ int   g_kept[BB * HH * MM * MAXK];
__device__ int   g_kcnt[BB * HH * MM];
__device__ __half g_xh [TOK * DD], g_xl [TOK * DD];   // activations hi/lo (fp16)
__device__ __half g_wq [3 * DD * DD];                 // weights single fp16
__device__ __half g_wp [DD * DD];
__device__ __half g_ah [TOK * DD], g_al [TOK * DD];   // attn out hi/lo (fp16)

// =====================================================================
// helpers
// =====================================================================
static __device__ __forceinline__ uint32_t pack2f16(float a, float b) {
    return (uint32_t)__half_as_ushort(__float2half_rn(a)) |
           ((uint32_t)__half_as_ushort(__float2half_rn(b)) << 16);
}
static __device__ __forceinline__ uint32_t smem_u32(const void* p) {
    uint32_t a;
    asm("{ .reg .u64 t; cvta.to.shared.u64 t, %1; cvt.u32.u64 %0, t; }"
        : "=r"(a) : "l"(p));
    return a;
}
static __device__ __forceinline__ void cp16(uint32_t s, const void* g) {
    asm volatile("cp.async.cg.shared.global [%0], [%1], 16;"
                 :: "r"(s), "l"(g) : "memory");
}
static __device__ __forceinline__ void ldm4(uint32_t* r, uint32_t a) {
    asm volatile("ldmatrix.sync.aligned.m8n8.x4.shared.b16 {%0,%1,%2,%3}, [%4];"
        : "=r"(r[0]), "=r"(r[1]), "=r"(r[2]), "=r"(r[3]) : "r"(a));
}
// ---- packed f32x2 ----
static __device__ __forceinline__ ull pk2(float a, float b) {
    ull r; asm("mov.b64 %0, {%1,%2};" : "=l"(r) : "f"(a), "f"(b)); return r;
}
static __device__ __forceinline__ void upk2(ull v, float* a, float* b) {
    asm("mov.b64 {%0,%1}, %2;" : "=f"(*a), "=f"(*b) : "l"(v));
}
static __device__ __forceinline__ ull fma2(ull a, ull b, ull c) {
    ull d; asm("fma.rn.f32x2 %0, %1, %2, %3;" : "=l"(d) : "l"(a), "l"(b), "l"(c));
    return d;
}
static __device__ __forceinline__ ull mul2(ull a, ull b) {
    ull d; asm("mul.rn.f32x2 %0, %1, %2;" : "=l"(d) : "l"(a), "l"(b));
    return d;
}

// =====================================================================
// fused splits: x -> fp16 hi/lo ; qkv_w, proj_w -> single fp16
// =====================================================================
#define N4_X (TOK * DD / 4)
#define N4_WQ (3 * DD * DD / 4)
#define N4_WP (DD * DD / 4)

__global__ __launch_bounds__(256) void split3_kernel(
    const float* __restrict__ sx, __half* __restrict__ xh, __half* __restrict__ xl,
    const float* __restrict__ sq, __half* __restrict__ wq,
    const float* __restrict__ sp, __half* __restrict__ wp)
{
    int i = blockIdx.x * blockDim.x + threadIdx.x;
    if (i < N4_X) {
        float4 v = ((const float4*)sx)[i];
        float f[4] = {v.x, v.y, v.z, v.w};
        float r[4];
#pragma unroll
        for (int j = 0; j < 4; j++) {
            __half h = __float2half_rn(f[j]);
            r[j] = f[j] - __half2float(h);
        }
        uint2 ph, pl;
        ph.x = pack2f16(f[0], f[1]); ph.y = pack2f16(f[2], f[3]);
        pl.x = pack2f16(r[0], r[1]); pl.y = pack2f16(r[2], r[3]);
        ((uint2*)xh)[i] = ph;
        ((uint2*)xl)[i] = pl;
        return;
    }
    i -= N4_X;
    const float* src; __half* dst;
    if (i < N4_WQ) { src = sq; dst = wq; }
    else { i -= N4_WQ; if (i >= N4_WP) return; src = sp; dst = wp; }
    float4 v = ((const float4*)src)[i];
    uint2 ph;
    ph.x = pack2f16(v.x, v.y); ph.y = pack2f16(v.z, v.w);
    ((uint2*)dst)[i] = ph;
}

// =====================================================================
// fp16 two-pass warp-MMA GEMM (NT): C = Ah*B + Al*B (+bias)
// 2-stage cp.async, K-chunk 32, 2 CTAs/SM, CTA 128x128, warp tile 64x32.
// =====================================================================
#define PADK 40
#define TILE_E (128 * PADK)
#define STAGE_B (3u * TILE_E * 2u)     // Ah, Al, B = 30720 B
#define GEMM_SMEM (2u * STAGE_B)       // 61440 B

#define MMA_F16(c, a, b)                                                   \
    asm volatile("mma.sync.aligned.m16n8k16.row.col.f32.f16.f16.f32 "      \
        "{%0,%1,%2,%3}, {%4,%5,%6,%7}, {%8,%9}, {%0,%1,%2,%3};"            \
        : "+f"((c)[0]), "+f"((c)[1]), "+f"((c)[2]), "+f"((c)[3])           \
        : "r"((a)[0]), "r"((a)[1]), "r"((a)[2]), "r"((a)[3]),              \
          "r"((b)[0]), "r"((b)[1]))

__global__ __launch_bounds__(256, 2) void gemm_mma(
    const __half* __restrict__ Ah_, const __half* __restrict__ Al_,
    const __half* __restrict__ Bh_,
    const float* __restrict__ bias, float* __restrict__ C,
    int Nc, int K, int useBias)
{
    extern __shared__ __align__(16) uint16_t smg[];
    const uint32_t sbase = smem_u32(smg);

    const int tid  = threadIdx.x;
    const int wid  = tid >> 5;
    const int lane = tid & 31;
    const int wm   = wid & 1;
    const int wn   = wid >> 1;
    const int bm   = blockIdx.y * 128;
    const int bn   = blockIdx.x * 128;

    const int crow0 = tid >> 2;
    const int ccb   = (tid & 3) << 4;
    uint32_t aoff[4];
#pragma unroll
    for (int mt = 0; mt < 4; mt++) {
        int mrow = wm * 64 + mt * 16 + (lane & 15);
        int ke   = (lane >> 4) << 3;
        aoff[mt] = (uint32_t)((mrow * PADK + ke) * 2);
    }
    uint32_t boff[2];
#pragma unroll
    for (int np = 0; np < 2; np++) {
        int nrow = wn * 32 + np * 16 + ((lane >> 4) << 3) + (lane & 7);
        int ke   = ((lane >> 3) & 1) << 3;
        boff[np] = (uint32_t)((nrow * PADK + ke) * 2);
    }

    float acc[4][4][4];
#pragma unroll
    for (int mt = 0; mt < 4; mt++)
#pragma unroll
        for (int nt = 0; nt < 4; nt++)
#pragma unroll
            for (int r = 0; r < 4; r++) acc[mt][nt][r] = 0.0f;

    const int NCH = K >> 5;

    auto issue = [&](int ch, int st) {
        const int k0 = ch << 5;
        const uint32_t stg = sbase + (uint32_t)st * STAGE_B;
#pragma unroll
        for (int j = 0; j < 2; j++) {
            int row = crow0 + (j << 6);
            uint32_t dst = (uint32_t)(row * PADK * 2) + ccb;
            size_t offA = (size_t)(bm + row) * K + k0 + (ccb >> 1);
            size_t offB = (size_t)(bn + row) * K + k0 + (ccb >> 1);
            cp16(stg + dst,              Ah_ + offA);
            cp16(stg + TILE_E * 2 + dst, Al_ + offA);
            cp16(stg + TILE_E * 4 + dst, Bh_ + offB);
        }
    };

    issue(0, 0);
    asm volatile("cp.async.commit_group;" ::: "memory");

    for (int ch = 0; ch < NCH; ch++) {
        if (ch + 1 < NCH) issue(ch + 1, (ch + 1) & 1);
        asm volatile("cp.async.commit_group;" ::: "memory");
        asm volatile("cp.async.wait_group 1;" ::: "memory");
        __syncthreads();

        const uint32_t stg = sbase + (uint32_t)(ch & 1) * STAGE_B;

#pragma unroll
        for (int ks = 0; ks < 2; ks++) {
            const uint32_t kadd = (uint32_t)(ks << 5);
            uint32_t fah[4][4], fal[4][4], fbh[2][4];
#pragma unroll
            for (int mt = 0; mt < 4; mt++) {
                ldm4(fah[mt], stg + aoff[mt] + kadd);
                ldm4(fal[mt], stg + TILE_E * 2 + aoff[mt] + kadd);
            }
#pragma unroll
            for (int np = 0; np < 2; np++)
                ldm4(fbh[np], stg + TILE_E * 4 + boff[np] + kadd);
#pragma unroll
            for (int mt = 0; mt < 4; mt++)
#pragma unroll
                for (int nt = 0; nt < 4; nt++)
                    MMA_F16(acc[mt][nt], fah[mt], &fbh[nt >> 1][(nt & 1) << 1]);
#pragma unroll
            for (int mt = 0; mt < 4; mt++)
#pragma unroll
                for (int nt = 0; nt < 4; nt++)
                    MMA_F16(acc[mt][nt], fal[mt], &fbh[nt >> 1][(nt & 1) << 1]);
        }
        __syncthreads();
    }

    const int g = lane >> 2;
    const int t = lane & 3;
#pragma unroll
    for (int nt = 0; nt < 4; nt++) {
        int col = bn + wn * 32 + nt * 8 + t * 2;
        float b0v = useBias ? bias[col]     : 0.0f;
        float b1v = useBias ? bias[col + 1] : 0.0f;
#pragma unroll
        for (int mt = 0; mt < 4; mt++) {
            int row = bm + wm * 64 + mt * 16 + g;
            float2 lo2, hi2;
            lo2.x = acc[mt][nt][0] + b0v; lo2.y = acc[mt][nt][1] + b1v;
            hi2.x = acc[mt][nt][2] + b0v; hi2.y = acc[mt][nt][3] + b1v;
            *(float2*)(C + (size_t)row * Nc + col)       = lo2;
            *(float2*)(C + (size_t)(row + 8) * Nc + col) = hi2;
        }
    }
}

// =====================================================================
// Block-mean pooling
// =====================================================================
__global__ __launch_bounds__(64) void pool_kernel()
{
    const int row = blockIdx.x;
    const int d   = threadIdx.x;
    const int m   = row % MM;
    const int b   = row / (MM * HH);
    const int h   = (row / MM) % HH;

    const float* base = g_qkv + ((size_t)(b * NN + m * BSZ) * (3 * DD)) + h * HDD + d;
    float sq = 0.0f, sk = 0.0f;
    for (int i = 0; i < BSZ; i++) {
        sq += base[(size_t)i * 3 * DD];
        sk += base[(size_t)i * 3 * DD + DD];
    }
    g_qb[(size_t)row * HDD + d] = sq * (1.0f / BSZ);
    g_kb[(size_t)row * HDD + d] = sk * (1.0f / BSZ);
}

// =====================================================================
// Block scores + top-2 threshold + diagonal keep
// =====================================================================
__global__ __launch_bounds__(32) void mask_kernel()
{
    const int row  = blockIdx.x;
    const int lane = threadIdx.x;
    const int m    = row % MM;
    const int bh   = row / MM;

    const float* qb = g_qb + (size_t)row * HDD;
    const float* kb = g_kb + ((size_t)bh * MM + lane) * HDD;

    float s = 0.0f;
    for (int d = 0; d < HDD; d++) s = fmaf(qb[d], kb[d], s);
    s *= SCALEF;

    const unsigned FULL = 0xffffffffu;
    float m1 = s;
#pragma unroll
    for (int off = 16; off; off >>= 1) m1 = fmaxf(m1, __shfl_xor_sync(FULL, m1, off));
    unsigned b1 = __ballot_sync(FULL, s == m1);
    int lead = __ffs(b1) - 1;
    float v2 = (lane == lead) ? -INFINITY : s;
    float m2 = v2;
#pragma unroll
    for (int off = 16; off; off >>= 1) m2 = fmaxf(m2, __shfl_xor_sync(FULL, m2, off));

    bool keep = (s >= m2) || (lane == m);
    unsigned km = __ballot_sync(FULL, keep);
    if (lane == 0) g_kcnt[row] = __popc(km);
    if (keep) {
        int pos = __popc(km & ((1u << lane) - 1u));
        g_kept[(size_t)row * MAXK + pos] = lane;
    }
}

// =====================================================================
// Sparse block attention (f32x2 math), fp16 hi/lo epilogue.
// =====================================================================
#define ATT_SMEM (8192u * 4u)

__global__ __launch_bounds__(64) void attn_kernel()
{
    extern __shared__ __align__(16) float asm_f[];

    const int row = blockIdx.x;
    const int t   = threadIdx.x;
    const int m   = row % MM;
    const int h   = (row / MM) % HH;
    const int b   = row / (MM * HH);

    const uint32_t sbase = smem_u32(asm_f);

    const float* qptr = g_qkv + ((size_t)(b * NN + m * BSZ + t) * (3 * DD)) + h * HDD;
    ull q2[32];
#pragma unroll
    for (int i = 0; i < 32; i++) q2[i] = *(const ull*)(qptr + (i << 1));

    ull acc2[32];
#pragma unroll
    for (int i = 0; i < 32; i++) acc2[i] = 0ull;
    float mrun = -INFINITY, lrun = 0.0f;

    const int cnt = g_kcnt[row];
    const int*  kept = g_kept + (size_t)row * MAXK;
    const float* hk  = g_qkv + DD + h * HDD;

    for (int kbi = 0; kbi < cnt; kbi++) {
        if (kbi > 0) __syncthreads();
        const int nblk = kept[kbi];
        const float* kb = hk + (size_t)(b * NN + nblk * BSZ) * (3 * DD);
#pragma unroll
        for (int j = 0; j < 16; j++) {
            int i = t + (j << 6);
            int r = i >> 4, c4 = i & 15;
            uint32_t so = sbase + (uint32_t)((r << 6) + (c4 << 2)) * 4u;
            const float* gk = kb + (size_t)r * 3 * DD + (c4 << 2);
            cp16(so, gk);
            cp16(so + 16384u, gk + DD);
        }
        asm volatile("cp.async.commit_group;" ::: "memory");
        asm volatile("cp.async.wait_group 0;" ::: "memory");
        __syncthreads();

        const ull* K8 = (const ull*)asm_f;
        const ull* V8 = K8 + 2048;

        for (int j0 = 0; j0 < 64; j0 += 8) {
            float sc[8];
#pragma unroll
            for (int jj = 0; jj < 8; jj++) {
                const ull* kr = K8 + ((j0 + jj) << 5);
                ull s01 = 0ull, s23 = 0ull;
#pragma unroll
                for (int p = 0; p < 16; p++) {
                    s01 = fma2(q2[(p << 1)],     kr[(p << 1)],     s01);
                    s23 = fma2(q2[(p << 1) + 1], kr[(p << 1) + 1], s23);
                }
                float c0, c1, c2, c3;
                upk2(s01, &c0, &c1);
                upk2(s23, &c2, &c3);
                sc[jj] = ((c0 + c1) + (c2 + c3)) * SCALEF;
            }
            float cmax = fmaxf(fmaxf(fmaxf(sc[0], sc[1]), fmaxf(sc[2], sc[3])),
                               fmaxf(fmaxf(sc[4], sc[5]), fmaxf(sc[6], sc[7])));
            float mnew = fmaxf(mrun, cmax);
            float esc  = __expf(mrun - mnew);
            float p[8]; float ps = 0.f;
#pragma unroll
            for (int jj = 0; jj < 8; jj++) { p[jj] = __expf(sc[jj] - mnew); ps += p[jj]; }
            lrun = lrun * esc + ps;
            mrun = mnew;

            ull esc2 = pk2(esc, esc);
            ull p2[8];
#pragma unroll
            for (int jj = 0; jj < 8; jj++) p2[jj] = pk2(p[jj], p[jj]);
#pragma unroll
            for (int i = 0; i < 32; i++) {
                ull a = mul2(acc2[i], esc2);
#pragma unroll
                for (int jj = 0; jj < 8; jj++)
                    a = fma2(p2[jj], V8[((j0 + jj) << 5) + i], a);
                acc2[i] = a;
            }
        }
    }

    const float inv = 1.0f / lrun;
    const size_t obase = ((size_t)(b * NN + m * BSZ + t) * DD) + h * HDD;
#pragma unroll
    for (int i = 0; i < 32; i += 2) {
        float f[4], r[4];
        upk2(acc2[i],     &f[0], &f[1]);
        upk2(acc2[i + 1], &f[2], &f[3]);
#pragma unroll
        for (int j = 0; j < 4; j++) {
            f[j] *= inv;
            __half hb = __float2half_rn(f[j]);
            r[j] = f[j] - __half2float(hb);
        }
        uint2 ph, pl;
        ph.x = pack2f16(f[0], f[1]); ph.y = pack2f16(f[2], f[3]);
        pl.x = pack2f16(r[0], r[1]); pl.y = pack2f16(r[2], r[3]);
        *(uint2*)(g_ah + obase + (i << 1)) = ph;
        *(uint2*)(g_al + obase + (i << 1)) = pl;
    }
}

// =====================================================================
// Launch
// =====================================================================
extern "C" void kernel_launch(void* const* d_in, const int* in_sizes, int n_in,
                              void* d_out, int out_size)
{
    const float* x = nullptr; const float* qkv_w = nullptr;
    const float* proj_w = nullptr; const float* proj_b = nullptr;
    for (int i = 0; i < n_in; i++) {
        if      (in_sizes[i] == BB * NN * DD) x      = (const float*)d_in[i];
        else if (in_sizes[i] == 3 * DD * DD)  qkv_w  = (const float*)d_in[i];
        else if (in_sizes[i] == DD * DD)      proj_w = (const float*)d_in[i];
        else if (in_sizes[i] == DD)           proj_b = (const float*)d_in[i];
    }
    float* out = (float*)d_out;

    void* p;
    cudaGetSymbolAddress(&p, g_qkv); float* qkv = (float*)p;
    __half *xh, *xl, *wq, *wp, *ah, *al;
    cudaGetSymbolAddress(&p, g_xh); xh = (__half*)p;
    cudaGetSymbolAddress(&p, g_xl); xl = (__half*)p;
    cudaGetSymbolAddress(&p, g_wq); wq = (__half*)p;
    cudaGetSymbolAddress(&p, g_wp); wp = (__half*)p;
    cudaGetSymbolAddress(&p, g_ah); ah = (__half*)p;
    cudaGetSymbolAddress(&p, g_al); al = (__half*)p;

    static int attr_done = 0;
    if (!attr_done) {
        cudaFuncSetAttribute(gemm_mma, cudaFuncAttributeMaxDynamicSharedMemorySize, GEMM_SMEM);
        cudaFuncSetAttribute(attn_kernel, cudaFuncAttributeMaxDynamicSharedMemorySize, ATT_SMEM);
        attr_done = 1;
    }

    {
        int n4 = N4_X + N4_WQ + N4_WP;
        split3_kernel<<<(n4 + 255) / 256, 256>>>(x, xh, xl, qkv_w, wq, proj_w, wp);
    }
    gemm_mma<<<dim3(3 * DD / 128, TOK / 128), 256, GEMM_SMEM>>>(
        xh, xl, wq, nullptr, qkv, 3 * DD, DD, 0);
    pool_kernel<<<BB * HH * MM, 64>>>();
    mask_kernel<<<BB * HH * MM, 32>>>();
    attn_kernel<<<BB * HH * MM, 64, ATT_SMEM>>>();
    gemm_mma<<<dim3(DD / 128, TOK / 128), 256, GEMM_SMEM>>>(
        ah, al, wp, proj_b, out, DD, DD, 1);
}

// round 10
// speedup vs baseline: 4.0296x; 1.2645x over previous
#include <cuda_runtime.h>
#include <cuda_fp16.h>
#include <math.h>
#include <stdint.h>

// Problem constants
#define BB   2
#define NN   2048
#define DD   1024
#define HH   16
#define HDD  64
#define BSZ  64
#define MM   32
#define MAXK 32
#define SCALEF 0.125f
#define TOK  (BB * NN)

// ---------------- scratch ----------------
__device__ float g_qkv [TOK * 3 * DD];
__device__ float g_qb  [BB * HH * MM * HDD];
__device__ float g_kb  [BB * HH * MM * HDD];
__device__ int   g_kept[BB * HH * MM * MAXK];
__device__ int   g_kcnt[BB * HH * MM];
__device__ __half g_xh [TOK * DD], g_xl [TOK * DD];
__device__ __half g_wq [3 * DD * DD];
__device__ __half g_wp [DD * DD];
__device__ __half g_ah [TOK * DD], g_al [TOK * DD];

// =====================================================================
// helpers
// =====================================================================
static __device__ __forceinline__ uint32_t pack2f16(float a, float b) {
    return (uint32_t)__half_as_ushort(__float2half_rn(a)) |
           ((uint32_t)__half_as_ushort(__float2half_rn(b)) << 16);
}
static __device__ __forceinline__ uint32_t smem_u32(const void* p) {
    uint32_t a;
    asm("{ .reg .u64 t; cvta.to.shared.u64 t, %1; cvt.u32.u64 %0, t; }"
        : "=r"(a) : "l"(p));
    return a;
}
static __device__ __forceinline__ void cp16(uint32_t s, const void* g) {
    asm volatile("cp.async.cg.shared.global [%0], [%1], 16;"
                 :: "r"(s), "l"(g) : "memory");
}
static __device__ __forceinline__ void ldm4(uint32_t* r, uint32_t a) {
    asm volatile("ldmatrix.sync.aligned.m8n8.x4.shared.b16 {%0,%1,%2,%3}, [%4];"
        : "=r"(r[0]), "=r"(r[1]), "=r"(r[2]), "=r"(r[3]) : "r"(a));
}
static __device__ __forceinline__ void ldm4t(uint32_t* r, uint32_t a) {
    asm volatile("ldmatrix.sync.aligned.m8n8.x4.trans.shared.b16 {%0,%1,%2,%3}, [%4];"
        : "=r"(r[0]), "=r"(r[1]), "=r"(r[2]), "=r"(r[3]) : "r"(a));
}

#define MMA_F16(c, a, b)                                                   \
    asm volatile("mma.sync.aligned.m16n8k16.row.col.f32.f16.f16.f32 "      \
        "{%0,%1,%2,%3}, {%4,%5,%6,%7}, {%8,%9}, {%0,%1,%2,%3};"            \
        : "+f"((c)[0]), "+f"((c)[1]), "+f"((c)[2]), "+f"((c)[3])           \
        : "r"((a)[0]), "r"((a)[1]), "r"((a)[2]), "r"((a)[3]),              \
          "r"((b)[0]), "r"((b)[1]))

// =====================================================================
// fused splits: x -> fp16 hi/lo ; qkv_w, proj_w -> single fp16
// =====================================================================
#define N4_X (TOK * DD / 4)
#define N4_WQ (3 * DD * DD / 4)
#define N4_WP (DD * DD / 4)

__global__ __launch_bounds__(256) void split3_kernel(
    const float* __restrict__ sx, __half* __restrict__ xh, __half* __restrict__ xl,
    const float* __restrict__ sq, __half* __restrict__ wq,
    const float* __restrict__ sp, __half* __restrict__ wp)
{
    int i = blockIdx.x * blockDim.x + threadIdx.x;
    if (i < N4_X) {
        float4 v = ((const float4*)sx)[i];
        float f[4] = {v.x, v.y, v.z, v.w};
        float r[4];
#pragma unroll
        for (int j = 0; j < 4; j++) {
            __half h = __float2half_rn(f[j]);
            r[j] = f[j] - __half2float(h);
        }
        uint2 ph, pl;
        ph.x = pack2f16(f[0], f[1]); ph.y = pack2f16(f[2], f[3]);
        pl.x = pack2f16(r[0], r[1]); pl.y = pack2f16(r[2], r[3]);
        ((uint2*)xh)[i] = ph;
        ((uint2*)xl)[i] = pl;
        return;
    }
    i -= N4_X;
    const float* src; __half* dst;
    if (i < N4_WQ) { src = sq; dst = wq; }
    else { i -= N4_WQ; if (i >= N4_WP) return; src = sp; dst = wp; }
    float4 v = ((const float4*)src)[i];
    uint2 ph;
    ph.x = pack2f16(v.x, v.y); ph.y = pack2f16(v.z, v.w);
    ((uint2*)dst)[i] = ph;
}

// =====================================================================
// fp16 two-pass warp-MMA GEMM (NT): C = Ah*B + Al*B (+bias)
// =====================================================================
#define PADK 40
#define TILE_E (128 * PADK)
#define STAGE_B (3u * TILE_E * 2u)
#define GEMM_SMEM (2u * STAGE_B)

__global__ __launch_bounds__(256, 2) void gemm_mma(
    const __half* __restrict__ Ah_, const __half* __restrict__ Al_,
    const __half* __restrict__ Bh_,
    const float* __restrict__ bias, float* __restrict__ C,
    int Nc, int K, int useBias)
{
    extern __shared__ __align__(16) uint16_t smg[];
    const uint32_t sbase = smem_u32(smg);

    const int tid  = threadIdx.x;
    const int wid  = tid >> 5;
    const int lane = tid & 31;
    const int wm   = wid & 1;
    const int wn   = wid >> 1;
    const int bm   = blockIdx.y * 128;
    const int bn   = blockIdx.x * 128;

    const int crow0 = tid >> 2;
    const int ccb   = (tid & 3) << 4;
    uint32_t aoff[4];
#pragma unroll
    for (int mt = 0; mt < 4; mt++) {
        int mrow = wm * 64 + mt * 16 + (lane & 15);
        int ke   = (lane >> 4) << 3;
        aoff[mt] = (uint32_t)((mrow * PADK + ke) * 2);
    }
    uint32_t boff[2];
#pragma unroll
    for (int np = 0; np < 2; np++) {
        int nrow = wn * 32 + np * 16 + ((lane >> 4) << 3) + (lane & 7);
        int ke   = ((lane >> 3) & 1) << 3;
        boff[np] = (uint32_t)((nrow * PADK + ke) * 2);
    }

    float acc[4][4][4];
#pragma unroll
    for (int mt = 0; mt < 4; mt++)
#pragma unroll
        for (int nt = 0; nt < 4; nt++)
#pragma unroll
            for (int r = 0; r < 4; r++) acc[mt][nt][r] = 0.0f;

    const int NCH = K >> 5;

    auto issue = [&](int ch, int st) {
        const int k0 = ch << 5;
        const uint32_t stg = sbase + (uint32_t)st * STAGE_B;
#pragma unroll
        for (int j = 0; j < 2; j++) {
            int row = crow0 + (j << 6);
            uint32_t dst = (uint32_t)(row * PADK * 2) + ccb;
            size_t offA = (size_t)(bm + row) * K + k0 + (ccb >> 1);
            size_t offB = (size_t)(bn + row) * K + k0 + (ccb >> 1);
            cp16(stg + dst,              Ah_ + offA);
            cp16(stg + TILE_E * 2 + dst, Al_ + offA);
            cp16(stg + TILE_E * 4 + dst, Bh_ + offB);
        }
    };

    issue(0, 0);
    asm volatile("cp.async.commit_group;" ::: "memory");

    for (int ch = 0; ch < NCH; ch++) {
        if (ch + 1 < NCH) issue(ch + 1, (ch + 1) & 1);
        asm volatile("cp.async.commit_group;" ::: "memory");
        asm volatile("cp.async.wait_group 1;" ::: "memory");
        __syncthreads();

        const uint32_t stg = sbase + (uint32_t)(ch & 1) * STAGE_B;

#pragma unroll
        for (int ks = 0; ks < 2; ks++) {
            const uint32_t kadd = (uint32_t)(ks << 5);
            uint32_t fah[4][4], fal[4][4], fbh[2][4];
#pragma unroll
            for (int mt = 0; mt < 4; mt++) {
                ldm4(fah[mt], stg + aoff[mt] + kadd);
                ldm4(fal[mt], stg + TILE_E * 2 + aoff[mt] + kadd);
            }
#pragma unroll
            for (int np = 0; np < 2; np++)
                ldm4(fbh[np], stg + TILE_E * 4 + boff[np] + kadd);
#pragma unroll
            for (int mt = 0; mt < 4; mt++)
#pragma unroll
                for (int nt = 0; nt < 4; nt++)
                    MMA_F16(acc[mt][nt], fah[mt], &fbh[nt >> 1][(nt & 1) << 1]);
#pragma unroll
            for (int mt = 0; mt < 4; mt++)
#pragma unroll
                for (int nt = 0; nt < 4; nt++)
                    MMA_F16(acc[mt][nt], fal[mt], &fbh[nt >> 1][(nt & 1) << 1]);
        }
        __syncthreads();
    }

    const int g = lane >> 2;
    const int t = lane & 3;
#pragma unroll
    for (int nt = 0; nt < 4; nt++) {
        int col = bn + wn * 32 + nt * 8 + t * 2;
        float b0v = useBias ? bias[col]     : 0.0f;
        float b1v = useBias ? bias[col + 1] : 0.0f;
#pragma unroll
        for (int mt = 0; mt < 4; mt++) {
            int row = bm + wm * 64 + mt * 16 + g;
            float2 lo2, hi2;
            lo2.x = acc[mt][nt][0] + b0v; lo2.y = acc[mt][nt][1] + b1v;
            hi2.x = acc[mt][nt][2] + b0v; hi2.y = acc[mt][nt][3] + b1v;
            *(float2*)(C + (size_t)row * Nc + col)       = lo2;
            *(float2*)(C + (size_t)(row + 8) * Nc + col) = hi2;
        }
    }
}

// =====================================================================
// Block-mean pooling
// =====================================================================
__global__ __launch_bounds__(64) void pool_kernel()
{
    const int row = blockIdx.x;
    const int d   = threadIdx.x;
    const int m   = row % MM;
    const int b   = row / (MM * HH);
    const int h   = (row / MM) % HH;

    const float* base = g_qkv + ((size_t)(b * NN + m * BSZ) * (3 * DD)) + h * HDD + d;
    float sq = 0.0f, sk = 0.0f;
    for (int i = 0; i < BSZ; i++) {
        sq += base[(size_t)i * 3 * DD];
        sk += base[(size_t)i * 3 * DD + DD];
    }
    g_qb[(size_t)row * HDD + d] = sq * (1.0f / BSZ);
    g_kb[(size_t)row * HDD + d] = sk * (1.0f / BSZ);
}

// =====================================================================
// Block scores + top-2 threshold + diagonal keep
// =====================================================================
__global__ __launch_bounds__(32) void mask_kernel()
{
    const int row  = blockIdx.x;
    const int lane = threadIdx.x;
    const int m    = row % MM;
    const int bh   = row / MM;

    const float* qb = g_qb + (size_t)row * HDD;
    const float* kb = g_kb + ((size_t)bh * MM + lane) * HDD;

    float s = 0.0f;
    for (int d = 0; d < HDD; d++) s = fmaf(qb[d], kb[d], s);
    s *= SCALEF;

    const unsigned FULL = 0xffffffffu;
    float m1 = s;
#pragma unroll
    for (int off = 16; off; off >>= 1) m1 = fmaxf(m1, __shfl_xor_sync(FULL, m1, off));
    unsigned b1 = __ballot_sync(FULL, s == m1);
    int lead = __ffs(b1) - 1;
    float v2 = (lane == lead) ? -INFINITY : s;
    float m2 = v2;
#pragma unroll
    for (int off = 16; off; off >>= 1) m2 = fmaxf(m2, __shfl_xor_sync(FULL, m2, off));

    bool keep = (s >= m2) || (lane == m);
    unsigned km = __ballot_sync(FULL, keep);
    if (lane == 0) g_kcnt[row] = __popc(km);
    if (keep) {
        int pos = __popc(km & ((1u << lane) - 1u));
        g_kept[(size_t)row * MAXK + pos] = lane;
    }
}

// =====================================================================
// Sparse block attention on tensor cores (flash-v2 fragment scheme).
// 128 threads; warp w owns query rows [w*16, w*16+16).
// S = Qh*Kh + Qh*Kl + Ql*Kh (Q pre-scaled by 0.125 — exact).
// O = Ph*Vf + Pl*Vf (P split exact, V single fp16).
// =====================================================================
#define APAD 72
#define TQH 0
#define TQL (64 * APAD)
#define TKH (2 * 64 * APAD)
#define TKL (3 * 64 * APAD)
#define TVF (4 * 64 * APAD)

__global__ __launch_bounds__(128) void attn_kernel()
{
    __shared__ __align__(16) __half sm[5 * 64 * APAD];
    const uint32_t sb = smem_u32(sm);

    const int tid  = threadIdx.x;
    const int wid  = tid >> 5;
    const int lane = tid & 31;
    const int row  = blockIdx.x;
    const int m    = row % MM;
    const int h    = (row / MM) % HH;
    const int b    = row / (MM * HH);

    const float* qbase = g_qkv + ((size_t)(b * NN + m * BSZ) * (3 * DD)) + h * HDD;

    // ---- load Q (pre-scaled), split fp16 hi/lo into smem ----
#pragma unroll
    for (int j = 0; j < 8; j++) {
        int i = tid + (j << 7);
        int r = i >> 4, c4 = (i & 15) << 2;
        float4 v = *(const float4*)(qbase + (size_t)r * (3 * DD) + c4);
        float f[4] = {v.x * SCALEF, v.y * SCALEF, v.z * SCALEF, v.w * SCALEF};
        float rr[4];
#pragma unroll
        for (int jj = 0; jj < 4; jj++) {
            __half hh = __float2half_rn(f[jj]);
            rr[jj] = f[jj] - __half2float(hh);
        }
        uint2 ph, pl;
        ph.x = pack2f16(f[0], f[1]);  ph.y = pack2f16(f[2], f[3]);
        pl.x = pack2f16(rr[0], rr[1]); pl.y = pack2f16(rr[2], rr[3]);
        *(uint2*)(sm + TQH + r * APAD + c4) = ph;
        *(uint2*)(sm + TQL + r * APAD + c4) = pl;
    }
    __syncthreads();

    // ---- Q fragments (held in regs for the whole kernel) ----
    uint32_t qh_a[4][4], ql_a[4][4];
    {
        int mrow = wid * 16 + (lane & 15);
        uint32_t ab = sb + (uint32_t)((mrow * APAD + ((lane >> 4) << 3)) << 1);
#pragma unroll
        for (int ks = 0; ks < 4; ks++) {
            ldm4(qh_a[ks], ab + (uint32_t)(TQH * 2) + ks * 32);
            ldm4(ql_a[ks], ab + (uint32_t)(TQL * 2) + ks * 32);
        }
    }

    // ldmatrix offsets for K (b-frag) and V (trans b-frag)
    uint32_t kboff[4], voff[4];
#pragma unroll
    for (int np = 0; np < 4; np++) {
        int nrow = np * 16 + ((lane >> 4) << 3) + (lane & 7);
        int ke   = ((lane >> 3) & 1) << 3;
        kboff[np] = (uint32_t)((nrow * APAD + ke) << 1);
    }
#pragma unroll
    for (int dp = 0; dp < 4; dp++) {
        int vrow = (((lane >> 3) & 1) << 3) + (lane & 7);
        int vcol = dp * 16 + ((lane >> 4) << 3);
        voff[dp] = (uint32_t)((vrow * APAD + vcol) << 1);
    }

    float c_o[8][4];
#pragma unroll
    for (int dt = 0; dt < 8; dt++)
#pragma unroll
        for (int r = 0; r < 4; r++) c_o[dt][r] = 0.0f;
    float mrun0 = -INFINITY, mrun1 = -INFINITY, lrun0 = 0.0f, lrun1 = 0.0f;

    const int cnt = g_kcnt[row];
    const int* kept = g_kept + (size_t)row * MAXK;

    for (int kbi = 0; kbi < cnt; kbi++) {
        __syncthreads();   // previous tile's fragment reads complete
        const int nblk = kept[kbi];
        const float* kbase = g_qkv + ((size_t)(b * NN + nblk * BSZ) * (3 * DD))
                             + DD + h * HDD;
        // load K (split hi/lo) and V (single fp16)
#pragma unroll
        for (int j = 0; j < 8; j++) {
            int i = tid + (j << 7);
            int r = i >> 4, c4 = (i & 15) << 2;
            float4 kv = *(const float4*)(kbase + (size_t)r * (3 * DD) + c4);
            float f[4] = {kv.x, kv.y, kv.z, kv.w};
            float rr[4];
#pragma unroll
            for (int jj = 0; jj < 4; jj++) {
                __half hh = __float2half_rn(f[jj]);
                rr[jj] = f[jj] - __half2float(hh);
            }
            uint2 ph, pl;
            ph.x = pack2f16(f[0], f[1]);  ph.y = pack2f16(f[2], f[3]);
            pl.x = pack2f16(rr[0], rr[1]); pl.y = pack2f16(rr[2], rr[3]);
            *(uint2*)(sm + TKH + r * APAD + c4) = ph;
            *(uint2*)(sm + TKL + r * APAD + c4) = pl;
            float4 vv = *(const float4*)(kbase + DD + (size_t)r * (3 * DD) + c4);
            uint2 pv;
            pv.x = pack2f16(vv.x, vv.y); pv.y = pack2f16(vv.z, vv.w);
            *(uint2*)(sm + TVF + r * APAD + c4) = pv;
        }
        __syncthreads();

        // ---- S = Q K^T (3 passes) ----
        float c_s[8][4];
#pragma unroll
        for (int nt = 0; nt < 8; nt++)
#pragma unroll
            for (int r = 0; r < 4; r++) c_s[nt][r] = 0.0f;
#pragma unroll
        for (int ks = 0; ks < 4; ks++) {
            uint32_t kh[4][4], kl[4][4];
#pragma unroll
            for (int np = 0; np < 4; np++) {
                ldm4(kh[np], sb + (uint32_t)(TKH * 2) + kboff[np] + ks * 32);
                ldm4(kl[np], sb + (uint32_t)(TKL * 2) + kboff[np] + ks * 32);
            }
#pragma unroll
            for (int nt = 0; nt < 8; nt++)
                MMA_F16(c_s[nt], qh_a[ks], &kh[nt >> 1][(nt & 1) << 1]);
#pragma unroll
            for (int nt = 0; nt < 8; nt++)
                MMA_F16(c_s[nt], qh_a[ks], &kl[nt >> 1][(nt & 1) << 1]);
#pragma unroll
            for (int nt = 0; nt < 8; nt++)
                MMA_F16(c_s[nt], ql_a[ks], &kh[nt >> 1][(nt & 1) << 1]);
        }

        // ---- online softmax on fragments ----
        const unsigned FULL = 0xffffffffu;
        float rmax0 = -INFINITY, rmax1 = -INFINITY;
#pragma unroll
        for (int nt = 0; nt < 8; nt++) {
            rmax0 = fmaxf(rmax0, fmaxf(c_s[nt][0], c_s[nt][1]));
            rmax1 = fmaxf(rmax1, fmaxf(c_s[nt][2], c_s[nt][3]));
        }
        rmax0 = fmaxf(rmax0, __shfl_xor_sync(FULL, rmax0, 1));
        rmax0 = fmaxf(rmax0, __shfl_xor_sync(FULL, rmax0, 2));
        rmax1 = fmaxf(rmax1, __shfl_xor_sync(FULL, rmax1, 1));
        rmax1 = fmaxf(rmax1, __shfl_xor_sync(FULL, rmax1, 2));

        float mn0 = fmaxf(mrun0, rmax0), mn1 = fmaxf(mrun1, rmax1);
        float e0 = __expf(mrun0 - mn0),  e1 = __expf(mrun1 - mn1);
        float rs0 = 0.0f, rs1 = 0.0f;
#pragma unroll
        for (int nt = 0; nt < 8; nt++) {
            c_s[nt][0] = __expf(c_s[nt][0] - mn0); rs0 += c_s[nt][0];
            c_s[nt][1] = __expf(c_s[nt][1] - mn0); rs0 += c_s[nt][1];
            c_s[nt][2] = __expf(c_s[nt][2] - mn1); rs1 += c_s[nt][2];
            c_s[nt][3] = __expf(c_s[nt][3] - mn1); rs1 += c_s[nt][3];
        }
        rs0 += __shfl_xor_sync(FULL, rs0, 1); rs0 += __shfl_xor_sync(FULL, rs0, 2);
        rs1 += __shfl_xor_sync(FULL, rs1, 1); rs1 += __shfl_xor_sync(FULL, rs1, 2);
        lrun0 = lrun0 * e0 + rs0;  lrun1 = lrun1 * e1 + rs1;
        mrun0 = mn0;               mrun1 = mn1;
#pragma unroll
        for (int dt = 0; dt < 8; dt++) {
            c_o[dt][0] *= e0; c_o[dt][1] *= e0;
            c_o[dt][2] *= e1; c_o[dt][3] *= e1;
        }

        // ---- O += P V (P split hi/lo, 2 passes) ----
#pragma unroll
        for (int ks = 0; ks < 4; ks++) {
            // P fragments for key columns [ks*16, ks*16+16)
            uint32_t pha[4], pla[4];
#pragma unroll
            for (int half = 0; half < 2; half++) {
                const float* cs = c_s[2 * ks + half];
                float x0 = cs[0], x1 = cs[1], x2 = cs[2], x3 = cs[3];
                __half h0 = __float2half_rn(x0), h1 = __float2half_rn(x1);
                __half h2 = __float2half_rn(x2), h3 = __float2half_rn(x3);
                pha[2 * half]     = (uint32_t)__half_as_ushort(h0) |
                                    ((uint32_t)__half_as_ushort(h1) << 16);
                pha[2 * half + 1] = (uint32_t)__half_as_ushort(h2) |
                                    ((uint32_t)__half_as_ushort(h3) << 16);
                pla[2 * half]     = pack2f16(x0 - __half2float(h0),
                                             x1 - __half2float(h1));
                pla[2 * half + 1] = pack2f16(x2 - __half2float(h2),
                                             x3 - __half2float(h3));
            }
            // NOTE: A-frag order is {a0=(row g,k lo), a1=(row g+8,k lo),
            //        a2=(row g,k hi), a3=(row g+8,k hi)}
            uint32_t pA[4] = {pha[0], pha[1], pha[2], pha[3]};
            uint32_t pL[4] = {pla[0], pla[1], pla[2], pla[3]};

            uint32_t vf[4][4];
#pragma unroll
            for (int dp = 0; dp < 4; dp++)
                ldm4t(vf[dp], sb + (uint32_t)(TVF * 2) + voff[dp]
                              + (uint32_t)(ks * 16 * APAD * 2));
#pragma unroll
            for (int dt = 0; dt < 8; dt++)
                MMA_F16(c_o[dt], pA, &vf[dt >> 1][(dt & 1) << 1]);
#pragma unroll
            for (int dt = 0; dt < 8; dt++)
                MMA_F16(c_o[dt], pL, &vf[dt >> 1][(dt & 1) << 1]);
        }
    }

    // ---- epilogue: normalize, split fp16 hi/lo, store ----
    const float inv0 = 1.0f / lrun0, inv1 = 1.0f / lrun1;
    const int g = lane >> 2, t = lane & 3;
    const int tok0 = b * NN + m * BSZ + wid * 16 + g;
    const size_t o0 = (size_t)tok0 * DD + h * HDD;
    const size_t o1 = o0 + (size_t)8 * DD;
#pragma unroll
    for (int dt = 0; dt < 8; dt++) {
        int col = dt * 8 + t * 2;
        float f0 = c_o[dt][0] * inv0, f1 = c_o[dt][1] * inv0;
        float f2 = c_o[dt][2] * inv1, f3 = c_o[dt][3] * inv1;
        __half h0 = __float2half_rn(f0), h1 = __float2half_rn(f1);
        __half h2 = __float2half_rn(f2), h3 = __float2half_rn(f3);
        *(uint32_t*)(g_ah + o0 + col) =
            (uint32_t)__half_as_ushort(h0) | ((uint32_t)__half_as_ushort(h1) << 16);
        *(uint32_t*)(g_ah + o1 + col) =
            (uint32_t)__half_as_ushort(h2) | ((uint32_t)__half_as_ushort(h3) << 16);
        *(uint32_t*)(g_al + o0 + col) =
            pack2f16(f0 - __half2float(h0), f1 - __half2float(h1));
        *(uint32_t*)(g_al + o1 + col) =
            pack2f16(f2 - __half2float(h2), f3 - __half2float(h3));
    }
}

// =====================================================================
// Launch
// =====================================================================
extern "C" void kernel_launch(void* const* d_in, const int* in_sizes, int n_in,
                              void* d_out, int out_size)
{
    const float* x = nullptr; const float* qkv_w = nullptr;
    const float* proj_w = nullptr; const float* proj_b = nullptr;
    for (int i = 0; i < n_in; i++) {
        if      (in_sizes[i] == BB * NN * DD) x      = (const float*)d_in[i];
        else if (in_sizes[i] == 3 * DD * DD)  qkv_w  = (const float*)d_in[i];
        else if (in_sizes[i] == DD * DD)      proj_w = (const float*)d_in[i];
        else if (in_sizes[i] == DD)           proj_b = (const float*)d_in[i];
    }
    float* out = (float*)d_out;

    void* p;
    cudaGetSymbolAddress(&p, g_qkv); float* qkv = (float*)p;
    __half *xh, *xl, *wq, *wp, *ah, *al;
    cudaGetSymbolAddress(&p, g_xh); xh = (__half*)p;
    cudaGetSymbolAddress(&p, g_xl); xl = (__half*)p;
    cudaGetSymbolAddress(&p, g_wq); wq = (__half*)p;
    cudaGetSymbolAddress(&p, g_wp); wp = (__half*)p;
    cudaGetSymbolAddress(&p, g_ah); ah = (__half*)p;
    cudaGetSymbolAddress(&p, g_al); al = (__half*)p;

    static int attr_done = 0;
    if (!attr_done) {
        cudaFuncSetAttribute(gemm_mma, cudaFuncAttributeMaxDynamicSharedMemorySize, GEMM_SMEM);
        attr_done = 1;
    }

    {
        int n4 = N4_X + N4_WQ + N4_WP;
        split3_kernel<<<(n4 + 255) / 256, 256>>>(x, xh, xl, qkv_w, wq, proj_w, wp);
    }
    gemm_mma<<<dim3(3 * DD / 128, TOK / 128), 256, GEMM_SMEM>>>(
        xh, xl, wq, nullptr, qkv, 3 * DD, DD, 0);
    pool_kernel<<<BB * HH * MM, 64>>>();
    mask_kernel<<<BB * HH * MM, 32>>>();
    attn_kernel<<<BB * HH * MM, 128>>>();
    gemm_mma<<<dim3(DD / 128, TOK / 128), 256, GEMM_SMEM>>>(
        ah, al, wp, proj_b, out, DD, DD, 1);
}

// round 11
// speedup vs baseline: 6.6879x; 1.6597x over previous
#include <cuda_runtime.h>
#include <cuda_fp16.h>
#include <math.h>
#include <stdint.h>

// Problem constants
#define BB   2
#define NN   2048
#define DD   1024
#define HH   16
#define HDD  64
#define BSZ  64
#define MM   32
#define MAXK 32
#define SCALEF 0.125f
#define TOK  (BB * NN)

// ---------------- scratch ----------------
__device__ float g_qkv [TOK * 3 * DD];
__device__ float g_qb  [BB * HH * MM * HDD];
__device__ float g_kb  [BB * HH * MM * HDD];
__device__ int   g_kept[BB * HH * MM * MAXK];
__device__ int   g_kcnt[BB * HH * MM];
__device__ __half g_xh [TOK * DD];            // activations single fp16
__device__ __half g_wq [3 * DD * DD];         // weights single fp16
__device__ __half g_wp [DD * DD];
__device__ __half g_ah [TOK * DD];            // attn out single fp16

// =====================================================================
// helpers
// =====================================================================
static __device__ __forceinline__ uint32_t pack2f16(float a, float b) {
    return (uint32_t)__half_as_ushort(__float2half_rn(a)) |
           ((uint32_t)__half_as_ushort(__float2half_rn(b)) << 16);
}
static __device__ __forceinline__ uint32_t smem_u32(const void* p) {
    uint32_t a;
    asm("{ .reg .u64 t; cvta.to.shared.u64 t, %1; cvt.u32.u64 %0, t; }"
        : "=r"(a) : "l"(p));
    return a;
}
static __device__ __forceinline__ void cp16(uint32_t s, const void* g) {
    asm volatile("cp.async.cg.shared.global [%0], [%1], 16;"
                 :: "r"(s), "l"(g) : "memory");
}
static __device__ __forceinline__ void ldm4(uint32_t* r, uint32_t a) {
    asm volatile("ldmatrix.sync.aligned.m8n8.x4.shared.b16 {%0,%1,%2,%3}, [%4];"
        : "=r"(r[0]), "=r"(r[1]), "=r"(r[2]), "=r"(r[3]) : "r"(a));
}
static __device__ __forceinline__ void ldm4t(uint32_t* r, uint32_t a) {
    asm volatile("ldmatrix.sync.aligned.m8n8.x4.trans.shared.b16 {%0,%1,%2,%3}, [%4];"
        : "=r"(r[0]), "=r"(r[1]), "=r"(r[2]), "=r"(r[3]) : "r"(a));
}

#define MMA_F16(c, a, b)                                                   \
    asm volatile("mma.sync.aligned.m16n8k16.row.col.f32.f16.f16.f32 "      \
        "{%0,%1,%2,%3}, {%4,%5,%6,%7}, {%8,%9}, {%0,%1,%2,%3};"            \
        : "+f"((c)[0]), "+f"((c)[1]), "+f"((c)[2]), "+f"((c)[3])           \
        : "r"((a)[0]), "r"((a)[1]), "r"((a)[2]), "r"((a)[3]),              \
          "r"((b)[0]), "r"((b)[1]))

// =====================================================================
// fused fp32 -> fp16 convert for x, qkv_w, proj_w
// =====================================================================
#define N4_X (TOK * DD / 4)
#define N4_WQ (3 * DD * DD / 4)
#define N4_WP (DD * DD / 4)

__global__ __launch_bounds__(256) void split3_kernel(
    const float* __restrict__ sx, __half* __restrict__ xh,
    const float* __restrict__ sq, __half* __restrict__ wq,
    const float* __restrict__ sp, __half* __restrict__ wp)
{
    int i = blockIdx.x * blockDim.x + threadIdx.x;
    const float* src; __half* dst;
    if (i < N4_X) { src = sx; dst = xh; }
    else if (i < N4_X + N4_WQ) { i -= N4_X; src = sq; dst = wq; }
    else { i -= N4_X + N4_WQ; if (i >= N4_WP) return; src = sp; dst = wp; }
    float4 v = ((const float4*)src)[i];
    uint2 ph;
    ph.x = pack2f16(v.x, v.y); ph.y = pack2f16(v.z, v.w);
    ((uint2*)dst)[i] = ph;
}

// =====================================================================
// fp16 single-pass warp-MMA GEMM (NT): C = A*B (+bias)
// 2-stage cp.async, K-chunk 64, 2 CTAs/SM, CTA 128x128, warp tile 64x32.
// =====================================================================
#define PADK 72
#define TILE_E (128 * PADK)                 // uint16 per tile
#define STAGE_B (2u * TILE_E * 2u)          // A + B tiles = 36864 B
#define GEMM_SMEM (2u * STAGE_B)            // 73728 B

__global__ __launch_bounds__(256, 2) void gemm_mma(
    const __half* __restrict__ Ah_, const __half* __restrict__ Bh_,
    const float* __restrict__ bias, float* __restrict__ C,
    int Nc, int K, int useBias)
{
    extern __shared__ __align__(16) uint16_t smg[];
    const uint32_t sbase = smem_u32(smg);

    const int tid  = threadIdx.x;
    const int wid  = tid >> 5;
    const int lane = tid & 31;
    const int wm   = wid & 1;
    const int wn   = wid >> 1;
    const int bm   = blockIdx.y * 128;
    const int bn   = blockIdx.x * 128;

    // cp.async coords: chunk row = 64 fp16... no: 64 fp32-K? CHK=64 elems
    // per row = 128 B = 8 x 16B pieces; lin = tid + 256*j (j<4)
    int crow[4]; uint32_t cdst[4]; int ccol[4];
#pragma unroll
    for (int j = 0; j < 4; j++) {
        int lin = tid + (j << 8);
        crow[j] = lin >> 3;
        ccol[j] = (lin & 7) << 3;
        cdst[j] = (uint32_t)(crow[j] * PADK * 2 + (lin & 7) * 16);
    }

    uint32_t aoff[4];
#pragma unroll
    for (int mt = 0; mt < 4; mt++) {
        int mrow = wm * 64 + mt * 16 + (lane & 15);
        int ke   = (lane >> 4) << 3;
        aoff[mt] = (uint32_t)((mrow * PADK + ke) * 2);
    }
    uint32_t boff[2];
#pragma unroll
    for (int np = 0; np < 2; np++) {
        int nrow = wn * 32 + np * 16 + ((lane >> 4) << 3) + (lane & 7);
        int ke   = ((lane >> 3) & 1) << 3;
        boff[np] = (uint32_t)((nrow * PADK + ke) * 2);
    }

    float acc[4][4][4];
#pragma unroll
    for (int mt = 0; mt < 4; mt++)
#pragma unroll
        for (int nt = 0; nt < 4; nt++)
#pragma unroll
            for (int r = 0; r < 4; r++) acc[mt][nt][r] = 0.0f;

    const int NCH = K >> 6;                 // 16 chunks for K=1024

    auto issue = [&](int ch, int st) {
        const int k0 = ch << 6;
        const uint32_t stg = sbase + (uint32_t)st * STAGE_B;
#pragma unroll
        for (int j = 0; j < 4; j++) {
            size_t offA = (size_t)(bm + crow[j]) * K + k0 + ccol[j];
            size_t offB = (size_t)(bn + crow[j]) * K + k0 + ccol[j];
            cp16(stg + cdst[j],              Ah_ + offA);
            cp16(stg + TILE_E * 2 + cdst[j], Bh_ + offB);
        }
    };

    issue(0, 0);
    asm volatile("cp.async.commit_group;" ::: "memory");

    for (int ch = 0; ch < NCH; ch++) {
        if (ch + 1 < NCH) issue(ch + 1, (ch + 1) & 1);
        asm volatile("cp.async.commit_group;" ::: "memory");
        asm volatile("cp.async.wait_group 1;" ::: "memory");
        __syncthreads();

        const uint32_t stg = sbase + (uint32_t)(ch & 1) * STAGE_B;

#pragma unroll
        for (int ks = 0; ks < 4; ks++) {
            const uint32_t kadd = (uint32_t)(ks << 5);
            uint32_t fah[4][4], fbh[2][4];
#pragma unroll
            for (int mt = 0; mt < 4; mt++)
                ldm4(fah[mt], stg + aoff[mt] + kadd);
#pragma unroll
            for (int np = 0; np < 2; np++)
                ldm4(fbh[np], stg + TILE_E * 2 + boff[np] + kadd);
#pragma unroll
            for (int mt = 0; mt < 4; mt++)
#pragma unroll
                for (int nt = 0; nt < 4; nt++)
                    MMA_F16(acc[mt][nt], fah[mt], &fbh[nt >> 1][(nt & 1) << 1]);
        }
        __syncthreads();
    }

    const int g = lane >> 2;
    const int t = lane & 3;
#pragma unroll
    for (int nt = 0; nt < 4; nt++) {
        int col = bn + wn * 32 + nt * 8 + t * 2;
        float b0v = useBias ? bias[col]     : 0.0f;
        float b1v = useBias ? bias[col + 1] : 0.0f;
#pragma unroll
        for (int mt = 0; mt < 4; mt++) {
            int row = bm + wm * 64 + mt * 16 + g;
            float2 lo2, hi2;
            lo2.x = acc[mt][nt][0] + b0v; lo2.y = acc[mt][nt][1] + b1v;
            hi2.x = acc[mt][nt][2] + b0v; hi2.y = acc[mt][nt][3] + b1v;
            *(float2*)(C + (size_t)row * Nc + col)       = lo2;
            *(float2*)(C + (size_t)(row + 8) * Nc + col) = hi2;
        }
    }
}

// =====================================================================
// Block-mean pooling
// =====================================================================
__global__ __launch_bounds__(64) void pool_kernel()
{
    const int row = blockIdx.x;
    const int d   = threadIdx.x;
    const int m   = row % MM;
    const int b   = row / (MM * HH);
    const int h   = (row / MM) % HH;

    const float* base = g_qkv + ((size_t)(b * NN + m * BSZ) * (3 * DD)) + h * HDD + d;
    float sq = 0.0f, sk = 0.0f;
    for (int i = 0; i < BSZ; i++) {
        sq += base[(size_t)i * 3 * DD];
        sk += base[(size_t)i * 3 * DD + DD];
    }
    g_qb[(size_t)row * HDD + d] = sq * (1.0f / BSZ);
    g_kb[(size_t)row * HDD + d] = sk * (1.0f / BSZ);
}

// =====================================================================
// Block scores + top-2 threshold + diagonal keep (8 warps/block)
// =====================================================================
__global__ __launch_bounds__(256) void mask_kernel()
{
    const int lane = threadIdx.x & 31;
    const int row  = blockIdx.x * 8 + (threadIdx.x >> 5);
    const int m    = row % MM;
    const int bh   = row / MM;

    const float* qb = g_qb + (size_t)row * HDD;
    const float* kb = g_kb + ((size_t)bh * MM + lane) * HDD;

    float s = 0.0f;
#pragma unroll
    for (int d4 = 0; d4 < 16; d4++) {
        float4 qv = *(const float4*)(qb + (d4 << 2));
        float4 kv = *(const float4*)(kb + (d4 << 2));
        s = fmaf(qv.x, kv.x, s); s = fmaf(qv.y, kv.y, s);
        s = fmaf(qv.z, kv.z, s); s = fmaf(qv.w, kv.w, s);
    }
    s *= SCALEF;

    const unsigned FULL = 0xffffffffu;
    float m1 = s;
#pragma unroll
    for (int off = 16; off; off >>= 1) m1 = fmaxf(m1, __shfl_xor_sync(FULL, m1, off));
    unsigned b1 = __ballot_sync(FULL, s == m1);
    int lead = __ffs(b1) - 1;
    float v2 = (lane == lead) ? -INFINITY : s;
    float m2 = v2;
#pragma unroll
    for (int off = 16; off; off >>= 1) m2 = fmaxf(m2, __shfl_xor_sync(FULL, m2, off));

    bool keep = (s >= m2) || (lane == m);
    unsigned km = __ballot_sync(FULL, keep);
    if (lane == 0) g_kcnt[row] = __popc(km);
    if (keep) {
        int pos = __popc(km & ((1u << lane) - 1u));
        g_kept[(size_t)row * MAXK + pos] = lane;
    }
}

// =====================================================================
// Sparse block attention on tensor cores (flash-v2 fragment scheme).
// S = Qh*Kh + Qh*Kl + Ql*Kh (Q pre-scaled); O = Ph*V + Pl*V.
// Epilogue: single fp16 write (proj input).
// =====================================================================
#define APAD 72
#define TQH 0
#define TQL (64 * APAD)
#define TKH (2 * 64 * APAD)
#define TKL (3 * 64 * APAD)
#define TVF (4 * 64 * APAD)

__global__ __launch_bounds__(128) void attn_kernel()
{
    __shared__ __align__(16) __half sm[5 * 64 * APAD];
    const uint32_t sb = smem_u32(sm);

    const int tid  = threadIdx.x;
    const int wid  = tid >> 5;
    const int lane = tid & 31;
    const int row  = blockIdx.x;
    const int m    = row % MM;
    const int h    = (row / MM) % HH;
    const int b    = row / (MM * HH);

    const float* qbase = g_qkv + ((size_t)(b * NN + m * BSZ) * (3 * DD)) + h * HDD;

#pragma unroll
    for (int j = 0; j < 8; j++) {
        int i = tid + (j << 7);
        int r = i >> 4, c4 = (i & 15) << 2;
        float4 v = *(const float4*)(qbase + (size_t)r * (3 * DD) + c4);
        float f[4] = {v.x * SCALEF, v.y * SCALEF, v.z * SCALEF, v.w * SCALEF};
        float rr[4];
#pragma unroll
        for (int jj = 0; jj < 4; jj++) {
            __half hh = __float2half_rn(f[jj]);
            rr[jj] = f[jj] - __half2float(hh);
        }
        uint2 ph, pl;
        ph.x = pack2f16(f[0], f[1]);  ph.y = pack2f16(f[2], f[3]);
        pl.x = pack2f16(rr[0], rr[1]); pl.y = pack2f16(rr[2], rr[3]);
        *(uint2*)(sm + TQH + r * APAD + c4) = ph;
        *(uint2*)(sm + TQL + r * APAD + c4) = pl;
    }
    __syncthreads();

    uint32_t qh_a[4][4], ql_a[4][4];
    {
        int mrow = wid * 16 + (lane & 15);
        uint32_t ab = sb + (uint32_t)((mrow * APAD + ((lane >> 4) << 3)) << 1);
#pragma unroll
        for (int ks = 0; ks < 4; ks++) {
            ldm4(qh_a[ks], ab + (uint32_t)(TQH * 2) + ks * 32);
            ldm4(ql_a[ks], ab + (uint32_t)(TQL * 2) + ks * 32);
        }
    }

    uint32_t kboff[4], voff[4];
#pragma unroll
    for (int np = 0; np < 4; np++) {
        int nrow = np * 16 + ((lane >> 4) << 3) + (lane & 7);
        int ke   = ((lane >> 3) & 1) << 3;
        kboff[np] = (uint32_t)((nrow * APAD + ke) << 1);
    }
#pragma unroll
    for (int dp = 0; dp < 4; dp++) {
        int vrow = (((lane >> 3) & 1) << 3) + (lane & 7);
        int vcol = dp * 16 + ((lane >> 4) << 3);
        voff[dp] = (uint32_t)((vrow * APAD + vcol) << 1);
    }

    float c_o[8][4];
#pragma unroll
    for (int dt = 0; dt < 8; dt++)
#pragma unroll
        for (int r = 0; r < 4; r++) c_o[dt][r] = 0.0f;
    float mrun0 = -INFINITY, mrun1 = -INFINITY, lrun0 = 0.0f, lrun1 = 0.0f;

    const int cnt = g_kcnt[row];
    const int* kept = g_kept + (size_t)row * MAXK;

    for (int kbi = 0; kbi < cnt; kbi++) {
        __syncthreads();
        const int nblk = kept[kbi];
        const float* kbase = g_qkv + ((size_t)(b * NN + nblk * BSZ) * (3 * DD))
                             + DD + h * HDD;
#pragma unroll
        for (int j = 0; j < 8; j++) {
            int i = tid + (j << 7);
            int r = i >> 4, c4 = (i & 15) << 2;
            float4 kv = *(const float4*)(kbase + (size_t)r * (3 * DD) + c4);
            float f[4] = {kv.x, kv.y, kv.z, kv.w};
            float rr[4];
#pragma unroll
            for (int jj = 0; jj < 4; jj++) {
                __half hh = __float2half_rn(f[jj]);
                rr[jj] = f[jj] - __half2float(hh);
            }
            uint2 ph, pl;
            ph.x = pack2f16(f[0], f[1]);  ph.y = pack2f16(f[2], f[3]);
            pl.x = pack2f16(rr[0], rr[1]); pl.y = pack2f16(rr[2], rr[3]);
            *(uint2*)(sm + TKH + r * APAD + c4) = ph;
            *(uint2*)(sm + TKL + r * APAD + c4) = pl;
            float4 vv = *(const float4*)(kbase + DD + (size_t)r * (3 * DD) + c4);
            uint2 pv;
            pv.x = pack2f16(vv.x, vv.y); pv.y = pack2f16(vv.z, vv.w);
            *(uint2*)(sm + TVF + r * APAD + c4) = pv;
        }
        __syncthreads();

        float c_s[8][4];
#pragma unroll
        for (int nt = 0; nt < 8; nt++)
#pragma unroll
            for (int r = 0; r < 4; r++) c_s[nt][r] = 0.0f;
#pragma unroll
        for (int ks = 0; ks < 4; ks++) {
            uint32_t kh[4][4], kl[4][4];
#pragma unroll
            for (int np = 0; np < 4; np++) {
                ldm4(kh[np], sb + (uint32_t)(TKH * 2) + kboff[np] + ks * 32);
                ldm4(kl[np], sb + (uint32_t)(TKL * 2) + kboff[np] + ks * 32);
            }
#pragma unroll
            for (int nt = 0; nt < 8; nt++)
                MMA_F16(c_s[nt], qh_a[ks], &kh[nt >> 1][(nt & 1) << 1]);
#pragma unroll
            for (int nt = 0; nt < 8; nt++)
                MMA_F16(c_s[nt], qh_a[ks], &kl[nt >> 1][(nt & 1) << 1]);
#pragma unroll
            for (int nt = 0; nt < 8; nt++)
                MMA_F16(c_s[nt], ql_a[ks], &kh[nt >> 1][(nt & 1) << 1]);
        }

        const unsigned FULL = 0xffffffffu;
        float rmax0 = -INFINITY, rmax1 = -INFINITY;
#pragma unroll
        for (int nt = 0; nt < 8; nt++) {
            rmax0 = fmaxf(rmax0, fmaxf(c_s[nt][0], c_s[nt][1]));
            rmax1 = fmaxf(rmax1, fmaxf(c_s[nt][2], c_s[nt][3]));
        }
        rmax0 = fmaxf(rmax0, __shfl_xor_sync(FULL, rmax0, 1));
        rmax0 = fmaxf(rmax0, __shfl_xor_sync(FULL, rmax0, 2));
        rmax1 = fmaxf(rmax1, __shfl_xor_sync(FULL, rmax1, 1));
        rmax1 = fmaxf(rmax1, __shfl_xor_sync(FULL, rmax1, 2));

        float mn0 = fmaxf(mrun0, rmax0), mn1 = fmaxf(mrun1, rmax1);
        float e0 = __expf(mrun0 - mn0),  e1 = __expf(mrun1 - mn1);
        float rs0 = 0.0f, rs1 = 0.0f;
#pragma unroll
        for (int nt = 0; nt < 8; nt++) {
            c_s[nt][0] = __expf(c_s[nt][0] - mn0); rs0 += c_s[nt][0];
            c_s[nt][1] = __expf(c_s[nt][1] - mn0); rs0 += c_s[nt][1];
            c_s[nt][2] = __expf(c_s[nt][2] - mn1); rs1 += c_s[nt][2];
            c_s[nt][3] = __expf(c_s[nt][3] - mn1); rs1 += c_s[nt][3];
        }
        rs0 += __shfl_xor_sync(FULL, rs0, 1); rs0 += __shfl_xor_sync(FULL, rs0, 2);
        rs1 += __shfl_xor_sync(FULL, rs1, 1); rs1 += __shfl_xor_sync(FULL, rs1, 2);
        lrun0 = lrun0 * e0 + rs0;  lrun1 = lrun1 * e1 + rs1;
        mrun0 = mn0;               mrun1 = mn1;
#pragma unroll
        for (int dt = 0; dt < 8; dt++) {
            c_o[dt][0] *= e0; c_o[dt][1] *= e0;
            c_o[dt][2] *= e1; c_o[dt][3] *= e1;
        }

#pragma unroll
        for (int ks = 0; ks < 4; ks++) {
            uint32_t pha[4], pla[4];
#pragma unroll
            for (int half = 0; half < 2; half++) {
                const float* cs = c_s[2 * ks + half];
                float x0 = cs[0], x1 = cs[1], x2 = cs[2], x3 = cs[3];
                __half h0 = __float2half_rn(x0), h1 = __float2half_rn(x1);
                __half h2 = __float2half_rn(x2), h3 = __float2half_rn(x3);
                pha[2 * half]     = (uint32_t)__half_as_ushort(h0) |
                                    ((uint32_t)__half_as_ushort(h1) << 16);
                pha[2 * half + 1] = (uint32_t)__half_as_ushort(h2) |
                                    ((uint32_t)__half_as_ushort(h3) << 16);
                pla[2 * half]     = pack2f16(x0 - __half2float(h0),
                                             x1 - __half2float(h1));
                pla[2 * half + 1] = pack2f16(x2 - __half2float(h2),
                                             x3 - __half2float(h3));
            }
            uint32_t pA[4] = {pha[0], pha[1], pha[2], pha[3]};
            uint32_t pL[4] = {pla[0], pla[1], pla[2], pla[3]};

            uint32_t vf[4][4];
#pragma unroll
            for (int dp = 0; dp < 4; dp++)
                ldm4t(vf[dp], sb + (uint32_t)(TVF * 2) + voff[dp]
                              + (uint32_t)(ks * 16 * APAD * 2));
#pragma unroll
            for (int dt = 0; dt < 8; dt++)
                MMA_F16(c_o[dt], pA, &vf[dt >> 1][(dt & 1) << 1]);
#pragma unroll
            for (int dt = 0; dt < 8; dt++)
                MMA_F16(c_o[dt], pL, &vf[dt >> 1][(dt & 1) << 1]);
        }
    }

    // ---- epilogue: normalize, single fp16 store ----
    const float inv0 = 1.0f / lrun0, inv1 = 1.0f / lrun1;
    const int g = lane >> 2, t = lane & 3;
    const int tok0 = b * NN + m * BSZ + wid * 16 + g;
    const size_t o0 = (size_t)tok0 * DD + h * HDD;
    const size_t o1 = o0 + (size_t)8 * DD;
#pragma unroll
    for (int dt = 0; dt < 8; dt++) {
        int col = dt * 8 + t * 2;
        *(uint32_t*)(g_ah + o0 + col) = pack2f16(c_o[dt][0] * inv0, c_o[dt][1] * inv0);
        *(uint32_t*)(g_ah + o1 + col) = pack2f16(c_o[dt][2] * inv1, c_o[dt][3] * inv1);
    }
}

// =====================================================================
// Launch
// =====================================================================
extern "C" void kernel_launch(void* const* d_in, const int* in_sizes, int n_in,
                              void* d_out, int out_size)
{
    const float* x = nullptr; const float* qkv_w = nullptr;
    const float* proj_w = nullptr; const float* proj_b = nullptr;
    for (int i = 0; i < n_in; i++) {
        if      (in_sizes[i] == BB * NN * DD) x      = (const float*)d_in[i];
        else if (in_sizes[i] == 3 * DD * DD)  qkv_w  = (const float*)d_in[i];
        else if (in_sizes[i] == DD * DD)      proj_w = (const float*)d_in[i];
        else if (in_sizes[i] == DD)           proj_b = (const float*)d_in[i];
    }
    float* out = (float*)d_out;

    void* p;
    cudaGetSymbolAddress(&p, g_qkv); float* qkv = (float*)p;
    __half *xh, *wq, *wp, *ah;
    cudaGetSymbolAddress(&p, g_xh); xh = (__half*)p;
    cudaGetSymbolAddress(&p, g_wq); wq = (__half*)p;
    cudaGetSymbolAddress(&p, g_wp); wp = (__half*)p;
    cudaGetSymbolAddress(&p, g_ah); ah = (__half*)p;

    static int attr_done = 0;
    if (!attr_done) {
        cudaFuncSetAttribute(gemm_mma, cudaFuncAttributeMaxDynamicSharedMemorySize, GEMM_SMEM);
        attr_done = 1;
    }

    {
        int n4 = N4_X + N4_WQ + N4_WP;
        split3_kernel<<<(n4 + 255) / 256, 256>>>(x, xh, qkv_w, wq, proj_w, wp);
    }
    gemm_mma<<<dim3(3 * DD / 128, TOK / 128), 256, GEMM_SMEM>>>(
        xh, wq, nullptr, qkv, 3 * DD, DD, 0);
    pool_kernel<<<BB * HH * MM, 64>>>();
    mask_kernel<<<BB * HH * MM / 8, 256>>>();
    attn_kernel<<<BB * HH * MM, 128>>>();
    gemm_mma<<<dim3(DD / 128, TOK / 128), 256, GEMM_SMEM>>>(
        ah, wp, proj_b, out, DD, DD, 1);
}